// round 4
// baseline (speedup 1.0000x reference)
#include <cuda_runtime.h>
#include <math.h>

#define NN 10000
#define NE 60000
#define DD 128
#define NLAYERS 15

// Scratch (device globals; allocation-free per harness rules)
__device__ float g_H1e[NE * 256];   // edge hidden after LN+GELU
__device__ float g_Hn1[NN * 256];   // node hidden after LN+GELU
__device__ float g_agg[NN * DD];    // per-node aggregated edge features
__device__ float g_cnt[NN];         // 1/max(count,1)

__global__ void copy_kernel(const float* __restrict__ src, float* __restrict__ dst, int n) {
    int i = blockIdx.x * blockDim.x + threadIdx.x;
    if (i < n) dst[i] = src[i];
}

__global__ void zero_cnt_kernel() {
    int i = blockIdx.x * blockDim.x + threadIdx.x;
    if (i < NN) g_cnt[i] = 0.f;
}

__global__ void count_kernel(const int* __restrict__ col) {
    int e = blockIdx.x * blockDim.x + threadIdx.x;
    if (e < NE) atomicAdd(&g_cnt[col[e]], 1.f);
}

__global__ void invcnt_kernel() {
    int i = blockIdx.x * blockDim.x + threadIdx.x;
    if (i < NN) g_cnt[i] = 1.f / fmaxf(g_cnt[i], 1.f);
}

__global__ void zero_agg_kernel() {
    int i = blockIdx.x * blockDim.x + threadIdx.x;
    if (i < NN * DD) g_agg[i] = 0.f;
}

// Fused GEMM + bias + LayerNorm (+GELU / +residual / +scatter) kernel.
// MODE 0: edge MLP L1: A=[x[row]|x[col]|ea] (K=384), N=256, LN+GELU -> g_H1e
// MODE 1: edge MLP L2: A=g_H1e (K=256), N=128, LN + residual(ea) + atomic agg scatter
// MODE 2: node MLP L1: A=[x | agg*invcnt] (K=256), N=256, LN+GELU -> g_Hn1
// MODE 3: node MLP L2: A=g_Hn1 (K=256), N=128, LN + residual(x)
//
// Tiling: BM=64, BN=N(full), BK=32, 256 threads, per-thread 8 x TN outputs.
// Warp w (=tid>>5) owns rows m0+w*8..m0+w*8+7 completely -> LN is a pure
// warp shfl reduction over accumulators (no smem staging of outputs).
template <int KDIM, int BN, int TN, int MODE>
__global__ void __launch_bounds__(256)
gemm_ln_kernel(const float* __restrict__ W, const float* __restrict__ bias,
               const float* __restrict__ gamma, const float* __restrict__ beta,
               float* __restrict__ xbuf, float* __restrict__ eabuf,
               const int* __restrict__ rowi, const int* __restrict__ coli, int M) {
    constexpr int BM = 64, BK = 32, TM = 8;
    __shared__ float As[BM * BK];
    __shared__ float Bs[BK * BN];

    const int tid = threadIdx.x;
    const int m0 = blockIdx.x * BM;
    const int tm = tid >> 5;   // warp id 0..7
    const int tn = tid & 31;   // lane

    // A-tile loader mapping: 512 float4 per tile; this thread loads f4 index
    // tid and tid+256 -> rows lr0 and lr0+32, cols lc..lc+3.
    const int lr0 = tid >> 3;
    const int lc = (tid & 7) * 4;

    const float* ap0[2];
    const float* ap1[2];
    const float* ap2[2];
    float invc[2];
#pragma unroll
    for (int jj = 0; jj < 2; jj++) {
        int r = lr0 + jj * 32;
        int m = min(m0 + r, M - 1);
        if (MODE == 0) {
            ap0[jj] = xbuf + (size_t)rowi[m] * DD;
            ap1[jj] = xbuf + (size_t)coli[m] * DD;
            ap2[jj] = eabuf + (size_t)m * DD;
        } else if (MODE == 2) {
            ap0[jj] = xbuf + (size_t)m * DD;
            ap1[jj] = g_agg + (size_t)m * DD;
            invc[jj] = g_cnt[m];
        } else if (MODE == 1) {
            ap0[jj] = g_H1e + (size_t)m * KDIM;
        } else {
            ap0[jj] = g_Hn1 + (size_t)m * KDIM;
        }
    }

    float acc[TM][TN];
#pragma unroll
    for (int i = 0; i < TM; i++)
#pragma unroll
        for (int j = 0; j < TN; j++) acc[i][j] = 0.f;

    for (int k0 = 0; k0 < KDIM; k0 += BK) {
        // ---- load A tile (gathered per mode) ----
#pragma unroll
        for (int jj = 0; jj < 2; jj++) {
            int r = lr0 + jj * 32;
            float4 av;
            if (MODE == 0) {
                int kg = k0 + lc;
                const float* p = (kg < 128) ? (ap0[jj] + kg)
                                : (kg < 256) ? (ap1[jj] + (kg - 128))
                                             : (ap2[jj] + (kg - 256));
                av = *(const float4*)p;
            } else if (MODE == 2) {
                int kg = k0 + lc;
                if (kg < 128) {
                    av = *(const float4*)(ap0[jj] + kg);
                } else {
                    av = *(const float4*)(ap1[jj] + (kg - 128));
                    av.x *= invc[jj]; av.y *= invc[jj];
                    av.z *= invc[jj]; av.w *= invc[jj];
                }
            } else {
                av = *(const float4*)(ap0[jj] + k0 + lc);
            }
            *(float4*)&As[r * BK + lc] = av;
        }
        // ---- load B tile: contiguous 32xBN slab of W ----
        {
            const float4* wsrc = (const float4*)(W + (size_t)k0 * BN);
            float4* bdst = (float4*)Bs;
#pragma unroll
            for (int j = 0; j < (BK * BN / 4) / 256; j++)
                bdst[tid + 256 * j] = wsrc[tid + 256 * j];
        }
        __syncthreads();

#pragma unroll
        for (int k = 0; k < BK; k++) {
            float a[TM];
#pragma unroll
            for (int i = 0; i < TM; i++) a[i] = As[(tm * TM + i) * BK + k];
            float b[TN];
#pragma unroll
            for (int j = 0; j < TN; j += 4) {
                float4 bv = *(const float4*)&Bs[k * BN + tn * TN + j];
                b[j] = bv.x; b[j + 1] = bv.y; b[j + 2] = bv.z; b[j + 3] = bv.w;
            }
#pragma unroll
            for (int i = 0; i < TM; i++)
#pragma unroll
                for (int j = 0; j < TN; j++) acc[i][j] = fmaf(a[i], b[j], acc[i][j]);
        }
        __syncthreads();
    }

    // ---- epilogue: bias + LayerNorm per row via warp reduction ----
#pragma unroll
    for (int i = 0; i < TM; i++) {
        float s = 0.f, sq = 0.f;
#pragma unroll
        for (int j = 0; j < TN; j++) {
            int c = tn * TN + j;
            float v = acc[i][j] + bias[c];
            acc[i][j] = v;
            s += v;
            sq += v * v;
        }
#pragma unroll
        for (int off = 16; off > 0; off >>= 1) {
            s += __shfl_xor_sync(0xffffffffu, s, off);
            sq += __shfl_xor_sync(0xffffffffu, sq, off);
        }
        float mean = s * (1.f / BN);
        float var = sq * (1.f / BN) - mean * mean;
        float rstd = rsqrtf(var + 1e-5f);
        int m = m0 + tm * TM + i;
        if (m < M) {
            if (MODE == 0 || MODE == 2) {
                float* out = (MODE == 0 ? g_H1e : g_Hn1) + (size_t)m * BN;
#pragma unroll
                for (int j = 0; j < TN; j++) {
                    int c = tn * TN + j;
                    float t = (acc[i][j] - mean) * rstd * gamma[c] + beta[c];
                    t = 0.5f * t * (1.f + erff(t * 0.70710678118654752f));  // exact GELU
                    out[c] = t;
                }
            } else if (MODE == 1) {
                int dst = coli[m];
#pragma unroll
                for (int j = 0; j < TN; j++) {
                    int c = tn * TN + j;
                    float t = (acc[i][j] - mean) * rstd * gamma[c] + beta[c];
                    float ne = eabuf[(size_t)m * DD + c] + t;
                    eabuf[(size_t)m * DD + c] = ne;
                    atomicAdd(&g_agg[(size_t)dst * DD + c], ne);
                }
            } else {
#pragma unroll
                for (int j = 0; j < TN; j++) {
                    int c = tn * TN + j;
                    float t = (acc[i][j] - mean) * rstd * gamma[c] + beta[c];
                    xbuf[(size_t)m * DD + c] += t;
                }
            }
        }
    }
}

extern "C" void kernel_launch(void* const* d_in, const int* in_sizes, int n_in,
                              void* d_out, int out_size) {
    const float* x    = (const float*)d_in[0];
    const int*   ei   = (const int*)d_in[1];
    const float* ea   = (const float*)d_in[2];
    const float* ew1  = (const float*)d_in[3];
    const float* eb1  = (const float*)d_in[4];
    const float* eg1  = (const float*)d_in[5];
    const float* ebt1 = (const float*)d_in[6];
    const float* ew2  = (const float*)d_in[7];
    const float* eb2  = (const float*)d_in[8];
    const float* eg2  = (const float*)d_in[9];
    const float* ebt2 = (const float*)d_in[10];
    const float* nw1  = (const float*)d_in[11];
    const float* nb1  = (const float*)d_in[12];
    const float* ng1  = (const float*)d_in[13];
    const float* nbt1 = (const float*)d_in[14];
    const float* nw2  = (const float*)d_in[15];
    const float* nb2  = (const float*)d_in[16];
    const float* ng2  = (const float*)d_in[17];
    const float* nbt2 = (const float*)d_in[18];

    // d_out layout: x [NN*DD] then edge_attr [NE*DD] — use it as the live buffers.
    float* xo = (float*)d_out;
    float* eo = xo + (size_t)NN * DD;
    const int* rowi = ei;
    const int* coli = ei + NE;

    copy_kernel<<<(NN * DD + 255) / 256, 256>>>(x, xo, NN * DD);
    copy_kernel<<<(NE * DD + 255) / 256, 256>>>(ea, eo, NE * DD);
    zero_cnt_kernel<<<(NN + 255) / 256, 256>>>();
    count_kernel<<<(NE + 255) / 256, 256>>>(coli);
    invcnt_kernel<<<(NN + 255) / 256, 256>>>();

    const int EG = (NE + 63) / 64;  // 938
    const int NG = (NN + 63) / 64;  // 157

    for (int l = 0; l < NLAYERS; l++) {
        zero_agg_kernel<<<(NN * DD + 255) / 256, 256>>>();
        gemm_ln_kernel<384, 256, 8, 0><<<EG, 256>>>(
            ew1 + (size_t)l * 384 * 256, eb1 + l * 256, eg1 + l * 256, ebt1 + l * 256,
            xo, eo, rowi, coli, NE);
        gemm_ln_kernel<256, 128, 4, 1><<<EG, 256>>>(
            ew2 + (size_t)l * 256 * 128, eb2 + l * 128, eg2 + l * 128, ebt2 + l * 128,
            xo, eo, rowi, coli, NE);
        gemm_ln_kernel<256, 256, 8, 2><<<NG, 256>>>(
            nw1 + (size_t)l * 256 * 256, nb1 + l * 256, ng1 + l * 256, nbt1 + l * 256,
            xo, eo, rowi, coli, NN);
        gemm_ln_kernel<256, 128, 4, 3><<<NG, 256>>>(
            nw2 + (size_t)l * 256 * 128, nb2 + l * 128, ng2 + l * 128, nbt2 + l * 128,
            xo, eo, rowi, coli, NN);
    }
}

// round 5
// speedup vs baseline: 1.1231x; 1.1231x over previous
#include <cuda_runtime.h>
#include <math.h>

#define NN 10000
#define NE 60000
#define DD 128
#define NLAYERS 15

typedef unsigned long long u64;

// Scratch (device globals; allocation-free per harness rules)
__device__ float g_H1e[NE * 256];   // edge hidden after LN+GELU
__device__ float g_Hn1[NN * 256];   // node hidden after LN+GELU
__device__ float g_agg[NN * DD];    // per-node aggregated edge features
__device__ float g_cnt[NN];         // 1/max(count,1)

__global__ void copy_kernel(const float* __restrict__ src, float* __restrict__ dst, int n) {
    int i = blockIdx.x * blockDim.x + threadIdx.x;
    if (i < n) dst[i] = src[i];
}

__global__ void zero_cnt_kernel() {
    int i = blockIdx.x * blockDim.x + threadIdx.x;
    if (i < NN) g_cnt[i] = 0.f;
}

__global__ void count_kernel(const int* __restrict__ col) {
    int e = blockIdx.x * blockDim.x + threadIdx.x;
    if (e < NE) atomicAdd(&g_cnt[col[e]], 1.f);
}

__global__ void invcnt_kernel() {
    int i = blockIdx.x * blockDim.x + threadIdx.x;
    if (i < NN) g_cnt[i] = 1.f / fmaxf(g_cnt[i], 1.f);
}

__global__ void zero_agg_kernel() {
    int i = blockIdx.x * blockDim.x + threadIdx.x;
    if (i < NN * DD) g_agg[i] = 0.f;
}

// Packed f32x2 FMA: d = a2 * b2 + d  (SASS FFMA2 — 2 fp32 FMA per issue slot)
__device__ __forceinline__ void ffma2(u64& d, u64 a2, u64 b2) {
    asm("fma.rn.f32x2 %0, %1, %2, %0;" : "+l"(d) : "l"(a2), "l"(b2));
}
__device__ __forceinline__ u64 splat2(float a) {
    u64 r;
    asm("mov.b64 %0, {%1, %1};" : "=l"(r) : "f"(a));
    return r;
}
__device__ __forceinline__ void unpack2(u64 v, float& lo, float& hi) {
    asm("mov.b64 {%0, %1}, %2;" : "=f"(lo), "=f"(hi) : "l"(v));
}

// Fused GEMM + bias + LayerNorm (+GELU / +residual / +scatter) kernel.
// MODE 0: edge MLP L1: A=[x[row]|x[col]|ea] (K=384), N=256, LN+GELU -> g_H1e
// MODE 1: edge MLP L2: A=g_H1e (K=256), N=128, LN + residual(ea) + atomic agg scatter
// MODE 2: node MLP L1: A=[x | agg*invcnt] (K=256), N=256, LN+GELU -> g_Hn1
// MODE 3: node MLP L2: A=g_Hn1 (K=256), N=128, LN + residual(x)
//
// Tiling: BM=64, BN=N(full), BK=32, 256 threads, per-thread 8 x TN outputs.
// Accumulators are packed f32x2 pairs along N (FFMA2); B pairs come pre-packed
// from float4 smem loads reinterpreted as ulonglong2.
// Warp w (=tid>>5) owns rows m0+w*8..m0+w*8+7 completely -> LN is a pure
// warp shfl reduction over accumulators (no smem staging of outputs).
template <int KDIM, int BN, int TN, int MODE>
__global__ void __launch_bounds__(256)
gemm_ln_kernel(const float* __restrict__ W, const float* __restrict__ bias,
               const float* __restrict__ gamma, const float* __restrict__ beta,
               float* __restrict__ xbuf, float* __restrict__ eabuf,
               const int* __restrict__ rowi, const int* __restrict__ coli, int M) {
    constexpr int BM = 64, BK = 32, TM = 8, TN2 = TN / 2;
    __shared__ float As[BM * BK];
    __shared__ float Bs[BK * BN];

    const int tid = threadIdx.x;
    const int m0 = blockIdx.x * BM;
    const int tm = tid >> 5;   // warp id 0..7
    const int tn = tid & 31;   // lane

    // A-tile loader mapping: 512 float4 per tile; this thread loads f4 index
    // tid and tid+256 -> rows lr0 and lr0+32, cols lc..lc+3.
    const int lr0 = tid >> 3;
    const int lc = (tid & 7) * 4;

    const float* ap0[2];
    const float* ap1[2];
    const float* ap2[2];
    float invc[2];
#pragma unroll
    for (int jj = 0; jj < 2; jj++) {
        int r = lr0 + jj * 32;
        int m = min(m0 + r, M - 1);
        if (MODE == 0) {
            ap0[jj] = xbuf + (size_t)rowi[m] * DD;
            ap1[jj] = xbuf + (size_t)coli[m] * DD;
            ap2[jj] = eabuf + (size_t)m * DD;
        } else if (MODE == 2) {
            ap0[jj] = xbuf + (size_t)m * DD;
            ap1[jj] = g_agg + (size_t)m * DD;
            invc[jj] = g_cnt[m];
        } else if (MODE == 1) {
            ap0[jj] = g_H1e + (size_t)m * KDIM;
        } else {
            ap0[jj] = g_Hn1 + (size_t)m * KDIM;
        }
    }

    u64 acc[TM][TN2];
#pragma unroll
    for (int i = 0; i < TM; i++)
#pragma unroll
        for (int j = 0; j < TN2; j++) acc[i][j] = 0ull;  // {0.f, 0.f}

    for (int k0 = 0; k0 < KDIM; k0 += BK) {
        // ---- load A tile (gathered per mode) ----
#pragma unroll
        for (int jj = 0; jj < 2; jj++) {
            int r = lr0 + jj * 32;
            float4 av;
            if (MODE == 0) {
                int kg = k0 + lc;
                const float* p = (kg < 128) ? (ap0[jj] + kg)
                                : (kg < 256) ? (ap1[jj] + (kg - 128))
                                             : (ap2[jj] + (kg - 256));
                av = *(const float4*)p;
            } else if (MODE == 2) {
                int kg = k0 + lc;
                if (kg < 128) {
                    av = *(const float4*)(ap0[jj] + kg);
                } else {
                    av = *(const float4*)(ap1[jj] + (kg - 128));
                    av.x *= invc[jj]; av.y *= invc[jj];
                    av.z *= invc[jj]; av.w *= invc[jj];
                }
            } else {
                av = *(const float4*)(ap0[jj] + k0 + lc);
            }
            *(float4*)&As[r * BK + lc] = av;
        }
        // ---- load B tile: contiguous 32xBN slab of W ----
        {
            const float4* wsrc = (const float4*)(W + (size_t)k0 * BN);
            float4* bdst = (float4*)Bs;
#pragma unroll
            for (int j = 0; j < (BK * BN / 4) / 256; j++)
                bdst[tid + 256 * j] = wsrc[tid + 256 * j];
        }
        __syncthreads();

#pragma unroll
        for (int k = 0; k < BK; k++) {
            u64 a2[TM];
#pragma unroll
            for (int i = 0; i < TM; i++) a2[i] = splat2(As[(tm * TM + i) * BK + k]);
            u64 b2[TN2];
#pragma unroll
            for (int j4 = 0; j4 < TN; j4 += 4) {
                ulonglong2 bv = *(const ulonglong2*)&Bs[k * BN + tn * TN + j4];
                b2[j4 / 2] = bv.x;
                b2[j4 / 2 + 1] = bv.y;
            }
#pragma unroll
            for (int i = 0; i < TM; i++)
#pragma unroll
                for (int j = 0; j < TN2; j++) ffma2(acc[i][j], a2[i], b2[j]);
        }
        __syncthreads();
    }

    // ---- epilogue: bias + LayerNorm per row via warp reduction ----
#pragma unroll
    for (int i = 0; i < TM; i++) {
        float av[TN];
#pragma unroll
        for (int j = 0; j < TN2; j++) unpack2(acc[i][j], av[2 * j], av[2 * j + 1]);
        float s = 0.f, sq = 0.f;
#pragma unroll
        for (int j = 0; j < TN; j++) {
            int c = tn * TN + j;
            float v = av[j] + bias[c];
            av[j] = v;
            s += v;
            sq += v * v;
        }
#pragma unroll
        for (int off = 16; off > 0; off >>= 1) {
            s += __shfl_xor_sync(0xffffffffu, s, off);
            sq += __shfl_xor_sync(0xffffffffu, sq, off);
        }
        float mean = s * (1.f / BN);
        float var = sq * (1.f / BN) - mean * mean;
        float rstd = rsqrtf(var + 1e-5f);
        int m = m0 + tm * TM + i;
        if (m < M) {
            if (MODE == 0 || MODE == 2) {
                float* out = (MODE == 0 ? g_H1e : g_Hn1) + (size_t)m * BN;
#pragma unroll
                for (int j = 0; j < TN; j++) {
                    int c = tn * TN + j;
                    float t = (av[j] - mean) * rstd * gamma[c] + beta[c];
                    t = 0.5f * t * (1.f + erff(t * 0.70710678118654752f));  // exact GELU
                    out[c] = t;
                }
            } else if (MODE == 1) {
                int dst = coli[m];
#pragma unroll
                for (int j = 0; j < TN; j++) {
                    int c = tn * TN + j;
                    float t = (av[j] - mean) * rstd * gamma[c] + beta[c];
                    float ne = eabuf[(size_t)m * DD + c] + t;
                    eabuf[(size_t)m * DD + c] = ne;
                    atomicAdd(&g_agg[(size_t)dst * DD + c], ne);
                }
            } else {
#pragma unroll
                for (int j = 0; j < TN; j++) {
                    int c = tn * TN + j;
                    float t = (av[j] - mean) * rstd * gamma[c] + beta[c];
                    xbuf[(size_t)m * DD + c] += t;
                }
            }
        }
    }
}

extern "C" void kernel_launch(void* const* d_in, const int* in_sizes, int n_in,
                              void* d_out, int out_size) {
    const float* x    = (const float*)d_in[0];
    const int*   ei   = (const int*)d_in[1];
    const float* ea   = (const float*)d_in[2];
    const float* ew1  = (const float*)d_in[3];
    const float* eb1  = (const float*)d_in[4];
    const float* eg1  = (const float*)d_in[5];
    const float* ebt1 = (const float*)d_in[6];
    const float* ew2  = (const float*)d_in[7];
    const float* eb2  = (const float*)d_in[8];
    const float* eg2  = (const float*)d_in[9];
    const float* ebt2 = (const float*)d_in[10];
    const float* nw1  = (const float*)d_in[11];
    const float* nb1  = (const float*)d_in[12];
    const float* ng1  = (const float*)d_in[13];
    const float* nbt1 = (const float*)d_in[14];
    const float* nw2  = (const float*)d_in[15];
    const float* nb2  = (const float*)d_in[16];
    const float* ng2  = (const float*)d_in[17];
    const float* nbt2 = (const float*)d_in[18];

    // d_out layout: x [NN*DD] then edge_attr [NE*DD] — use it as the live buffers.
    float* xo = (float*)d_out;
    float* eo = xo + (size_t)NN * DD;
    const int* rowi = ei;
    const int* coli = ei + NE;

    copy_kernel<<<(NN * DD + 255) / 256, 256>>>(x, xo, NN * DD);
    copy_kernel<<<(NE * DD + 255) / 256, 256>>>(ea, eo, NE * DD);
    zero_cnt_kernel<<<(NN + 255) / 256, 256>>>();
    count_kernel<<<(NE + 255) / 256, 256>>>(coli);
    invcnt_kernel<<<(NN + 255) / 256, 256>>>();

    const int EG = (NE + 63) / 64;  // 938
    const int NG = (NN + 63) / 64;  // 157

    for (int l = 0; l < NLAYERS; l++) {
        zero_agg_kernel<<<(NN * DD + 255) / 256, 256>>>();
        gemm_ln_kernel<384, 256, 8, 0><<<EG, 256>>>(
            ew1 + (size_t)l * 384 * 256, eb1 + l * 256, eg1 + l * 256, ebt1 + l * 256,
            xo, eo, rowi, coli, NE);
        gemm_ln_kernel<256, 128, 4, 1><<<EG, 256>>>(
            ew2 + (size_t)l * 256 * 128, eb2 + l * 128, eg2 + l * 128, ebt2 + l * 128,
            xo, eo, rowi, coli, NE);
        gemm_ln_kernel<256, 256, 8, 2><<<NG, 256>>>(
            nw1 + (size_t)l * 256 * 256, nb1 + l * 256, ng1 + l * 256, nbt1 + l * 256,
            xo, eo, rowi, coli, NN);
        gemm_ln_kernel<256, 128, 4, 3><<<NG, 256>>>(
            nw2 + (size_t)l * 256 * 128, nb2 + l * 128, ng2 + l * 128, nbt2 + l * 128,
            xo, eo, rowi, coli, NN);
    }
}

// round 7
// speedup vs baseline: 1.2961x; 1.1541x over previous
#include <cuda_runtime.h>
#include <cuda_bf16.h>
#include <math.h>
#include <stdint.h>

#define NN 10000
#define NE 60000
#define DD 128
#define NLAYERS 15

#define ERT 3750   // edge row tiles (60000/16)
#define NRT 625    // node row tiles (10000/16)

// ---------------- device scratch (allocation-free) ----------------
__device__ float g_agg[NN * DD];    // per-node aggregated edge features
__device__ float g_cnt[NN];         // 1/max(count,1)

// hidden activations pre-packed as bf16 hi/lo A-fragments:
// layout [rowtile][ktile][lane][{hi uint4, lo uint4}]
__device__ uint4 g_H1p[ERT * 16 * 32 * 2];   // edge hidden (K=256 -> 16 ktiles)
__device__ uint4 g_Hn1p[NRT * 16 * 32 * 2];  // node hidden

// weights pre-packed as B-fragments {bh0,bh1,bl0,bl1}:
// layout [layer][ktile][ntile][lane]
__device__ uint4 g_ew1p[NLAYERS * 24 * 32 * 32];
__device__ uint4 g_ew2p[NLAYERS * 16 * 16 * 32];
__device__ uint4 g_nw1p[NLAYERS * 16 * 32 * 32];
__device__ uint4 g_nw2p[NLAYERS * 16 * 16 * 32];

// ---------------- helpers ----------------
__device__ __forceinline__ uint32_t pkh(float a, float b) {
    __nv_bfloat162 t = __floats2bfloat162_rn(a, b);
    return *(uint32_t*)&t;
}
__device__ __forceinline__ uint32_t pkl(float a, float b) {
    __nv_bfloat16 ha = __float2bfloat16(a), hb = __float2bfloat16(b);
    return pkh(a - __bfloat162float(ha), b - __bfloat162float(hb));
}

#define MMA4(d, a, b0, b1) \
    asm volatile("mma.sync.aligned.m16n8k16.row.col.f32.bf16.bf16.f32 " \
                 "{%0,%1,%2,%3},{%4,%5,%6,%7},{%8,%9},{%0,%1,%2,%3};" \
                 : "+f"((d).x), "+f"((d).y), "+f"((d).z), "+f"((d).w) \
                 : "r"((a)[0]), "r"((a)[1]), "r"((a)[2]), "r"((a)[3]), \
                   "r"(b0), "r"(b1))

// ---------------- aux kernels ----------------
__global__ void copy_kernel(const float* __restrict__ src, float* __restrict__ dst, int n) {
    int i = blockIdx.x * blockDim.x + threadIdx.x;
    if (i < n) dst[i] = src[i];
}
__global__ void zero_cnt_kernel() {
    int i = blockIdx.x * blockDim.x + threadIdx.x;
    if (i < NN) g_cnt[i] = 0.f;
}
__global__ void count_kernel(const int* __restrict__ col) {
    int e = blockIdx.x * blockDim.x + threadIdx.x;
    if (e < NE) atomicAdd(&g_cnt[col[e]], 1.f);
}
__global__ void invcnt_kernel() {
    int i = blockIdx.x * blockDim.x + threadIdx.x;
    if (i < NN) g_cnt[i] = 1.f / fmaxf(g_cnt[i], 1.f);
}
__global__ void zero_agg_kernel() {
    int i = blockIdx.x * blockDim.x + threadIdx.x;
    if (i < NN * DD) g_agg[i] = 0.f;
}

// Pre-pack fp32 W[L][K][N] into per-lane B fragments {bh0,bh1,bl0,bl1}.
__global__ void pack_w(const float* __restrict__ W, uint4* __restrict__ out,
                       int KT, int NT, int K, int N, int total) {
    int idx = blockIdx.x * blockDim.x + threadIdx.x;
    if (idx >= total) return;
    int lane = idx & 31;
    int t = idx >> 5;
    int nt = t % NT; t /= NT;
    int kt = t % KT;
    int l = t / KT;
    int g = lane >> 2, tg = lane & 3;
    const float* Wl = W + (size_t)l * K * N;
    int n = nt * 8 + g;
    int ka = kt * 16 + tg * 2;
    float v00 = Wl[(size_t)ka * N + n];
    float v01 = Wl[(size_t)(ka + 1) * N + n];
    float v10 = Wl[(size_t)(ka + 8) * N + n];
    float v11 = Wl[(size_t)(ka + 9) * N + n];
    uint4 o;
    o.x = pkh(v00, v01);
    o.y = pkh(v10, v11);
    o.z = pkl(v00, v01);
    o.w = pkl(v10, v11);
    out[idx] = o;
}

// ---------------- fused HMMA GEMM + LN kernel ----------------
// MODE 0: edge L1: A=[x[row]|x[col]|ea] K=384, N=256, LN+GELU -> g_H1p (packed)
// MODE 1: edge L2: A=g_H1p K=256, N=128, LN + residual(ea) + atomic agg scatter
// MODE 2: node L1: A=[x | agg*invcnt] K=256, N=256, LN+GELU -> g_Hn1p (packed)
// MODE 3: node L2: A=g_Hn1p K=256, N=128, LN + residual(x)
// CTA = 4 warps = 64 rows; warp owns 16 rows x full N; LN = quad shfl.
template <int KT, int NT, int MODE>
__global__ void __launch_bounds__(128)
gemm_mma(const uint4* __restrict__ Wp, const float* __restrict__ bias,
         const float* __restrict__ gamma, const float* __restrict__ beta,
         float* __restrict__ xbuf, float* __restrict__ eabuf,
         const int* __restrict__ rowi, const int* __restrict__ coli, int M) {
    constexpr int BN = NT * 8;
    const int lane = threadIdx.x & 31;
    const int warp = threadIdx.x >> 5;
    const int g = lane >> 2, tg = lane & 3;
    const int rt = blockIdx.x * 4 + warp;
    const int RT = (M + 15) >> 4;
    const int rta = min(rt, RT - 1);
    const int r0 = rt * 16 + g, r1 = r0 + 8;
    const int r0c = min(r0, M - 1), r1c = min(r1, M - 1);

    const float *p00 = nullptr, *p01 = nullptr, *p02 = nullptr;
    const float *p10 = nullptr, *p11 = nullptr, *p12 = nullptr;
    float ic0 = 1.f, ic1 = 1.f;
    const uint4* Ap = nullptr;
    if (MODE == 0) {
        p00 = xbuf + (size_t)rowi[r0c] * DD;
        p01 = xbuf + (size_t)coli[r0c] * DD;
        p02 = eabuf + (size_t)r0c * DD;
        p10 = xbuf + (size_t)rowi[r1c] * DD;
        p11 = xbuf + (size_t)coli[r1c] * DD;
        p12 = eabuf + (size_t)r1c * DD;
    } else if (MODE == 2) {
        p00 = xbuf + (size_t)r0c * DD;
        p01 = g_agg + (size_t)r0c * DD;
        p10 = xbuf + (size_t)r1c * DD;
        p11 = g_agg + (size_t)r1c * DD;
        ic0 = g_cnt[r0c];
        ic1 = g_cnt[r1c];
    } else {
        Ap = (MODE == 1 ? g_H1p : g_Hn1p) + (size_t)rta * KT * 64 + lane * 2;
    }

    float4 acc[NT];
#pragma unroll
    for (int i = 0; i < NT; i++) acc[i] = make_float4(0.f, 0.f, 0.f, 0.f);

    for (int kt = 0; kt < KT; kt++) {
        uint32_t ah[4], al[4];
        if (MODE == 1 || MODE == 3) {
            uint4 h = Ap[(size_t)kt * 64];
            uint4 lo = Ap[(size_t)kt * 64 + 1];
            ah[0] = h.x; ah[1] = h.y; ah[2] = h.z; ah[3] = h.w;
            al[0] = lo.x; al[1] = lo.y; al[2] = lo.z; al[3] = lo.w;
        } else {
            int seg = kt >> 3;
            int ko = (kt & 7) * 16 + tg * 2;
            const float *q0, *q1;
            float s0 = 1.f, s1 = 1.f;
            if (MODE == 0) {
                q0 = (seg == 0) ? p00 : (seg == 1) ? p01 : p02;
                q1 = (seg == 0) ? p10 : (seg == 1) ? p11 : p12;
            } else {
                q0 = (seg == 0) ? p00 : p01;
                q1 = (seg == 0) ? p10 : p11;
                if (seg == 1) { s0 = ic0; s1 = ic1; }
            }
            float2 a0 = *(const float2*)(q0 + ko);
            float2 a2 = *(const float2*)(q0 + ko + 8);
            float2 b0 = *(const float2*)(q1 + ko);
            float2 b2 = *(const float2*)(q1 + ko + 8);
            a0.x *= s0; a0.y *= s0; a2.x *= s0; a2.y *= s0;
            b0.x *= s1; b0.y *= s1; b2.x *= s1; b2.y *= s1;
            ah[0] = pkh(a0.x, a0.y); ah[1] = pkh(b0.x, b0.y);
            ah[2] = pkh(a2.x, a2.y); ah[3] = pkh(b2.x, b2.y);
            al[0] = pkl(a0.x, a0.y); al[1] = pkl(b0.x, b0.y);
            al[2] = pkl(a2.x, a2.y); al[3] = pkl(b2.x, b2.y);
        }
        const uint4* Bp = Wp + (size_t)kt * NT * 32 + lane;
#pragma unroll
        for (int nt = 0; nt < NT; nt++) {
            uint4 b = Bp[nt * 32];
            MMA4(acc[nt], ah, b.x, b.y);  // hi * hi
            MMA4(acc[nt], ah, b.z, b.w);  // hi * lo
            MMA4(acc[nt], al, b.x, b.y);  // lo * hi
        }
    }

    // ---- bias + LN stats (rows r0, r1); reduce across the lane quad ----
    float s0 = 0.f, q0s = 0.f, s1 = 0.f, q1s = 0.f;
#pragma unroll
    for (int nt = 0; nt < NT; nt++) {
        int c = nt * 8 + tg * 2;
        float bx = bias[c], by = bias[c + 1];
        acc[nt].x += bx; acc[nt].y += by;
        acc[nt].z += bx; acc[nt].w += by;
        s0 += acc[nt].x + acc[nt].y;
        q0s += acc[nt].x * acc[nt].x + acc[nt].y * acc[nt].y;
        s1 += acc[nt].z + acc[nt].w;
        q1s += acc[nt].z * acc[nt].z + acc[nt].w * acc[nt].w;
    }
#pragma unroll
    for (int off = 1; off <= 2; off <<= 1) {
        s0 += __shfl_xor_sync(0xffffffffu, s0, off);
        q0s += __shfl_xor_sync(0xffffffffu, q0s, off);
        s1 += __shfl_xor_sync(0xffffffffu, s1, off);
        q1s += __shfl_xor_sync(0xffffffffu, q1s, off);
    }
    const float inv = 1.f / (float)BN;
    float m0 = s0 * inv, v0 = q0s * inv - m0 * m0, rs0 = rsqrtf(v0 + 1e-5f);
    float m1 = s1 * inv, v1 = q1s * inv - m1 * m1, rs1 = rsqrtf(v1 + 1e-5f);

    const bool ok0 = r0 < M, ok1 = r1 < M;

    if (MODE == 0 || MODE == 2) {
        uint4* Hp = (MODE == 0 ? g_H1p : g_Hn1p);
#pragma unroll
        for (int kt = 0; kt < NT / 2; kt++) {
            int c = kt * 16 + tg * 2;
            float ga0 = gamma[c], ga1 = gamma[c + 1], be0 = beta[c], be1 = beta[c + 1];
            float ga2 = gamma[c + 8], ga3 = gamma[c + 9], be2 = beta[c + 8], be3 = beta[c + 9];
            float tv[8];
            tv[0] = (acc[2 * kt].x - m0) * rs0 * ga0 + be0;
            tv[1] = (acc[2 * kt].y - m0) * rs0 * ga1 + be1;
            tv[2] = (acc[2 * kt].z - m1) * rs1 * ga0 + be0;
            tv[3] = (acc[2 * kt].w - m1) * rs1 * ga1 + be1;
            tv[4] = (acc[2 * kt + 1].x - m0) * rs0 * ga2 + be2;
            tv[5] = (acc[2 * kt + 1].y - m0) * rs0 * ga3 + be3;
            tv[6] = (acc[2 * kt + 1].z - m1) * rs1 * ga2 + be2;
            tv[7] = (acc[2 * kt + 1].w - m1) * rs1 * ga3 + be3;
#pragma unroll
            for (int j = 0; j < 8; j++)
                tv[j] = 0.5f * tv[j] * (1.f + erff(tv[j] * 0.70710678118654752f));  // exact GELU
            uint4 oh, ol;
            oh.x = pkh(tv[0], tv[1]); oh.y = pkh(tv[2], tv[3]);
            oh.z = pkh(tv[4], tv[5]); oh.w = pkh(tv[6], tv[7]);
            ol.x = pkl(tv[0], tv[1]); ol.y = pkl(tv[2], tv[3]);
            ol.z = pkl(tv[4], tv[5]); ol.w = pkl(tv[6], tv[7]);
            if (ok0) {
                size_t o = ((size_t)rt * (NT / 2) + kt) * 64 + lane * 2;
                Hp[o] = oh;
                Hp[o + 1] = ol;
            }
        }
    } else if (MODE == 1) {
        int d0 = coli[r0c], d1 = coli[r1c];
#pragma unroll
        for (int nt = 0; nt < NT; nt++) {
            int c = nt * 8 + tg * 2;
            float ga0 = gamma[c], ga1 = gamma[c + 1], be0 = beta[c], be1 = beta[c + 1];
            if (ok0) {
                float t0 = (acc[nt].x - m0) * rs0 * ga0 + be0;
                float t1 = (acc[nt].y - m0) * rs0 * ga1 + be1;
                float2 e = *(float2*)&eabuf[(size_t)r0 * DD + c];
                e.x += t0; e.y += t1;
                *(float2*)&eabuf[(size_t)r0 * DD + c] = e;
                atomicAdd(&g_agg[(size_t)d0 * DD + c], e.x);
                atomicAdd(&g_agg[(size_t)d0 * DD + c + 1], e.y);
            }
            if (ok1) {
                float t0 = (acc[nt].z - m1) * rs1 * ga0 + be0;
                float t1 = (acc[nt].w - m1) * rs1 * ga1 + be1;
                float2 e = *(float2*)&eabuf[(size_t)r1 * DD + c];
                e.x += t0; e.y += t1;
                *(float2*)&eabuf[(size_t)r1 * DD + c] = e;
                atomicAdd(&g_agg[(size_t)d1 * DD + c], e.x);
                atomicAdd(&g_agg[(size_t)d1 * DD + c + 1], e.y);
            }
        }
    } else {
#pragma unroll
        for (int nt = 0; nt < NT; nt++) {
            int c = nt * 8 + tg * 2;
            float ga0 = gamma[c], ga1 = gamma[c + 1], be0 = beta[c], be1 = beta[c + 1];
            if (ok0) {
                float t0 = (acc[nt].x - m0) * rs0 * ga0 + be0;
                float t1 = (acc[nt].y - m0) * rs0 * ga1 + be1;
                float2 e = *(float2*)&xbuf[(size_t)r0 * DD + c];
                e.x += t0; e.y += t1;
                *(float2*)&xbuf[(size_t)r0 * DD + c] = e;
            }
            if (ok1) {
                float t0 = (acc[nt].z - m1) * rs1 * ga0 + be0;
                float t1 = (acc[nt].w - m1) * rs1 * ga1 + be1;
                float2 e = *(float2*)&xbuf[(size_t)r1 * DD + c];
                e.x += t0; e.y += t1;
                *(float2*)&xbuf[(size_t)r1 * DD + c] = e;
            }
        }
    }
}

// ---------------- host launcher ----------------
extern "C" void kernel_launch(void* const* d_in, const int* in_sizes, int n_in,
                              void* d_out, int out_size) {
    const float* x    = (const float*)d_in[0];
    const int*   ei   = (const int*)d_in[1];
    const float* ea   = (const float*)d_in[2];
    const float* ew1  = (const float*)d_in[3];
    const float* eb1  = (const float*)d_in[4];
    const float* eg1  = (const float*)d_in[5];
    const float* ebt1 = (const float*)d_in[6];
    const float* ew2  = (const float*)d_in[7];
    const float* eb2  = (const float*)d_in[8];
    const float* eg2  = (const float*)d_in[9];
    const float* ebt2 = (const float*)d_in[10];
    const float* nw1  = (const float*)d_in[11];
    const float* nb1  = (const float*)d_in[12];
    const float* ng1  = (const float*)d_in[13];
    const float* nbt1 = (const float*)d_in[14];
    const float* nw2  = (const float*)d_in[15];
    const float* nb2  = (const float*)d_in[16];
    const float* ng2  = (const float*)d_in[17];
    const float* nbt2 = (const float*)d_in[18];

    float* xo = (float*)d_out;
    float* eo = xo + (size_t)NN * DD;
    const int* rowi = ei;
    const int* coli = ei + NE;

    uint4 *ew1p, *ew2p, *nw1p, *nw2p;
    cudaGetSymbolAddress((void**)&ew1p, g_ew1p);
    cudaGetSymbolAddress((void**)&ew2p, g_ew2p);
    cudaGetSymbolAddress((void**)&nw1p, g_nw1p);
    cudaGetSymbolAddress((void**)&nw2p, g_nw2p);

    // pack weights into B-fragment layout
    {
        int t1 = NLAYERS * 24 * 32 * 32;
        int t2 = NLAYERS * 16 * 16 * 32;
        int t3 = NLAYERS * 16 * 32 * 32;
        pack_w<<<(t1 + 255) / 256, 256>>>(ew1, ew1p, 24, 32, 384, 256, t1);
        pack_w<<<(t2 + 255) / 256, 256>>>(ew2, ew2p, 16, 16, 256, 128, t2);
        pack_w<<<(t3 + 255) / 256, 256>>>(nw1, nw1p, 16, 32, 256, 256, t3);
        pack_w<<<(t2 + 255) / 256, 256>>>(nw2, nw2p, 16, 16, 256, 128, t2);
    }

    copy_kernel<<<(NN * DD + 255) / 256, 256>>>(x, xo, NN * DD);
    copy_kernel<<<(NE * DD + 255) / 256, 256>>>(ea, eo, NE * DD);
    zero_cnt_kernel<<<(NN + 255) / 256, 256>>>();
    count_kernel<<<(NE + 255) / 256, 256>>>(coli);
    invcnt_kernel<<<(NN + 255) / 256, 256>>>();

    const int EG = (ERT + 3) / 4;  // 938
    const int NG = (NRT + 3) / 4;  // 157

    for (int l = 0; l < NLAYERS; l++) {
        zero_agg_kernel<<<(NN * DD + 255) / 256, 256>>>();
        gemm_mma<24, 32, 0><<<EG, 128>>>(
            ew1p + (size_t)l * 24 * 32 * 32,
            eb1 + l * 256, eg1 + l * 256, ebt1 + l * 256, xo, eo, rowi, coli, NE);
        gemm_mma<16, 16, 1><<<EG, 128>>>(
            ew2p + (size_t)l * 16 * 16 * 32,
            eb2 + l * 128, eg2 + l * 128, ebt2 + l * 128, xo, eo, rowi, coli, NE);
        gemm_mma<16, 32, 2><<<NG, 128>>>(
            nw1p + (size_t)l * 16 * 32 * 32,
            nb1 + l * 256, ng1 + l * 256, nbt1 + l * 256, xo, eo, rowi, coli, NN);
        gemm_mma<16, 16, 3><<<NG, 128>>>(
            nw2p + (size_t)l * 16 * 16 * 32,
            nb2 + l * 128, ng2 + l * 128, nbt2 + l * 128, xo, eo, rowi, coli, NN);
    }
}

// round 8
// speedup vs baseline: 1.9915x; 1.5365x over previous
#include <cuda_runtime.h>
#include <cuda_bf16.h>
#include <math.h>
#include <stdint.h>

#define NN 10000
#define NE 60000
#define DD 128
#define NLAYERS 15

#define ERT 3750   // edge row tiles (60000/16)
#define NRT 625    // node row tiles (10000/16)

// ---------------- device scratch (allocation-free) ----------------
__device__ float g_agg[NN * DD];    // per-node aggregated edge features
__device__ float g_cnt[NN];         // 1/max(count,1)

// hidden activations pre-packed as bf16 hi/lo A-fragments:
// layout [rowtile][ktile][lane][{hi uint4, lo uint4}]
__device__ uint4 g_H1p[ERT * 16 * 32 * 2];   // edge hidden (K=256 -> 16 ktiles)
__device__ uint4 g_Hn1p[NRT * 16 * 32 * 2];  // node hidden

// weights pre-packed as B-fragments {bh0,bh1,bl0,bl1}:
// layout [layer][ktile][ntile][lane]
__device__ uint4 g_ew1p[NLAYERS * 24 * 32 * 32];
__device__ uint4 g_ew2p[NLAYERS * 16 * 16 * 32];
__device__ uint4 g_nw1p[NLAYERS * 16 * 32 * 32];
__device__ uint4 g_nw2p[NLAYERS * 16 * 16 * 32];

// ---------------- helpers ----------------
__device__ __forceinline__ uint32_t pkh(float a, float b) {
    __nv_bfloat162 t = __floats2bfloat162_rn(a, b);
    return *(uint32_t*)&t;
}
__device__ __forceinline__ uint32_t pkl(float a, float b) {
    __nv_bfloat16 ha = __float2bfloat16(a), hb = __float2bfloat16(b);
    return pkh(a - __bfloat162float(ha), b - __bfloat162float(hb));
}

#define MMA4(d, a, b0, b1) \
    asm volatile("mma.sync.aligned.m16n8k16.row.col.f32.bf16.bf16.f32 " \
                 "{%0,%1,%2,%3},{%4,%5,%6,%7},{%8,%9},{%0,%1,%2,%3};" \
                 : "+f"((d).x), "+f"((d).y), "+f"((d).z), "+f"((d).w) \
                 : "r"((a)[0]), "r"((a)[1]), "r"((a)[2]), "r"((a)[3]), \
                   "r"(b0), "r"(b1))

// ---------------- aux kernels ----------------
__global__ void copy_kernel(const float* __restrict__ src, float* __restrict__ dst, int n) {
    int i = blockIdx.x * blockDim.x + threadIdx.x;
    if (i < n) dst[i] = src[i];
}
__global__ void zero_cnt_kernel() {
    int i = blockIdx.x * blockDim.x + threadIdx.x;
    if (i < NN) g_cnt[i] = 0.f;
}
__global__ void count_kernel(const int* __restrict__ col) {
    int e = blockIdx.x * blockDim.x + threadIdx.x;
    if (e < NE) atomicAdd(&g_cnt[col[e]], 1.f);
}
__global__ void invcnt_kernel() {
    int i = blockIdx.x * blockDim.x + threadIdx.x;
    if (i < NN) g_cnt[i] = 1.f / fmaxf(g_cnt[i], 1.f);
}
__global__ void zero_agg_kernel() {
    int i = blockIdx.x * blockDim.x + threadIdx.x;
    if (i < NN * DD) g_agg[i] = 0.f;
}

// Pre-pack fp32 W[L][K][N] into per-lane B fragments {bh0,bh1,bl0,bl1}.
__global__ void pack_w(const float* __restrict__ W, uint4* __restrict__ out,
                       int KT, int NT, int K, int N, int total) {
    int idx = blockIdx.x * blockDim.x + threadIdx.x;
    if (idx >= total) return;
    int lane = idx & 31;
    int t = idx >> 5;
    int nt = t % NT; t /= NT;
    int kt = t % KT;
    int l = t / KT;
    int g = lane >> 2, tg = lane & 3;
    const float* Wl = W + (size_t)l * K * N;
    int n = nt * 8 + g;
    int ka = kt * 16 + tg * 2;
    float v00 = Wl[(size_t)ka * N + n];
    float v01 = Wl[(size_t)(ka + 1) * N + n];
    float v10 = Wl[(size_t)(ka + 8) * N + n];
    float v11 = Wl[(size_t)(ka + 9) * N + n];
    uint4 o;
    o.x = pkh(v00, v01);
    o.y = pkh(v10, v11);
    o.z = pkl(v00, v01);
    o.w = pkl(v10, v11);
    out[idx] = o;
}

// ---------------- fused HMMA GEMM + LN kernel ----------------
// MODE 0: edge L1: A=[x[row]|x[col]|ea] K=384, N=256, LN+GELU -> g_H1p (packed)
// MODE 1: edge L2: A=g_H1p K=256, N=128, LN + residual(ea) + atomic agg scatter
// MODE 2: node L1: A=[x | agg*invcnt] K=256, N=256, LN+GELU -> g_Hn1p (packed)
// MODE 3: node L2: A=g_Hn1p K=256, N=128, LN + residual(x)
// CTA = 8 warps = 128 rows; warp owns 16 rows x full N; LN = quad shfl.
// B fragments staged in double-buffered smem, shared by all 8 warps (8x less L2).
template <int KT, int NT, int MODE>
__global__ void __launch_bounds__(256)
gemm_mma(const uint4* __restrict__ Wp, const float* __restrict__ bias,
         const float* __restrict__ gamma, const float* __restrict__ beta,
         float* __restrict__ xbuf, float* __restrict__ eabuf,
         const int* __restrict__ rowi, const int* __restrict__ coli, int M) {
    constexpr int BN = NT * 8;
    constexpr int SLAB = NT * 32;  // uint4 per k-tile B slab
    __shared__ uint4 sB[2][SLAB];

    const int tid = threadIdx.x;
    const int lane = tid & 31;
    const int warp = tid >> 5;
    const int g = lane >> 2, tg = lane & 3;
    const int rt = blockIdx.x * 8 + warp;
    const int RT = (M + 15) >> 4;
    const int rta = min(rt, RT - 1);
    const int r0 = rt * 16 + g, r1 = r0 + 8;
    const int r0c = min(r0, M - 1), r1c = min(r1, M - 1);

    const float *p00 = nullptr, *p01 = nullptr, *p02 = nullptr;
    const float *p10 = nullptr, *p11 = nullptr, *p12 = nullptr;
    float ic0 = 1.f, ic1 = 1.f;
    const uint4* Ap = nullptr;
    if (MODE == 0) {
        p00 = xbuf + (size_t)rowi[r0c] * DD;
        p01 = xbuf + (size_t)coli[r0c] * DD;
        p02 = eabuf + (size_t)r0c * DD;
        p10 = xbuf + (size_t)rowi[r1c] * DD;
        p11 = xbuf + (size_t)coli[r1c] * DD;
        p12 = eabuf + (size_t)r1c * DD;
    } else if (MODE == 2) {
        p00 = xbuf + (size_t)r0c * DD;
        p01 = g_agg + (size_t)r0c * DD;
        p10 = xbuf + (size_t)r1c * DD;
        p11 = g_agg + (size_t)r1c * DD;
        ic0 = g_cnt[r0c];
        ic1 = g_cnt[r1c];
    } else {
        Ap = (MODE == 1 ? g_H1p : g_Hn1p) + (size_t)rta * KT * 64 + lane * 2;
    }

    float4 acc[NT];
#pragma unroll
    for (int i = 0; i < NT; i++) acc[i] = make_float4(0.f, 0.f, 0.f, 0.f);

    // preload B slab for kt=0
#pragma unroll
    for (int i = 0; i < SLAB / 256; i++) sB[0][tid + 256 * i] = Wp[tid + 256 * i];
    __syncthreads();

    for (int kt = 0; kt < KT; kt++) {
        // prefetch next slab into the other buffer (readers of it synced last iter)
        if (kt + 1 < KT) {
            const uint4* Bg = Wp + (size_t)(kt + 1) * SLAB;
            uint4* Sn = sB[(kt + 1) & 1];
#pragma unroll
            for (int i = 0; i < SLAB / 256; i++) Sn[tid + 256 * i] = Bg[tid + 256 * i];
        }

        uint32_t ah[4], al[4];
        if (MODE == 1 || MODE == 3) {
            uint4 h = Ap[(size_t)kt * 64];
            uint4 lo = Ap[(size_t)kt * 64 + 1];
            ah[0] = h.x; ah[1] = h.y; ah[2] = h.z; ah[3] = h.w;
            al[0] = lo.x; al[1] = lo.y; al[2] = lo.z; al[3] = lo.w;
        } else {
            int seg = kt >> 3;
            int ko = (kt & 7) * 16 + tg * 2;
            const float *q0, *q1;
            float s0 = 1.f, s1 = 1.f;
            if (MODE == 0) {
                q0 = (seg == 0) ? p00 : (seg == 1) ? p01 : p02;
                q1 = (seg == 0) ? p10 : (seg == 1) ? p11 : p12;
            } else {
                q0 = (seg == 0) ? p00 : p01;
                q1 = (seg == 0) ? p10 : p11;
                if (seg == 1) { s0 = ic0; s1 = ic1; }
            }
            float2 a0 = *(const float2*)(q0 + ko);
            float2 a2 = *(const float2*)(q0 + ko + 8);
            float2 b0 = *(const float2*)(q1 + ko);
            float2 b2 = *(const float2*)(q1 + ko + 8);
            a0.x *= s0; a0.y *= s0; a2.x *= s0; a2.y *= s0;
            b0.x *= s1; b0.y *= s1; b2.x *= s1; b2.y *= s1;
            ah[0] = pkh(a0.x, a0.y); ah[1] = pkh(b0.x, b0.y);
            ah[2] = pkh(a2.x, a2.y); ah[3] = pkh(b2.x, b2.y);
            al[0] = pkl(a0.x, a0.y); al[1] = pkl(b0.x, b0.y);
            al[2] = pkl(a2.x, a2.y); al[3] = pkl(b2.x, b2.y);
        }
        const uint4* Bs = sB[kt & 1] + lane;
#pragma unroll
        for (int nt = 0; nt < NT; nt++) {
            uint4 b = Bs[nt * 32];
            MMA4(acc[nt], ah, b.x, b.y);  // hi * hi
            MMA4(acc[nt], ah, b.z, b.w);  // hi * lo
            MMA4(acc[nt], al, b.x, b.y);  // lo * hi
        }
        __syncthreads();
    }

    // ---- bias + LN stats (rows r0, r1); reduce across the lane quad ----
    float s0 = 0.f, q0s = 0.f, s1 = 0.f, q1s = 0.f;
#pragma unroll
    for (int nt = 0; nt < NT; nt++) {
        int c = nt * 8 + tg * 2;
        float bx = bias[c], by = bias[c + 1];
        acc[nt].x += bx; acc[nt].y += by;
        acc[nt].z += bx; acc[nt].w += by;
        s0 += acc[nt].x + acc[nt].y;
        q0s += acc[nt].x * acc[nt].x + acc[nt].y * acc[nt].y;
        s1 += acc[nt].z + acc[nt].w;
        q1s += acc[nt].z * acc[nt].z + acc[nt].w * acc[nt].w;
    }
#pragma unroll
    for (int off = 1; off <= 2; off <<= 1) {
        s0 += __shfl_xor_sync(0xffffffffu, s0, off);
        q0s += __shfl_xor_sync(0xffffffffu, q0s, off);
        s1 += __shfl_xor_sync(0xffffffffu, s1, off);
        q1s += __shfl_xor_sync(0xffffffffu, q1s, off);
    }
    const float inv = 1.f / (float)BN;
    float m0 = s0 * inv, v0 = q0s * inv - m0 * m0, rs0 = rsqrtf(v0 + 1e-5f);
    float m1 = s1 * inv, v1 = q1s * inv - m1 * m1, rs1 = rsqrtf(v1 + 1e-5f);

    const bool ok0 = r0 < M, ok1 = r1 < M;

    if (MODE == 0 || MODE == 2) {
        uint4* Hp = (MODE == 0 ? g_H1p : g_Hn1p);
#pragma unroll
        for (int kt = 0; kt < NT / 2; kt++) {
            int c = kt * 16 + tg * 2;
            float ga0 = gamma[c], ga1 = gamma[c + 1], be0 = beta[c], be1 = beta[c + 1];
            float ga2 = gamma[c + 8], ga3 = gamma[c + 9], be2 = beta[c + 8], be3 = beta[c + 9];
            float tv[8];
            tv[0] = (acc[2 * kt].x - m0) * rs0 * ga0 + be0;
            tv[1] = (acc[2 * kt].y - m0) * rs0 * ga1 + be1;
            tv[2] = (acc[2 * kt].z - m1) * rs1 * ga0 + be0;
            tv[3] = (acc[2 * kt].w - m1) * rs1 * ga1 + be1;
            tv[4] = (acc[2 * kt + 1].x - m0) * rs0 * ga2 + be2;
            tv[5] = (acc[2 * kt + 1].y - m0) * rs0 * ga3 + be3;
            tv[6] = (acc[2 * kt + 1].z - m1) * rs1 * ga2 + be2;
            tv[7] = (acc[2 * kt + 1].w - m1) * rs1 * ga3 + be3;
#pragma unroll
            for (int j = 0; j < 8; j++)
                tv[j] = 0.5f * tv[j] * (1.f + erff(tv[j] * 0.70710678118654752f));  // exact GELU
            uint4 oh, ol;
            oh.x = pkh(tv[0], tv[1]); oh.y = pkh(tv[2], tv[3]);
            oh.z = pkh(tv[4], tv[5]); oh.w = pkh(tv[6], tv[7]);
            ol.x = pkl(tv[0], tv[1]); ol.y = pkl(tv[2], tv[3]);
            ol.z = pkl(tv[4], tv[5]); ol.w = pkl(tv[6], tv[7]);
            if (ok0) {
                size_t o = ((size_t)rt * (NT / 2) + kt) * 64 + lane * 2;
                Hp[o] = oh;
                Hp[o + 1] = ol;
            }
        }
    } else if (MODE == 1) {
        int d0 = coli[r0c], d1 = coli[r1c];
#pragma unroll
        for (int nt = 0; nt < NT; nt++) {
            int c = nt * 8 + tg * 2;
            float ga0 = gamma[c], ga1 = gamma[c + 1], be0 = beta[c], be1 = beta[c + 1];
            if (ok0) {
                float t0 = (acc[nt].x - m0) * rs0 * ga0 + be0;
                float t1 = (acc[nt].y - m0) * rs0 * ga1 + be1;
                float2 e = *(float2*)&eabuf[(size_t)r0 * DD + c];
                e.x += t0; e.y += t1;
                *(float2*)&eabuf[(size_t)r0 * DD + c] = e;
                atomicAdd(&g_agg[(size_t)d0 * DD + c], e.x);
                atomicAdd(&g_agg[(size_t)d0 * DD + c + 1], e.y);
            }
            if (ok1) {
                float t0 = (acc[nt].z - m1) * rs1 * ga0 + be0;
                float t1 = (acc[nt].w - m1) * rs1 * ga1 + be1;
                float2 e = *(float2*)&eabuf[(size_t)r1 * DD + c];
                e.x += t0; e.y += t1;
                *(float2*)&eabuf[(size_t)r1 * DD + c] = e;
                atomicAdd(&g_agg[(size_t)d1 * DD + c], e.x);
                atomicAdd(&g_agg[(size_t)d1 * DD + c + 1], e.y);
            }
        }
    } else {
#pragma unroll
        for (int nt = 0; nt < NT; nt++) {
            int c = nt * 8 + tg * 2;
            float ga0 = gamma[c], ga1 = gamma[c + 1], be0 = beta[c], be1 = beta[c + 1];
            if (ok0) {
                float t0 = (acc[nt].x - m0) * rs0 * ga0 + be0;
                float t1 = (acc[nt].y - m0) * rs0 * ga1 + be1;
                float2 e = *(float2*)&xbuf[(size_t)r0 * DD + c];
                e.x += t0; e.y += t1;
                *(float2*)&xbuf[(size_t)r0 * DD + c] = e;
            }
            if (ok1) {
                float t0 = (acc[nt].z - m1) * rs1 * ga0 + be0;
                float t1 = (acc[nt].w - m1) * rs1 * ga1 + be1;
                float2 e = *(float2*)&xbuf[(size_t)r1 * DD + c];
                e.x += t0; e.y += t1;
                *(float2*)&xbuf[(size_t)r1 * DD + c] = e;
            }
        }
    }
}

// ---------------- host launcher ----------------
extern "C" void kernel_launch(void* const* d_in, const int* in_sizes, int n_in,
                              void* d_out, int out_size) {
    const float* x    = (const float*)d_in[0];
    const int*   ei   = (const int*)d_in[1];
    const float* ea   = (const float*)d_in[2];
    const float* ew1  = (const float*)d_in[3];
    const float* eb1  = (const float*)d_in[4];
    const float* eg1  = (const float*)d_in[5];
    const float* ebt1 = (const float*)d_in[6];
    const float* ew2  = (const float*)d_in[7];
    const float* eb2  = (const float*)d_in[8];
    const float* eg2  = (const float*)d_in[9];
    const float* ebt2 = (const float*)d_in[10];
    const float* nw1  = (const float*)d_in[11];
    const float* nb1  = (const float*)d_in[12];
    const float* ng1  = (const float*)d_in[13];
    const float* nbt1 = (const float*)d_in[14];
    const float* nw2  = (const float*)d_in[15];
    const float* nb2  = (const float*)d_in[16];
    const float* ng2  = (const float*)d_in[17];
    const float* nbt2 = (const float*)d_in[18];

    float* xo = (float*)d_out;
    float* eo = xo + (size_t)NN * DD;
    const int* rowi = ei;
    const int* coli = ei + NE;

    uint4 *ew1p, *ew2p, *nw1p, *nw2p;
    cudaGetSymbolAddress((void**)&ew1p, g_ew1p);
    cudaGetSymbolAddress((void**)&ew2p, g_ew2p);
    cudaGetSymbolAddress((void**)&nw1p, g_nw1p);
    cudaGetSymbolAddress((void**)&nw2p, g_nw2p);

    // pack weights into B-fragment layout
    {
        int t1 = NLAYERS * 24 * 32 * 32;
        int t2 = NLAYERS * 16 * 16 * 32;
        int t3 = NLAYERS * 16 * 32 * 32;
        pack_w<<<(t1 + 255) / 256, 256>>>(ew1, ew1p, 24, 32, 384, 256, t1);
        pack_w<<<(t2 + 255) / 256, 256>>>(ew2, ew2p, 16, 16, 256, 128, t2);
        pack_w<<<(t3 + 255) / 256, 256>>>(nw1, nw1p, 16, 32, 256, 256, t3);
        pack_w<<<(t2 + 255) / 256, 256>>>(nw2, nw2p, 16, 16, 256, 128, t2);
    }

    copy_kernel<<<(NN * DD + 255) / 256, 256>>>(x, xo, NN * DD);
    copy_kernel<<<(NE * DD + 255) / 256, 256>>>(ea, eo, NE * DD);
    zero_cnt_kernel<<<(NN + 255) / 256, 256>>>();
    count_kernel<<<(NE + 255) / 256, 256>>>(coli);
    invcnt_kernel<<<(NN + 255) / 256, 256>>>();

    const int EG = (ERT + 7) / 8;  // 469
    const int NG = (NRT + 7) / 8;  // 79

    for (int l = 0; l < NLAYERS; l++) {
        zero_agg_kernel<<<(NN * DD + 255) / 256, 256>>>();
        gemm_mma<24, 32, 0><<<EG, 256>>>(
            ew1p + (size_t)l * 24 * 32 * 32,
            eb1 + l * 256, eg1 + l * 256, ebt1 + l * 256, xo, eo, rowi, coli, NE);
        gemm_mma<16, 16, 1><<<EG, 256>>>(
            ew2p + (size_t)l * 16 * 16 * 32,
            eb2 + l * 128, eg2 + l * 128, ebt2 + l * 128, xo, eo, rowi, coli, NE);
        gemm_mma<16, 32, 2><<<NG, 256>>>(
            nw1p + (size_t)l * 16 * 32 * 32,
            nb1 + l * 256, ng1 + l * 256, nbt1 + l * 256, xo, eo, rowi, coli, NN);
        gemm_mma<16, 16, 3><<<NG, 256>>>(
            nw2p + (size_t)l * 16 * 16 * 32,
            nb2 + l * 128, ng2 + l * 128, nbt2 + l * 128, xo, eo, rowi, coli, NN);
    }
}

// round 9
// speedup vs baseline: 2.2030x; 1.1062x over previous
#include <cuda_runtime.h>
#include <cuda_bf16.h>
#include <math.h>
#include <stdint.h>

#define NN 10000
#define NE 60000
#define DD 128
#define NLAYERS 15

#define ERT 3750   // edge row tiles (60000/16)
#define NRT 625    // node row tiles (10000/16)

// ---------------- device scratch (allocation-free) ----------------
__device__ float g_agg[NN * DD];    // per-node aggregated edge features
__device__ float g_cnt[NN];         // 1/max(count,1)

// hidden activations pre-packed as bf16 hi/lo A-fragments:
// layout [rowtile][ktile][lane][{hi uint4, lo uint4}]
__device__ uint4 g_H1p[ERT * 16 * 32 * 2];   // edge hidden (K=256 -> 16 ktiles)
__device__ uint4 g_Hn1p[NRT * 16 * 32 * 2];  // node hidden

// weights pre-packed as B-fragments {bh0,bh1,bl0,bl1}:
// layout [layer][ktile][ntile][lane]
__device__ uint4 g_ew1p[NLAYERS * 24 * 32 * 32];
__device__ uint4 g_ew2p[NLAYERS * 16 * 16 * 32];
__device__ uint4 g_nw1p[NLAYERS * 16 * 32 * 32];
__device__ uint4 g_nw2p[NLAYERS * 16 * 16 * 32];

// ---------------- helpers ----------------
__device__ __forceinline__ uint32_t pkh(float a, float b) {
    __nv_bfloat162 t = __floats2bfloat162_rn(a, b);
    return *(uint32_t*)&t;
}
__device__ __forceinline__ uint32_t pkl(float a, float b) {
    __nv_bfloat16 ha = __float2bfloat16(a), hb = __float2bfloat16(b);
    return pkh(a - __bfloat162float(ha), b - __bfloat162float(hb));
}

#define MMA4(d, a, b0, b1) \
    asm volatile("mma.sync.aligned.m16n8k16.row.col.f32.bf16.bf16.f32 " \
                 "{%0,%1,%2,%3},{%4,%5,%6,%7},{%8,%9},{%0,%1,%2,%3};" \
                 : "+f"((d).x), "+f"((d).y), "+f"((d).z), "+f"((d).w) \
                 : "r"((a)[0]), "r"((a)[1]), "r"((a)[2]), "r"((a)[3]), \
                   "r"(b0), "r"(b1))

// ---------------- aux kernels ----------------
__global__ void copy_kernel(const float* __restrict__ src, float* __restrict__ dst, int n) {
    int i = blockIdx.x * blockDim.x + threadIdx.x;
    if (i < n) dst[i] = src[i];
}
__global__ void zero_cnt_kernel() {
    int i = blockIdx.x * blockDim.x + threadIdx.x;
    if (i < NN) g_cnt[i] = 0.f;
}
__global__ void count_kernel(const int* __restrict__ col) {
    int e = blockIdx.x * blockDim.x + threadIdx.x;
    if (e < NE) atomicAdd(&g_cnt[col[e]], 1.f);
}
__global__ void invcnt_kernel() {
    int i = blockIdx.x * blockDim.x + threadIdx.x;
    if (i < NN) g_cnt[i] = 1.f / fmaxf(g_cnt[i], 1.f);
}
__global__ void zero_agg_kernel() {
    int i = blockIdx.x * blockDim.x + threadIdx.x;
    if (i < NN * DD) g_agg[i] = 0.f;
}

// Pre-pack fp32 W[L][K][N] into per-lane B fragments {bh0,bh1,bl0,bl1}.
__global__ void pack_w(const float* __restrict__ W, uint4* __restrict__ out,
                       int KT, int NT, int K, int N, int total) {
    int idx = blockIdx.x * blockDim.x + threadIdx.x;
    if (idx >= total) return;
    int lane = idx & 31;
    int t = idx >> 5;
    int nt = t % NT; t /= NT;
    int kt = t % KT;
    int l = t / KT;
    int g = lane >> 2, tg = lane & 3;
    const float* Wl = W + (size_t)l * K * N;
    int n = nt * 8 + g;
    int ka = kt * 16 + tg * 2;
    float v00 = Wl[(size_t)ka * N + n];
    float v01 = Wl[(size_t)(ka + 1) * N + n];
    float v10 = Wl[(size_t)(ka + 8) * N + n];
    float v11 = Wl[(size_t)(ka + 9) * N + n];
    uint4 o;
    o.x = pkh(v00, v01);
    o.y = pkh(v10, v11);
    o.z = pkl(v00, v01);
    o.w = pkl(v10, v11);
    out[idx] = o;
}

// ---------------- fused HMMA GEMM + LN kernel ----------------
// MODE 0: edge L1: A=[x[row]|x[col]|ea] K=384, N=256, LN+GELU -> g_H1p (packed)
// MODE 1: edge L2: A=g_H1p K=256, N=128, LN + residual(ea) + atomic agg scatter
// MODE 2: node L1: A=[x | agg*invcnt] K=256, N=256, LN+GELU -> g_Hn1p; zeroes g_agg
// MODE 3: node L2: A=g_Hn1p K=256, N=128, LN + residual(x)
// CTA = 8 warps = 128 rows; warp owns 16 rows x full N; LN = quad shfl.
// B fragments: 4-stage cp.async smem ring shared by all 8 warps.
// A operands: register-pipelined one k-tile ahead.
template <int KT, int NT, int MODE>
__global__ void __launch_bounds__(256)
gemm_mma(const uint4* __restrict__ Wp, const float* __restrict__ bias,
         const float* __restrict__ gamma, const float* __restrict__ beta,
         float* __restrict__ xbuf, float* __restrict__ eabuf,
         const int* __restrict__ rowi, const int* __restrict__ coli, int M) {
    constexpr int BN = NT * 8;
    constexpr int SLAB = NT * 32;  // uint4 per k-tile B slab
    extern __shared__ uint4 sB[];  // [4][SLAB]

    const int tid = threadIdx.x;
    const int lane = tid & 31;
    const int warp = tid >> 5;
    const int g = lane >> 2, tg = lane & 3;
    const int rt = blockIdx.x * 8 + warp;
    const int RT = (M + 15) >> 4;
    const int rta = min(rt, RT - 1);
    const int r0 = rt * 16 + g, r1 = r0 + 8;
    const int r0c = min(r0, M - 1), r1c = min(r1, M - 1);

    const float *p00 = nullptr, *p01 = nullptr, *p02 = nullptr;
    const float *p10 = nullptr, *p11 = nullptr, *p12 = nullptr;
    float ic0 = 1.f, ic1 = 1.f;
    const uint4* Ap = nullptr;
    if (MODE == 0) {
        p00 = xbuf + (size_t)rowi[r0c] * DD;
        p01 = xbuf + (size_t)coli[r0c] * DD;
        p02 = eabuf + (size_t)r0c * DD;
        p10 = xbuf + (size_t)rowi[r1c] * DD;
        p11 = xbuf + (size_t)coli[r1c] * DD;
        p12 = eabuf + (size_t)r1c * DD;
    } else if (MODE == 2) {
        p00 = xbuf + (size_t)r0c * DD;
        p01 = g_agg + (size_t)r0c * DD;
        p10 = xbuf + (size_t)r1c * DD;
        p11 = g_agg + (size_t)r1c * DD;
        ic0 = g_cnt[r0c];
        ic1 = g_cnt[r1c];
    } else {
        Ap = (MODE == 1 ? g_H1p : g_Hn1p) + (size_t)rta * KT * 64 + lane * 2;
    }

    // async B slab prefetch into ring slot (kt & 3); always commits a group
    auto prefB = [&](int kt) {
        if (kt < KT) {
            const uint4* src = Wp + (size_t)kt * SLAB + tid;
            uint4* dstp = sB + (kt & 3) * SLAB + tid;
            uint32_t dst = (uint32_t)__cvta_generic_to_shared(dstp);
#pragma unroll
            for (int i = 0; i < SLAB / 256; i++)
                asm volatile("cp.async.cg.shared.global [%0], [%1], 16;"
                             :: "r"(dst + i * 256 * 16), "l"(src + i * 256));
        }
        asm volatile("cp.async.commit_group;" ::: "memory");
    };

    // A operand load for k-tile kt (raw for modes 0/2, packed for 1/3)
    auto loadA = [&](int kt, float2& a0, float2& a2, float2& b0, float2& b2,
                     uint4& h, uint4& l) {
        if (MODE == 1 || MODE == 3) {
            h = Ap[(size_t)kt * 64];
            l = Ap[(size_t)kt * 64 + 1];
        } else {
            int seg = kt >> 3;
            int ko = (kt & 7) * 16 + tg * 2;
            const float *q0, *q1;
            if (MODE == 0) {
                q0 = (seg == 0) ? p00 : (seg == 1) ? p01 : p02;
                q1 = (seg == 0) ? p10 : (seg == 1) ? p11 : p12;
            } else {
                q0 = (seg == 0) ? p00 : p01;
                q1 = (seg == 0) ? p10 : p11;
            }
            a0 = *(const float2*)(q0 + ko);
            a2 = *(const float2*)(q0 + ko + 8);
            b0 = *(const float2*)(q1 + ko);
            b2 = *(const float2*)(q1 + ko + 8);
            if (MODE == 2 && seg == 1) {
                // each agg element is read exactly once across the grid:
                // zero it for the next layer's scatter (replaces zero_agg kernel)
                float2 z = make_float2(0.f, 0.f);
                *(float2*)(const_cast<float*>(q0) + ko) = z;
                *(float2*)(const_cast<float*>(q0) + ko + 8) = z;
                *(float2*)(const_cast<float*>(q1) + ko) = z;
                *(float2*)(const_cast<float*>(q1) + ko + 8) = z;
            }
        }
    };

    float4 acc[NT];
#pragma unroll
    for (int i = 0; i < NT; i++) acc[i] = make_float4(0.f, 0.f, 0.f, 0.f);

    prefB(0); prefB(1); prefB(2);
    float2 ca0 = {}, ca2 = {}, cb0 = {}, cb2 = {};
    uint4 cah = {}, cal = {};
    loadA(0, ca0, ca2, cb0, cb2, cah, cal);

    for (int kt = 0; kt < KT; kt++) {
        asm volatile("cp.async.wait_group 2;" ::: "memory");
        __syncthreads();
        // register-pipeline A for kt+1
        float2 na0 = ca0, na2 = ca2, nb0 = cb0, nb2 = cb2;
        uint4 nah = cah, nal = cal;
        if (kt + 1 < KT) loadA(kt + 1, na0, na2, nb0, nb2, nah, nal);
        // pack current A
        uint32_t ah[4], al[4];
        if (MODE == 1 || MODE == 3) {
            ah[0] = cah.x; ah[1] = cah.y; ah[2] = cah.z; ah[3] = cah.w;
            al[0] = cal.x; al[1] = cal.y; al[2] = cal.z; al[3] = cal.w;
        } else {
            float s0 = 1.f, s1 = 1.f;
            if (MODE == 2 && (kt >> 3) == 1) { s0 = ic0; s1 = ic1; }
            float ax = ca0.x * s0, ay = ca0.y * s0, cx = ca2.x * s0, cy = ca2.y * s0;
            float bx = cb0.x * s1, by = cb0.y * s1, dx = cb2.x * s1, dy = cb2.y * s1;
            ah[0] = pkh(ax, ay); ah[1] = pkh(bx, by);
            ah[2] = pkh(cx, cy); ah[3] = pkh(dx, dy);
            al[0] = pkl(ax, ay); al[1] = pkl(bx, by);
            al[2] = pkl(cx, cy); al[3] = pkl(dx, dy);
        }
        const uint4* Bs = sB + (kt & 3) * SLAB + lane;
#pragma unroll
        for (int nt = 0; nt < NT; nt++) {
            uint4 b = Bs[nt * 32];
            MMA4(acc[nt], ah, b.x, b.y);  // hi * hi
            MMA4(acc[nt], ah, b.z, b.w);  // hi * lo
            MMA4(acc[nt], al, b.x, b.y);  // lo * hi
        }
        prefB(kt + 3);
        ca0 = na0; ca2 = na2; cb0 = nb0; cb2 = nb2; cah = nah; cal = nal;
    }

    // ---- bias + LN stats (rows r0, r1); reduce across the lane quad ----
    float s0 = 0.f, q0s = 0.f, s1 = 0.f, q1s = 0.f;
#pragma unroll
    for (int nt = 0; nt < NT; nt++) {
        int c = nt * 8 + tg * 2;
        float bx = bias[c], by = bias[c + 1];
        acc[nt].x += bx; acc[nt].y += by;
        acc[nt].z += bx; acc[nt].w += by;
        s0 += acc[nt].x + acc[nt].y;
        q0s += acc[nt].x * acc[nt].x + acc[nt].y * acc[nt].y;
        s1 += acc[nt].z + acc[nt].w;
        q1s += acc[nt].z * acc[nt].z + acc[nt].w * acc[nt].w;
    }
#pragma unroll
    for (int off = 1; off <= 2; off <<= 1) {
        s0 += __shfl_xor_sync(0xffffffffu, s0, off);
        q0s += __shfl_xor_sync(0xffffffffu, q0s, off);
        s1 += __shfl_xor_sync(0xffffffffu, s1, off);
        q1s += __shfl_xor_sync(0xffffffffu, q1s, off);
    }
    const float inv = 1.f / (float)BN;
    float m0 = s0 * inv, v0 = q0s * inv - m0 * m0, rs0 = rsqrtf(v0 + 1e-5f);
    float m1 = s1 * inv, v1 = q1s * inv - m1 * m1, rs1 = rsqrtf(v1 + 1e-5f);

    const bool ok0 = r0 < M, ok1 = r1 < M;

    if (MODE == 0 || MODE == 2) {
        uint4* Hp = (MODE == 0 ? g_H1p : g_Hn1p);
#pragma unroll
        for (int kt = 0; kt < NT / 2; kt++) {
            int c = kt * 16 + tg * 2;
            float ga0 = gamma[c], ga1 = gamma[c + 1], be0 = beta[c], be1 = beta[c + 1];
            float ga2 = gamma[c + 8], ga3 = gamma[c + 9], be2 = beta[c + 8], be3 = beta[c + 9];
            float tv[8];
            tv[0] = (acc[2 * kt].x - m0) * rs0 * ga0 + be0;
            tv[1] = (acc[2 * kt].y - m0) * rs0 * ga1 + be1;
            tv[2] = (acc[2 * kt].z - m1) * rs1 * ga0 + be0;
            tv[3] = (acc[2 * kt].w - m1) * rs1 * ga1 + be1;
            tv[4] = (acc[2 * kt + 1].x - m0) * rs0 * ga2 + be2;
            tv[5] = (acc[2 * kt + 1].y - m0) * rs0 * ga3 + be3;
            tv[6] = (acc[2 * kt + 1].z - m1) * rs1 * ga2 + be2;
            tv[7] = (acc[2 * kt + 1].w - m1) * rs1 * ga3 + be3;
#pragma unroll
            for (int j = 0; j < 8; j++)
                tv[j] = 0.5f * tv[j] * (1.f + erff(tv[j] * 0.70710678118654752f));  // exact GELU
            uint4 oh, ol;
            oh.x = pkh(tv[0], tv[1]); oh.y = pkh(tv[2], tv[3]);
            oh.z = pkh(tv[4], tv[5]); oh.w = pkh(tv[6], tv[7]);
            ol.x = pkl(tv[0], tv[1]); ol.y = pkl(tv[2], tv[3]);
            ol.z = pkl(tv[4], tv[5]); ol.w = pkl(tv[6], tv[7]);
            if (ok0) {
                size_t o = ((size_t)rt * (NT / 2) + kt) * 64 + lane * 2;
                Hp[o] = oh;
                Hp[o + 1] = ol;
            }
        }
    } else if (MODE == 1) {
        int d0 = coli[r0c], d1 = coli[r1c];
#pragma unroll
        for (int nt = 0; nt < NT; nt++) {
            int c = nt * 8 + tg * 2;
            float ga0 = gamma[c], ga1 = gamma[c + 1], be0 = beta[c], be1 = beta[c + 1];
            if (ok0) {
                float t0 = (acc[nt].x - m0) * rs0 * ga0 + be0;
                float t1 = (acc[nt].y - m0) * rs0 * ga1 + be1;
                float2 e = *(float2*)&eabuf[(size_t)r0 * DD + c];
                e.x += t0; e.y += t1;
                *(float2*)&eabuf[(size_t)r0 * DD + c] = e;
                atomicAdd(&g_agg[(size_t)d0 * DD + c], e.x);
                atomicAdd(&g_agg[(size_t)d0 * DD + c + 1], e.y);
            }
            if (ok1) {
                float t0 = (acc[nt].z - m1) * rs1 * ga0 + be0;
                float t1 = (acc[nt].w - m1) * rs1 * ga1 + be1;
                float2 e = *(float2*)&eabuf[(size_t)r1 * DD + c];
                e.x += t0; e.y += t1;
                *(float2*)&eabuf[(size_t)r1 * DD + c] = e;
                atomicAdd(&g_agg[(size_t)d1 * DD + c], e.x);
                atomicAdd(&g_agg[(size_t)d1 * DD + c + 1], e.y);
            }
        }
    } else {
#pragma unroll
        for (int nt = 0; nt < NT; nt++) {
            int c = nt * 8 + tg * 2;
            float ga0 = gamma[c], ga1 = gamma[c + 1], be0 = beta[c], be1 = beta[c + 1];
            if (ok0) {
                float t0 = (acc[nt].x - m0) * rs0 * ga0 + be0;
                float t1 = (acc[nt].y - m0) * rs0 * ga1 + be1;
                float2 e = *(float2*)&xbuf[(size_t)r0 * DD + c];
                e.x += t0; e.y += t1;
                *(float2*)&xbuf[(size_t)r0 * DD + c] = e;
            }
            if (ok1) {
                float t0 = (acc[nt].z - m1) * rs1 * ga0 + be0;
                float t1 = (acc[nt].w - m1) * rs1 * ga1 + be1;
                float2 e = *(float2*)&xbuf[(size_t)r1 * DD + c];
                e.x += t0; e.y += t1;
                *(float2*)&xbuf[(size_t)r1 * DD + c] = e;
            }
        }
    }
}

// ---------------- host launcher ----------------
extern "C" void kernel_launch(void* const* d_in, const int* in_sizes, int n_in,
                              void* d_out, int out_size) {
    const float* x    = (const float*)d_in[0];
    const int*   ei   = (const int*)d_in[1];
    const float* ea   = (const float*)d_in[2];
    const float* ew1  = (const float*)d_in[3];
    const float* eb1  = (const float*)d_in[4];
    const float* eg1  = (const float*)d_in[5];
    const float* ebt1 = (const float*)d_in[6];
    const float* ew2  = (const float*)d_in[7];
    const float* eb2  = (const float*)d_in[8];
    const float* eg2  = (const float*)d_in[9];
    const float* ebt2 = (const float*)d_in[10];
    const float* nw1  = (const float*)d_in[11];
    const float* nb1  = (const float*)d_in[12];
    const float* ng1  = (const float*)d_in[13];
    const float* nbt1 = (const float*)d_in[14];
    const float* nw2  = (const float*)d_in[15];
    const float* nb2  = (const float*)d_in[16];
    const float* ng2  = (const float*)d_in[17];
    const float* nbt2 = (const float*)d_in[18];

    float* xo = (float*)d_out;
    float* eo = xo + (size_t)NN * DD;
    const int* rowi = ei;
    const int* coli = ei + NE;

    uint4 *ew1p, *ew2p, *nw1p, *nw2p;
    cudaGetSymbolAddress((void**)&ew1p, g_ew1p);
    cudaGetSymbolAddress((void**)&ew2p, g_ew2p);
    cudaGetSymbolAddress((void**)&nw1p, g_nw1p);
    cudaGetSymbolAddress((void**)&nw2p, g_nw2p);

    const int SM_BIG = 4 * 32 * 32 * 16;    // 65536 (NT=32)
    const int SM_SMALL = 4 * 16 * 32 * 16;  // 32768 (NT=16)
    cudaFuncSetAttribute(gemm_mma<24, 32, 0>, cudaFuncAttributeMaxDynamicSharedMemorySize, SM_BIG);
    cudaFuncSetAttribute(gemm_mma<16, 16, 1>, cudaFuncAttributeMaxDynamicSharedMemorySize, SM_SMALL);
    cudaFuncSetAttribute(gemm_mma<16, 32, 2>, cudaFuncAttributeMaxDynamicSharedMemorySize, SM_BIG);
    cudaFuncSetAttribute(gemm_mma<16, 16, 3>, cudaFuncAttributeMaxDynamicSharedMemorySize, SM_SMALL);

    // pack weights into B-fragment layout
    {
        int t1 = NLAYERS * 24 * 32 * 32;
        int t2 = NLAYERS * 16 * 16 * 32;
        int t3 = NLAYERS * 16 * 32 * 32;
        pack_w<<<(t1 + 255) / 256, 256>>>(ew1, ew1p, 24, 32, 384, 256, t1);
        pack_w<<<(t2 + 255) / 256, 256>>>(ew2, ew2p, 16, 16, 256, 128, t2);
        pack_w<<<(t3 + 255) / 256, 256>>>(nw1, nw1p, 16, 32, 256, 256, t3);
        pack_w<<<(t2 + 255) / 256, 256>>>(nw2, nw2p, 16, 16, 256, 128, t2);
    }

    copy_kernel<<<(NN * DD + 255) / 256, 256>>>(x, xo, NN * DD);
    copy_kernel<<<(NE * DD + 255) / 256, 256>>>(ea, eo, NE * DD);
    zero_cnt_kernel<<<(NN + 255) / 256, 256>>>();
    count_kernel<<<(NE + 255) / 256, 256>>>(coli);
    invcnt_kernel<<<(NN + 255) / 256, 256>>>();
    zero_agg_kernel<<<(NN * DD + 255) / 256, 256>>>();  // once; mode-2 re-zeroes per layer

    const int EG = (ERT + 7) / 8;  // 469
    const int NG = (NRT + 7) / 8;  // 79

    for (int l = 0; l < NLAYERS; l++) {
        gemm_mma<24, 32, 0><<<EG, 256, SM_BIG>>>(
            ew1p + (size_t)l * 24 * 32 * 32,
            eb1 + l * 256, eg1 + l * 256, ebt1 + l * 256, xo, eo, rowi, coli, NE);
        gemm_mma<16, 16, 1><<<EG, 256, SM_SMALL>>>(
            ew2p + (size_t)l * 16 * 16 * 32,
            eb2 + l * 128, eg2 + l * 128, ebt2 + l * 128, xo, eo, rowi, coli, NE);
        gemm_mma<16, 32, 2><<<NG, 256, SM_BIG>>>(
            nw1p + (size_t)l * 16 * 32 * 32,
            nb1 + l * 256, ng1 + l * 256, nbt1 + l * 256, xo, eo, rowi, coli, NN);
        gemm_mma<16, 16, 3><<<NG, 256, SM_SMALL>>>(
            nw2p + (size_t)l * 16 * 16 * 32,
            nb2 + l * 128, ng2 + l * 128, nbt2 + l * 128, xo, eo, rowi, coli, NN);
    }
}

// round 10
// speedup vs baseline: 2.8615x; 1.2989x over previous
#include <cuda_runtime.h>
#include <cuda_fp16.h>
#include <math.h>
#include <stdint.h>

#define NN 10000
#define NE 60000
#define DD 128
#define NLAYERS 15

#define ERT 3750   // edge row tiles (60000/16)
#define NRT 625    // node row tiles (10000/16)

// ---------------- device scratch (allocation-free) ----------------
__device__ float g_agg[NN * DD];    // per-node aggregated edge features
__device__ float g_cnt[NN];         // 1/max(count,1)

// hidden activations pre-packed as fp16 A-fragments (hi only):
// layout [rowtile][ktile][lane] -> uint4
__device__ uint4 g_H1p[ERT * 16 * 32];   // edge hidden (K=256 -> 16 ktiles)
__device__ uint4 g_Hn1p[NRT * 16 * 32];  // node hidden

// weights pre-packed as B-fragments {bh0,bh1,bl0,bl1} (fp16 hi/lo):
// layout [layer][ktile][ntile][lane]
__device__ uint4 g_ew1p[NLAYERS * 24 * 32 * 32];
__device__ uint4 g_ew2p[NLAYERS * 16 * 16 * 32];
__device__ uint4 g_nw1p[NLAYERS * 16 * 32 * 32];
__device__ uint4 g_nw2p[NLAYERS * 16 * 16 * 32];

// ---------------- helpers ----------------
__device__ __forceinline__ uint32_t pkh(float a, float b) {
    __half2 t = __floats2half2_rn(a, b);
    return *(uint32_t*)&t;
}
__device__ __forceinline__ uint32_t pkl(float a, float b) {
    __half ha = __float2half_rn(a), hb = __float2half_rn(b);
    return pkh(a - __half2float(ha), b - __half2float(hb));
}

#define MMA4(d, a, b0, b1) \
    asm volatile("mma.sync.aligned.m16n8k16.row.col.f32.f16.f16.f32 " \
                 "{%0,%1,%2,%3},{%4,%5,%6,%7},{%8,%9},{%0,%1,%2,%3};" \
                 : "+f"((d).x), "+f"((d).y), "+f"((d).z), "+f"((d).w) \
                 : "r"((a)[0]), "r"((a)[1]), "r"((a)[2]), "r"((a)[3]), \
                   "r"(b0), "r"(b1))

// ---------------- aux kernels ----------------
__global__ void copy_kernel(const float* __restrict__ src, float* __restrict__ dst, int n) {
    int i = blockIdx.x * blockDim.x + threadIdx.x;
    if (i < n) dst[i] = src[i];
}
__global__ void zero_cnt_kernel() {
    int i = blockIdx.x * blockDim.x + threadIdx.x;
    if (i < NN) g_cnt[i] = 0.f;
}
__global__ void count_kernel(const int* __restrict__ col) {
    int e = blockIdx.x * blockDim.x + threadIdx.x;
    if (e < NE) atomicAdd(&g_cnt[col[e]], 1.f);
}
__global__ void invcnt_kernel() {
    int i = blockIdx.x * blockDim.x + threadIdx.x;
    if (i < NN) g_cnt[i] = 1.f / fmaxf(g_cnt[i], 1.f);
}
__global__ void zero_agg_kernel() {
    int i = blockIdx.x * blockDim.x + threadIdx.x;
    if (i < NN * DD) g_agg[i] = 0.f;
}

// Pre-pack fp32 W[L][K][N] into per-lane B fragments {bh0,bh1,bl0,bl1} (fp16).
__global__ void pack_w(const float* __restrict__ W, uint4* __restrict__ out,
                       int KT, int NT, int K, int N, int total) {
    int idx = blockIdx.x * blockDim.x + threadIdx.x;
    if (idx >= total) return;
    int lane = idx & 31;
    int t = idx >> 5;
    int nt = t % NT; t /= NT;
    int kt = t % KT;
    int l = t / KT;
    int g = lane >> 2, tg = lane & 3;
    const float* Wl = W + (size_t)l * K * N;
    int n = nt * 8 + g;
    int ka = kt * 16 + tg * 2;
    float v00 = Wl[(size_t)ka * N + n];
    float v01 = Wl[(size_t)(ka + 1) * N + n];
    float v10 = Wl[(size_t)(ka + 8) * N + n];
    float v11 = Wl[(size_t)(ka + 9) * N + n];
    uint4 o;
    o.x = pkh(v00, v01);
    o.y = pkh(v10, v11);
    o.z = pkl(v00, v01);
    o.w = pkl(v10, v11);
    out[idx] = o;
}

// ---------------- fused HMMA GEMM + LN kernel ----------------
// MODE 0: edge L1: A=[x[row]|x[col]|ea] K=384, N=256, LN+GELU -> g_H1p (packed)
// MODE 1: edge L2: A=g_H1p K=256, N=128, LN + residual(ea) + atomic agg scatter
// MODE 2: node L1: A=[x | agg*invcnt] K=256, N=256, LN+GELU -> g_Hn1p; zeroes g_agg
// MODE 3: node L2: A=g_Hn1p K=256, N=128, LN + residual(x)
// CTA = 8 warps = 128 rows; warp owns 16 rows x full N; LN = quad shfl.
// fp16 2-term: acc = Ah*Wh + Ah*Wl (activations fp16-quantized, weights split).
// B fragments: 4-stage cp.async smem ring shared by all 8 warps.
// A operands: register-pipelined one k-tile ahead.
template <int KT, int NT, int MODE>
__global__ void __launch_bounds__(256)
gemm_mma(const uint4* __restrict__ Wp, const float* __restrict__ bias,
         const float* __restrict__ gamma, const float* __restrict__ beta,
         float* __restrict__ xbuf, float* __restrict__ eabuf,
         const int* __restrict__ rowi, const int* __restrict__ coli, int M) {
    constexpr int BN = NT * 8;
    constexpr int SLAB = NT * 32;  // uint4 per k-tile B slab
    extern __shared__ uint4 sB[];  // [4][SLAB]

    const int tid = threadIdx.x;
    const int lane = tid & 31;
    const int warp = tid >> 5;
    const int g = lane >> 2, tg = lane & 3;
    const int rt = blockIdx.x * 8 + warp;
    const int RT = (M + 15) >> 4;
    const int rta = min(rt, RT - 1);
    const int r0 = rt * 16 + g, r1 = r0 + 8;
    const int r0c = min(r0, M - 1), r1c = min(r1, M - 1);

    const float *p00 = nullptr, *p01 = nullptr, *p02 = nullptr;
    const float *p10 = nullptr, *p11 = nullptr, *p12 = nullptr;
    float ic0 = 1.f, ic1 = 1.f;
    const uint4* Ap = nullptr;
    if (MODE == 0) {
        p00 = xbuf + (size_t)rowi[r0c] * DD;
        p01 = xbuf + (size_t)coli[r0c] * DD;
        p02 = eabuf + (size_t)r0c * DD;
        p10 = xbuf + (size_t)rowi[r1c] * DD;
        p11 = xbuf + (size_t)coli[r1c] * DD;
        p12 = eabuf + (size_t)r1c * DD;
    } else if (MODE == 2) {
        p00 = xbuf + (size_t)r0c * DD;
        p01 = g_agg + (size_t)r0c * DD;
        p10 = xbuf + (size_t)r1c * DD;
        p11 = g_agg + (size_t)r1c * DD;
        ic0 = g_cnt[r0c];
        ic1 = g_cnt[r1c];
    } else {
        Ap = (MODE == 1 ? g_H1p : g_Hn1p) + (size_t)rta * KT * 32 + lane;
    }

    // async B slab prefetch into ring slot (kt & 3); always commits a group
    auto prefB = [&](int kt) {
        if (kt < KT) {
            const uint4* src = Wp + (size_t)kt * SLAB + tid;
            uint4* dstp = sB + (kt & 3) * SLAB + tid;
            uint32_t dst = (uint32_t)__cvta_generic_to_shared(dstp);
#pragma unroll
            for (int i = 0; i < SLAB / 256; i++)
                asm volatile("cp.async.cg.shared.global [%0], [%1], 16;"
                             :: "r"(dst + i * 256 * 16), "l"(src + i * 256));
        }
        asm volatile("cp.async.commit_group;" ::: "memory");
    };

    // A operand load for k-tile kt (raw for modes 0/2, packed for 1/3)
    auto loadA = [&](int kt, float2& a0, float2& a2, float2& b0, float2& b2, uint4& h) {
        if (MODE == 1 || MODE == 3) {
            h = Ap[(size_t)kt * 32];
        } else {
            int seg = kt >> 3;
            int ko = (kt & 7) * 16 + tg * 2;
            const float *q0, *q1;
            if (MODE == 0) {
                q0 = (seg == 0) ? p00 : (seg == 1) ? p01 : p02;
                q1 = (seg == 0) ? p10 : (seg == 1) ? p11 : p12;
            } else {
                q0 = (seg == 0) ? p00 : p01;
                q1 = (seg == 0) ? p10 : p11;
            }
            a0 = *(const float2*)(q0 + ko);
            a2 = *(const float2*)(q0 + ko + 8);
            b0 = *(const float2*)(q1 + ko);
            b2 = *(const float2*)(q1 + ko + 8);
            if (MODE == 2 && seg == 1) {
                // each agg element is read exactly once across the grid:
                // zero it for the next layer's scatter (replaces zero_agg kernel)
                float2 z = make_float2(0.f, 0.f);
                *(float2*)(const_cast<float*>(q0) + ko) = z;
                *(float2*)(const_cast<float*>(q0) + ko + 8) = z;
                *(float2*)(const_cast<float*>(q1) + ko) = z;
                *(float2*)(const_cast<float*>(q1) + ko + 8) = z;
            }
        }
    };

    float4 acc[NT];
#pragma unroll
    for (int i = 0; i < NT; i++) acc[i] = make_float4(0.f, 0.f, 0.f, 0.f);

    prefB(0); prefB(1); prefB(2);
    float2 ca0 = {}, ca2 = {}, cb0 = {}, cb2 = {};
    uint4 cah = {};
    loadA(0, ca0, ca2, cb0, cb2, cah);

    for (int kt = 0; kt < KT; kt++) {
        asm volatile("cp.async.wait_group 2;" ::: "memory");
        __syncthreads();
        // register-pipeline A for kt+1
        float2 na0 = ca0, na2 = ca2, nb0 = cb0, nb2 = cb2;
        uint4 nah = cah;
        if (kt + 1 < KT) loadA(kt + 1, na0, na2, nb0, nb2, nah);
        // pack current A (fp16 hi only)
        uint32_t ah[4];
        if (MODE == 1 || MODE == 3) {
            ah[0] = cah.x; ah[1] = cah.y; ah[2] = cah.z; ah[3] = cah.w;
        } else {
            float s0 = 1.f, s1 = 1.f;
            if (MODE == 2 && (kt >> 3) == 1) { s0 = ic0; s1 = ic1; }
            ah[0] = pkh(ca0.x * s0, ca0.y * s0);
            ah[1] = pkh(cb0.x * s1, cb0.y * s1);
            ah[2] = pkh(ca2.x * s0, ca2.y * s0);
            ah[3] = pkh(cb2.x * s1, cb2.y * s1);
        }
        const uint4* Bs = sB + (kt & 3) * SLAB + lane;
#pragma unroll
        for (int nt = 0; nt < NT; nt++) {
            uint4 b = Bs[nt * 32];
            MMA4(acc[nt], ah, b.x, b.y);  // Ah * Wh
            MMA4(acc[nt], ah, b.z, b.w);  // Ah * Wl
        }
        prefB(kt + 3);
        ca0 = na0; ca2 = na2; cb0 = nb0; cb2 = nb2; cah = nah;
    }

    // ---- bias + LN stats (rows r0, r1); reduce across the lane quad ----
    float s0 = 0.f, q0s = 0.f, s1 = 0.f, q1s = 0.f;
#pragma unroll
    for (int nt = 0; nt < NT; nt++) {
        int c = nt * 8 + tg * 2;
        float bx = bias[c], by = bias[c + 1];
        acc[nt].x += bx; acc[nt].y += by;
        acc[nt].z += bx; acc[nt].w += by;
        s0 += acc[nt].x + acc[nt].y;
        q0s += acc[nt].x * acc[nt].x + acc[nt].y * acc[nt].y;
        s1 += acc[nt].z + acc[nt].w;
        q1s += acc[nt].z * acc[nt].z + acc[nt].w * acc[nt].w;
    }
#pragma unroll
    for (int off = 1; off <= 2; off <<= 1) {
        s0 += __shfl_xor_sync(0xffffffffu, s0, off);
        q0s += __shfl_xor_sync(0xffffffffu, q0s, off);
        s1 += __shfl_xor_sync(0xffffffffu, s1, off);
        q1s += __shfl_xor_sync(0xffffffffu, q1s, off);
    }
    const float inv = 1.f / (float)BN;
    float m0 = s0 * inv, v0 = q0s * inv - m0 * m0, rs0 = rsqrtf(v0 + 1e-5f);
    float m1 = s1 * inv, v1 = q1s * inv - m1 * m1, rs1 = rsqrtf(v1 + 1e-5f);

    const bool ok0 = r0 < M, ok1 = r1 < M;

    if (MODE == 0 || MODE == 2) {
        uint4* Hp = (MODE == 0 ? g_H1p : g_Hn1p);
#pragma unroll
        for (int kt = 0; kt < NT / 2; kt++) {
            int c = kt * 16 + tg * 2;
            float ga0 = gamma[c], ga1 = gamma[c + 1], be0 = beta[c], be1 = beta[c + 1];
            float ga2 = gamma[c + 8], ga3 = gamma[c + 9], be2 = beta[c + 8], be3 = beta[c + 9];
            float tv[8];
            tv[0] = (acc[2 * kt].x - m0) * rs0 * ga0 + be0;
            tv[1] = (acc[2 * kt].y - m0) * rs0 * ga1 + be1;
            tv[2] = (acc[2 * kt].z - m1) * rs1 * ga0 + be0;
            tv[3] = (acc[2 * kt].w - m1) * rs1 * ga1 + be1;
            tv[4] = (acc[2 * kt + 1].x - m0) * rs0 * ga2 + be2;
            tv[5] = (acc[2 * kt + 1].y - m0) * rs0 * ga3 + be3;
            tv[6] = (acc[2 * kt + 1].z - m1) * rs1 * ga2 + be2;
            tv[7] = (acc[2 * kt + 1].w - m1) * rs1 * ga3 + be3;
#pragma unroll
            for (int j = 0; j < 8; j++)
                tv[j] = 0.5f * tv[j] * (1.f + erff(tv[j] * 0.70710678118654752f));  // exact GELU
            uint4 oh;
            oh.x = pkh(tv[0], tv[1]); oh.y = pkh(tv[2], tv[3]);
            oh.z = pkh(tv[4], tv[5]); oh.w = pkh(tv[6], tv[7]);
            if (ok0) {
                size_t o = ((size_t)rt * (NT / 2) + kt) * 32 + lane;
                Hp[o] = oh;
            }
        }
    } else if (MODE == 1) {
        int d0 = coli[r0c], d1 = coli[r1c];
#pragma unroll
        for (int nt = 0; nt < NT; nt++) {
            int c = nt * 8 + tg * 2;
            float ga0 = gamma[c], ga1 = gamma[c + 1], be0 = beta[c], be1 = beta[c + 1];
            if (ok0) {
                float t0 = (acc[nt].x - m0) * rs0 * ga0 + be0;
                float t1 = (acc[nt].y - m0) * rs0 * ga1 + be1;
                float2 e = *(float2*)&eabuf[(size_t)r0 * DD + c];
                e.x += t0; e.y += t1;
                *(float2*)&eabuf[(size_t)r0 * DD + c] = e;
                atomicAdd(&g_agg[(size_t)d0 * DD + c], e.x);
                atomicAdd(&g_agg[(size_t)d0 * DD + c + 1], e.y);
            }
            if (ok1) {
                float t0 = (acc[nt].z - m1) * rs1 * ga0 + be0;
                float t1 = (acc[nt].w - m1) * rs1 * ga1 + be1;
                float2 e = *(float2*)&eabuf[(size_t)r1 * DD + c];
                e.x += t0; e.y += t1;
                *(float2*)&eabuf[(size_t)r1 * DD + c] = e;
                atomicAdd(&g_agg[(size_t)d1 * DD + c], e.x);
                atomicAdd(&g_agg[(size_t)d1 * DD + c + 1], e.y);
            }
        }
    } else {
#pragma unroll
        for (int nt = 0; nt < NT; nt++) {
            int c = nt * 8 + tg * 2;
            float ga0 = gamma[c], ga1 = gamma[c + 1], be0 = beta[c], be1 = beta[c + 1];
            if (ok0) {
                float t0 = (acc[nt].x - m0) * rs0 * ga0 + be0;
                float t1 = (acc[nt].y - m0) * rs0 * ga1 + be1;
                float2 e = *(float2*)&xbuf[(size_t)r0 * DD + c];
                e.x += t0; e.y += t1;
                *(float2*)&xbuf[(size_t)r0 * DD + c] = e;
            }
            if (ok1) {
                float t0 = (acc[nt].z - m1) * rs1 * ga0 + be0;
                float t1 = (acc[nt].w - m1) * rs1 * ga1 + be1;
                float2 e = *(float2*)&xbuf[(size_t)r1 * DD + c];
                e.x += t0; e.y += t1;
                *(float2*)&xbuf[(size_t)r1 * DD + c] = e;
            }
        }
    }
}

// ---------------- host launcher ----------------
extern "C" void kernel_launch(void* const* d_in, const int* in_sizes, int n_in,
                              void* d_out, int out_size) {
    const float* x    = (const float*)d_in[0];
    const int*   ei   = (const int*)d_in[1];
    const float* ea   = (const float*)d_in[2];
    const float* ew1  = (const float*)d_in[3];
    const float* eb1  = (const float*)d_in[4];
    const float* eg1  = (const float*)d_in[5];
    const float* ebt1 = (const float*)d_in[6];
    const float* ew2  = (const float*)d_in[7];
    const float* eb2  = (const float*)d_in[8];
    const float* eg2  = (const float*)d_in[9];
    const float* ebt2 = (const float*)d_in[10];
    const float* nw1  = (const float*)d_in[11];
    const float* nb1  = (const float*)d_in[12];
    const float* ng1  = (const float*)d_in[13];
    const float* nbt1 = (const float*)d_in[14];
    const float* nw2  = (const float*)d_in[15];
    const float* nb2  = (const float*)d_in[16];
    const float* ng2  = (const float*)d_in[17];
    const float* nbt2 = (const float*)d_in[18];

    float* xo = (float*)d_out;
    float* eo = xo + (size_t)NN * DD;
    const int* rowi = ei;
    const int* coli = ei + NE;

    uint4 *ew1p, *ew2p, *nw1p, *nw2p;
    cudaGetSymbolAddress((void**)&ew1p, g_ew1p);
    cudaGetSymbolAddress((void**)&ew2p, g_ew2p);
    cudaGetSymbolAddress((void**)&nw1p, g_nw1p);
    cudaGetSymbolAddress((void**)&nw2p, g_nw2p);

    const int SM_BIG = 4 * 32 * 32 * 16;    // 65536 (NT=32)
    const int SM_SMALL = 4 * 16 * 32 * 16;  // 32768 (NT=16)
    cudaFuncSetAttribute(gemm_mma<24, 32, 0>, cudaFuncAttributeMaxDynamicSharedMemorySize, SM_BIG);
    cudaFuncSetAttribute(gemm_mma<16, 16, 1>, cudaFuncAttributeMaxDynamicSharedMemorySize, SM_SMALL);
    cudaFuncSetAttribute(gemm_mma<16, 32, 2>, cudaFuncAttributeMaxDynamicSharedMemorySize, SM_BIG);
    cudaFuncSetAttribute(gemm_mma<16, 16, 3>, cudaFuncAttributeMaxDynamicSharedMemorySize, SM_SMALL);

    // pack weights into B-fragment layout
    {
        int t1 = NLAYERS * 24 * 32 * 32;
        int t2 = NLAYERS * 16 * 16 * 32;
        int t3 = NLAYERS * 16 * 32 * 32;
        pack_w<<<(t1 + 255) / 256, 256>>>(ew1, ew1p, 24, 32, 384, 256, t1);
        pack_w<<<(t2 + 255) / 256, 256>>>(ew2, ew2p, 16, 16, 256, 128, t2);
        pack_w<<<(t3 + 255) / 256, 256>>>(nw1, nw1p, 16, 32, 256, 256, t3);
        pack_w<<<(t2 + 255) / 256, 256>>>(nw2, nw2p, 16, 16, 256, 128, t2);
    }

    copy_kernel<<<(NN * DD + 255) / 256, 256>>>(x, xo, NN * DD);
    copy_kernel<<<(NE * DD + 255) / 256, 256>>>(ea, eo, NE * DD);
    zero_cnt_kernel<<<(NN + 255) / 256, 256>>>();
    count_kernel<<<(NE + 255) / 256, 256>>>(coli);
    invcnt_kernel<<<(NN + 255) / 256, 256>>>();
    zero_agg_kernel<<<(NN * DD + 255) / 256, 256>>>();  // once; mode-2 re-zeroes per layer

    const int EG = (ERT + 7) / 8;  // 469
    const int NG = (NRT + 7) / 8;  // 79

    for (int l = 0; l < NLAYERS; l++) {
        gemm_mma<24, 32, 0><<<EG, 256, SM_BIG>>>(
            ew1p + (size_t)l * 24 * 32 * 32,
            eb1 + l * 256, eg1 + l * 256, ebt1 + l * 256, xo, eo, rowi, coli, NE);
        gemm_mma<16, 16, 1><<<EG, 256, SM_SMALL>>>(
            ew2p + (size_t)l * 16 * 16 * 32,
            eb2 + l * 128, eg2 + l * 128, ebt2 + l * 128, xo, eo, rowi, coli, NE);
        gemm_mma<16, 32, 2><<<NG, 256, SM_BIG>>>(
            nw1p + (size_t)l * 16 * 32 * 32,
            nb1 + l * 256, ng1 + l * 256, nbt1 + l * 256, xo, eo, rowi, coli, NN);
        gemm_mma<16, 16, 3><<<NG, 256, SM_SMALL>>>(
            nw2p + (size_t)l * 16 * 16 * 32,
            nb2 + l * 128, ng2 + l * 128, nbt2 + l * 128, xo, eo, rowi, coli, NN);
    }
}

// round 11
// speedup vs baseline: 3.1102x; 1.0869x over previous
#include <cuda_runtime.h>
#include <cuda_fp16.h>
#include <math.h>
#include <stdint.h>

#define NN 10000
#define NE 60000
#define DD 128
#define NLAYERS 15

#define ERT 3750   // edge row tiles (60000/16)
#define NRT 625    // node row tiles (10000/16)

// ---------------- device scratch (allocation-free) ----------------
__device__ float g_agg[NN * DD];    // per-node aggregated edge features
__device__ float g_cnt[NN];         // 1/max(count,1)

// weights pre-packed as B-fragments {bh0,bh1,bl0,bl1} (fp16 hi/lo):
// layout [layer][ktile][ntile][lane]
__device__ uint4 g_ew1p[NLAYERS * 24 * 32 * 32];
__device__ uint4 g_ew2p[NLAYERS * 16 * 16 * 32];
__device__ uint4 g_nw1p[NLAYERS * 16 * 32 * 32];
__device__ uint4 g_nw2p[NLAYERS * 16 * 16 * 32];

// ---------------- helpers ----------------
__device__ __forceinline__ uint32_t pkh(float a, float b) {
    __half2 t = __floats2half2_rn(a, b);
    return *(uint32_t*)&t;
}
__device__ __forceinline__ uint32_t pkl(float a, float b) {
    __half ha = __float2half_rn(a), hb = __float2half_rn(b);
    return pkh(a - __half2float(ha), b - __half2float(hb));
}

// exact-GELU via Abramowitz-Stegun 7.1.26 erf (abs err <= 1.5e-7)
__device__ __forceinline__ float gelu_f(float t) {
    float x = fabsf(t) * 0.70710678118654752f;
    float k = __fdividef(1.f, fmaf(0.3275911f, x, 1.f));
    float p = fmaf(1.061405429f, k, -1.453152027f);
    p = fmaf(p, k, 1.421413741f);
    p = fmaf(p, k, -0.284496736f);
    p = fmaf(p, k, 0.254829592f);
    p = p * k;
    float e = __expf(-x * x);
    float er = copysignf(fmaf(-p, e, 1.f), t);
    return 0.5f * t * (1.f + er);
}

#define MMA4(d, a, b0, b1) \
    asm volatile("mma.sync.aligned.m16n8k16.row.col.f32.f16.f16.f32 " \
                 "{%0,%1,%2,%3},{%4,%5,%6,%7},{%8,%9},{%0,%1,%2,%3};" \
                 : "+f"((d).x), "+f"((d).y), "+f"((d).z), "+f"((d).w) \
                 : "r"((a)[0]), "r"((a)[1]), "r"((a)[2]), "r"((a)[3]), \
                   "r"(b0), "r"(b1))

// async B slab prefetch into 4-deep ring slot (kt & 3); always commits a group
template <int SLAB, int NTH>
__device__ __forceinline__ void pref_slab(uint4* sB, const uint4* Wp, int kt, int KT, int tid) {
    if (kt < KT) {
        const uint4* src = Wp + (size_t)kt * SLAB + tid;
        uint32_t dst = (uint32_t)__cvta_generic_to_shared(sB + (kt & 3) * SLAB + tid);
#pragma unroll
        for (int i = 0; i < SLAB / NTH; i++)
            asm volatile("cp.async.cg.shared.global [%0], [%1], 16;"
                         :: "r"(dst + i * NTH * 16), "l"(src + i * NTH));
    }
    asm volatile("cp.async.commit_group;" ::: "memory");
}
#define CPWAIT2() asm volatile("cp.async.wait_group 2;" ::: "memory")
#define CPWAIT0() asm volatile("cp.async.wait_group 0;" ::: "memory")

// ---------------- aux kernels ----------------
__global__ void copy_kernel(const float* __restrict__ src, float* __restrict__ dst, int n) {
    int i = blockIdx.x * blockDim.x + threadIdx.x;
    if (i < n) dst[i] = src[i];
}
__global__ void zero_cnt_kernel() {
    int i = blockIdx.x * blockDim.x + threadIdx.x;
    if (i < NN) g_cnt[i] = 0.f;
}
__global__ void count_kernel(const int* __restrict__ col) {
    int e = blockIdx.x * blockDim.x + threadIdx.x;
    if (e < NE) atomicAdd(&g_cnt[col[e]], 1.f);
}
__global__ void invcnt_kernel() {
    int i = blockIdx.x * blockDim.x + threadIdx.x;
    if (i < NN) g_cnt[i] = 1.f / fmaxf(g_cnt[i], 1.f);
}
__global__ void zero_agg_kernel() {
    int i = blockIdx.x * blockDim.x + threadIdx.x;
    if (i < NN * DD) g_agg[i] = 0.f;
}

// Pre-pack fp32 W[L][K][N] into per-lane B fragments {bh0,bh1,bl0,bl1} (fp16).
__global__ void pack_w(const float* __restrict__ W, uint4* __restrict__ out,
                       int KT, int NT, int K, int N, int total) {
    int idx = blockIdx.x * blockDim.x + threadIdx.x;
    if (idx >= total) return;
    int lane = idx & 31;
    int t = idx >> 5;
    int nt = t % NT; t /= NT;
    int kt = t % KT;
    int l = t / KT;
    int g = lane >> 2, tg = lane & 3;
    const float* Wl = W + (size_t)l * K * N;
    int n = nt * 8 + g;
    int ka = kt * 16 + tg * 2;
    float v00 = Wl[(size_t)ka * N + n];
    float v01 = Wl[(size_t)(ka + 1) * N + n];
    float v10 = Wl[(size_t)(ka + 8) * N + n];
    float v11 = Wl[(size_t)(ka + 9) * N + n];
    uint4 o;
    o.x = pkh(v00, v01);
    o.y = pkh(v10, v11);
    o.z = pkl(v00, v01);
    o.w = pkl(v10, v11);
    out[idx] = o;
}

// ---------------- fused edge MLP kernel (GEMM1 + LN + GELU + GEMM2 + LN + scatter) ----------------
// A1=[x[row]|x[col]|ea] K=384 N=256; hidden kept in registers as fp16 A-fragments;
// GEMM2 K=256 N=128; out: ea += LN2, atomicAdd into g_agg[col].
__global__ void __launch_bounds__(256)
edge_fused(const uint4* __restrict__ W1, const uint4* __restrict__ W2,
           const float* __restrict__ b1v, const float* __restrict__ g1v, const float* __restrict__ bt1v,
           const float* __restrict__ b2v, const float* __restrict__ g2v, const float* __restrict__ bt2v,
           float* __restrict__ xbuf, float* __restrict__ eabuf,
           const int* __restrict__ rowi, const int* __restrict__ coli) {
    constexpr int KT1 = 24, NT1 = 32, SLAB1 = NT1 * 32;
    constexpr int KT2 = 16, NT2 = 16, SLAB2 = NT2 * 32;
    extern __shared__ uint4 sB[];

    const int tid = threadIdx.x, lane = tid & 31, warp = tid >> 5;
    const int g = lane >> 2, tg = lane & 3;
    const int rt = blockIdx.x * 8 + warp;
    const int r0 = rt * 16 + g, r1 = r0 + 8;
    const int r0c = min(r0, NE - 1), r1c = min(r1, NE - 1);
    const bool ok0 = r0 < NE, ok1 = r1 < NE;

    const float* p00 = xbuf + (size_t)rowi[r0c] * DD;
    const float* p01 = xbuf + (size_t)coli[r0c] * DD;
    const float* p02 = eabuf + (size_t)r0c * DD;
    const float* p10 = xbuf + (size_t)rowi[r1c] * DD;
    const float* p11 = xbuf + (size_t)coli[r1c] * DD;
    const float* p12 = eabuf + (size_t)r1c * DD;

    auto loadA = [&](int kt, float2& a0, float2& a2, float2& b0, float2& b2) {
        int seg = kt >> 3, ko = (kt & 7) * 16 + tg * 2;
        const float* q0 = seg == 0 ? p00 : seg == 1 ? p01 : p02;
        const float* q1 = seg == 0 ? p10 : seg == 1 ? p11 : p12;
        a0 = *(const float2*)(q0 + ko); a2 = *(const float2*)(q0 + ko + 8);
        b0 = *(const float2*)(q1 + ko); b2 = *(const float2*)(q1 + ko + 8);
    };

    // ---- phase 1: GEMM1 ----
    float4 acc[NT1];
#pragma unroll
    for (int i = 0; i < NT1; i++) acc[i] = make_float4(0.f, 0.f, 0.f, 0.f);

    pref_slab<SLAB1, 256>(sB, W1, 0, KT1, tid);
    pref_slab<SLAB1, 256>(sB, W1, 1, KT1, tid);
    pref_slab<SLAB1, 256>(sB, W1, 2, KT1, tid);
    float2 ca0, ca2, cb0, cb2;
    loadA(0, ca0, ca2, cb0, cb2);

    for (int kt = 0; kt < KT1; kt++) {
        CPWAIT2();
        __syncthreads();
        float2 na0 = ca0, na2 = ca2, nb0 = cb0, nb2 = cb2;
        if (kt + 1 < KT1) loadA(kt + 1, na0, na2, nb0, nb2);
        uint32_t ah[4];
        ah[0] = pkh(ca0.x, ca0.y); ah[1] = pkh(cb0.x, cb0.y);
        ah[2] = pkh(ca2.x, ca2.y); ah[3] = pkh(cb2.x, cb2.y);
        const uint4* Bs = sB + (kt & 3) * SLAB1 + lane;
#pragma unroll
        for (int nt = 0; nt < NT1; nt++) {
            uint4 b = Bs[nt * 32];
            MMA4(acc[nt], ah, b.x, b.y);
            MMA4(acc[nt], ah, b.z, b.w);
        }
        pref_slab<SLAB1, 256>(sB, W1, kt + 3, KT1, tid);
        ca0 = na0; ca2 = na2; cb0 = nb0; cb2 = nb2;
    }

    // ---- LN1 stats ----
    float s0 = 0.f, q0s = 0.f, s1 = 0.f, q1s = 0.f;
#pragma unroll
    for (int nt = 0; nt < NT1; nt++) {
        int c = nt * 8 + tg * 2;
        float bx = b1v[c], by = b1v[c + 1];
        acc[nt].x += bx; acc[nt].y += by;
        acc[nt].z += bx; acc[nt].w += by;
        s0 += acc[nt].x + acc[nt].y;
        q0s += acc[nt].x * acc[nt].x + acc[nt].y * acc[nt].y;
        s1 += acc[nt].z + acc[nt].w;
        q1s += acc[nt].z * acc[nt].z + acc[nt].w * acc[nt].w;
    }
#pragma unroll
    for (int off = 1; off <= 2; off <<= 1) {
        s0 += __shfl_xor_sync(0xffffffffu, s0, off);
        q0s += __shfl_xor_sync(0xffffffffu, q0s, off);
        s1 += __shfl_xor_sync(0xffffffffu, s1, off);
        q1s += __shfl_xor_sync(0xffffffffu, q1s, off);
    }
    float m0 = s0 * (1.f / 256.f), v0 = q0s * (1.f / 256.f) - m0 * m0, rs0 = rsqrtf(v0 + 1e-5f);
    float m1 = s1 * (1.f / 256.f), v1 = q1s * (1.f / 256.f) - m1 * m1, rs1 = rsqrtf(v1 + 1e-5f);

    // ---- phase boundary: drain ring, start phase-2 prefetch, then GELU epilogue ----
    CPWAIT0();
    __syncthreads();
    pref_slab<SLAB2, 256>(sB, W2, 0, KT2, tid);
    pref_slab<SLAB2, 256>(sB, W2, 1, KT2, tid);
    pref_slab<SLAB2, 256>(sB, W2, 2, KT2, tid);

    uint4 hf[16];  // hidden rows as fp16 A-fragments for GEMM2
#pragma unroll
    for (int kt = 0; kt < 16; kt++) {
        int c = kt * 16 + tg * 2;
        float ga0 = g1v[c], ga1 = g1v[c + 1], be0 = bt1v[c], be1 = bt1v[c + 1];
        float ga2 = g1v[c + 8], ga3 = g1v[c + 9], be2 = bt1v[c + 8], be3 = bt1v[c + 9];
        float tv[8];
        tv[0] = (acc[2 * kt].x - m0) * rs0 * ga0 + be0;
        tv[1] = (acc[2 * kt].y - m0) * rs0 * ga1 + be1;
        tv[2] = (acc[2 * kt].z - m1) * rs1 * ga0 + be0;
        tv[3] = (acc[2 * kt].w - m1) * rs1 * ga1 + be1;
        tv[4] = (acc[2 * kt + 1].x - m0) * rs0 * ga2 + be2;
        tv[5] = (acc[2 * kt + 1].y - m0) * rs0 * ga3 + be3;
        tv[6] = (acc[2 * kt + 1].z - m1) * rs1 * ga2 + be2;
        tv[7] = (acc[2 * kt + 1].w - m1) * rs1 * ga3 + be3;
#pragma unroll
        for (int j = 0; j < 8; j++) tv[j] = gelu_f(tv[j]);
        hf[kt].x = pkh(tv[0], tv[1]); hf[kt].y = pkh(tv[2], tv[3]);
        hf[kt].z = pkh(tv[4], tv[5]); hf[kt].w = pkh(tv[6], tv[7]);
    }

    // ---- phase 2: GEMM2 (A from registers) ----
    float4 acc2[NT2];
#pragma unroll
    for (int i = 0; i < NT2; i++) acc2[i] = make_float4(0.f, 0.f, 0.f, 0.f);

    for (int kt = 0; kt < KT2; kt++) {
        CPWAIT2();
        __syncthreads();
        uint32_t ah[4] = {hf[kt].x, hf[kt].y, hf[kt].z, hf[kt].w};
        const uint4* Bs = sB + (kt & 3) * SLAB2 + lane;
#pragma unroll
        for (int nt = 0; nt < NT2; nt++) {
            uint4 b = Bs[nt * 32];
            MMA4(acc2[nt], ah, b.x, b.y);
            MMA4(acc2[nt], ah, b.z, b.w);
        }
        pref_slab<SLAB2, 256>(sB, W2, kt + 3, KT2, tid);
    }

    // ---- LN2 + residual(ea) + agg scatter ----
    s0 = 0.f; q0s = 0.f; s1 = 0.f; q1s = 0.f;
#pragma unroll
    for (int nt = 0; nt < NT2; nt++) {
        int c = nt * 8 + tg * 2;
        float bx = b2v[c], by = b2v[c + 1];
        acc2[nt].x += bx; acc2[nt].y += by;
        acc2[nt].z += bx; acc2[nt].w += by;
        s0 += acc2[nt].x + acc2[nt].y;
        q0s += acc2[nt].x * acc2[nt].x + acc2[nt].y * acc2[nt].y;
        s1 += acc2[nt].z + acc2[nt].w;
        q1s += acc2[nt].z * acc2[nt].z + acc2[nt].w * acc2[nt].w;
    }
#pragma unroll
    for (int off = 1; off <= 2; off <<= 1) {
        s0 += __shfl_xor_sync(0xffffffffu, s0, off);
        q0s += __shfl_xor_sync(0xffffffffu, q0s, off);
        s1 += __shfl_xor_sync(0xffffffffu, s1, off);
        q1s += __shfl_xor_sync(0xffffffffu, q1s, off);
    }
    m0 = s0 * (1.f / 128.f); v0 = q0s * (1.f / 128.f) - m0 * m0; rs0 = rsqrtf(v0 + 1e-5f);
    m1 = s1 * (1.f / 128.f); v1 = q1s * (1.f / 128.f) - m1 * m1; rs1 = rsqrtf(v1 + 1e-5f);

    int d0 = coli[r0c], d1 = coli[r1c];
#pragma unroll
    for (int nt = 0; nt < NT2; nt++) {
        int c = nt * 8 + tg * 2;
        float ga0 = g2v[c], ga1 = g2v[c + 1], be0 = bt2v[c], be1 = bt2v[c + 1];
        if (ok0) {
            float t0 = (acc2[nt].x - m0) * rs0 * ga0 + be0;
            float t1 = (acc2[nt].y - m0) * rs0 * ga1 + be1;
            float2 e = *(float2*)&eabuf[(size_t)r0 * DD + c];
            e.x += t0; e.y += t1;
            *(float2*)&eabuf[(size_t)r0 * DD + c] = e;
            atomicAdd(&g_agg[(size_t)d0 * DD + c], e.x);
            atomicAdd(&g_agg[(size_t)d0 * DD + c + 1], e.y);
        }
        if (ok1) {
            float t0 = (acc2[nt].z - m1) * rs1 * ga0 + be0;
            float t1 = (acc2[nt].w - m1) * rs1 * ga1 + be1;
            float2 e = *(float2*)&eabuf[(size_t)r1 * DD + c];
            e.x += t0; e.y += t1;
            *(float2*)&eabuf[(size_t)r1 * DD + c] = e;
            atomicAdd(&g_agg[(size_t)d1 * DD + c], e.x);
            atomicAdd(&g_agg[(size_t)d1 * DD + c + 1], e.y);
        }
    }
}

// ---------------- fused node MLP kernel ----------------
// A1=[x | agg*invcnt] K=256 N=256 (re-zeroes agg for next layer);
// GEMM2 K=256 N=128; out: x += LN2. 4 warps/CTA for full-chip coverage.
__global__ void __launch_bounds__(128)
node_fused(const uint4* __restrict__ W1, const uint4* __restrict__ W2,
           const float* __restrict__ b1v, const float* __restrict__ g1v, const float* __restrict__ bt1v,
           const float* __restrict__ b2v, const float* __restrict__ g2v, const float* __restrict__ bt2v,
           float* __restrict__ xbuf) {
    constexpr int KT1 = 16, NT1 = 32, SLAB1 = NT1 * 32;
    constexpr int KT2 = 16, NT2 = 16, SLAB2 = NT2 * 32;
    extern __shared__ uint4 sB[];

    const int tid = threadIdx.x, lane = tid & 31, warp = tid >> 5;
    const int g = lane >> 2, tg = lane & 3;
    const int rt = blockIdx.x * 4 + warp;
    const int r0 = rt * 16 + g, r1 = r0 + 8;
    const int r0c = min(r0, NN - 1), r1c = min(r1, NN - 1);
    const bool ok0 = r0 < NN, ok1 = r1 < NN;

    const float* p00 = xbuf + (size_t)r0c * DD;
    float* p01 = g_agg + (size_t)r0c * DD;
    const float* p10 = xbuf + (size_t)r1c * DD;
    float* p11 = g_agg + (size_t)r1c * DD;
    const float ic0 = g_cnt[r0c], ic1 = g_cnt[r1c];

    auto loadA = [&](int kt, float2& a0, float2& a2, float2& b0, float2& b2) {
        int seg = kt >> 3, ko = (kt & 7) * 16 + tg * 2;
        const float* q0 = seg == 0 ? p00 : p01;
        const float* q1 = seg == 0 ? p10 : p11;
        a0 = *(const float2*)(q0 + ko); a2 = *(const float2*)(q0 + ko + 8);
        b0 = *(const float2*)(q1 + ko); b2 = *(const float2*)(q1 + ko + 8);
        if (seg == 1) {
            // each agg element read exactly once per layer: zero it for the next
            // layer's scatter. Guarded so clamped (out-of-range) warps never write.
            float2 z = make_float2(0.f, 0.f);
            if (ok0) { *(float2*)(p01 + ko) = z; *(float2*)(p01 + ko + 8) = z; }
            if (ok1) { *(float2*)(p11 + ko) = z; *(float2*)(p11 + ko + 8) = z; }
        }
    };

    // ---- phase 1: GEMM1 ----
    float4 acc[NT1];
#pragma unroll
    for (int i = 0; i < NT1; i++) acc[i] = make_float4(0.f, 0.f, 0.f, 0.f);

    pref_slab<SLAB1, 128>(sB, W1, 0, KT1, tid);
    pref_slab<SLAB1, 128>(sB, W1, 1, KT1, tid);
    pref_slab<SLAB1, 128>(sB, W1, 2, KT1, tid);
    float2 ca0, ca2, cb0, cb2;
    loadA(0, ca0, ca2, cb0, cb2);

    for (int kt = 0; kt < KT1; kt++) {
        CPWAIT2();
        __syncthreads();
        float2 na0 = ca0, na2 = ca2, nb0 = cb0, nb2 = cb2;
        if (kt + 1 < KT1) loadA(kt + 1, na0, na2, nb0, nb2);
        float s0f = 1.f, s1f = 1.f;
        if ((kt >> 3) == 1) { s0f = ic0; s1f = ic1; }
        uint32_t ah[4];
        ah[0] = pkh(ca0.x * s0f, ca0.y * s0f);
        ah[1] = pkh(cb0.x * s1f, cb0.y * s1f);
        ah[2] = pkh(ca2.x * s0f, ca2.y * s0f);
        ah[3] = pkh(cb2.x * s1f, cb2.y * s1f);
        const uint4* Bs = sB + (kt & 3) * SLAB1 + lane;
#pragma unroll
        for (int nt = 0; nt < NT1; nt++) {
            uint4 b = Bs[nt * 32];
            MMA4(acc[nt], ah, b.x, b.y);
            MMA4(acc[nt], ah, b.z, b.w);
        }
        pref_slab<SLAB1, 128>(sB, W1, kt + 3, KT1, tid);
        ca0 = na0; ca2 = na2; cb0 = nb0; cb2 = nb2;
    }

    // ---- LN1 stats ----
    float s0 = 0.f, q0s = 0.f, s1 = 0.f, q1s = 0.f;
#pragma unroll
    for (int nt = 0; nt < NT1; nt++) {
        int c = nt * 8 + tg * 2;
        float bx = b1v[c], by = b1v[c + 1];
        acc[nt].x += bx; acc[nt].y += by;
        acc[nt].z += bx; acc[nt].w += by;
        s0 += acc[nt].x + acc[nt].y;
        q0s += acc[nt].x * acc[nt].x + acc[nt].y * acc[nt].y;
        s1 += acc[nt].z + acc[nt].w;
        q1s += acc[nt].z * acc[nt].z + acc[nt].w * acc[nt].w;
    }
#pragma unroll
    for (int off = 1; off <= 2; off <<= 1) {
        s0 += __shfl_xor_sync(0xffffffffu, s0, off);
        q0s += __shfl_xor_sync(0xffffffffu, q0s, off);
        s1 += __shfl_xor_sync(0xffffffffu, s1, off);
        q1s += __shfl_xor_sync(0xffffffffu, q1s, off);
    }
    float m0 = s0 * (1.f / 256.f), v0 = q0s * (1.f / 256.f) - m0 * m0, rs0 = rsqrtf(v0 + 1e-5f);
    float m1 = s1 * (1.f / 256.f), v1 = q1s * (1.f / 256.f) - m1 * m1, rs1 = rsqrtf(v1 + 1e-5f);

    // ---- phase boundary ----
    CPWAIT0();
    __syncthreads();
    pref_slab<SLAB2, 128>(sB, W2, 0, KT2, tid);
    pref_slab<SLAB2, 128>(sB, W2, 1, KT2, tid);
    pref_slab<SLAB2, 128>(sB, W2, 2, KT2, tid);

    uint4 hf[16];
#pragma unroll
    for (int kt = 0; kt < 16; kt++) {
        int c = kt * 16 + tg * 2;
        float ga0 = g1v[c], ga1 = g1v[c + 1], be0 = bt1v[c], be1 = bt1v[c + 1];
        float ga2 = g1v[c + 8], ga3 = g1v[c + 9], be2 = bt1v[c + 8], be3 = bt1v[c + 9];
        float tv[8];
        tv[0] = (acc[2 * kt].x - m0) * rs0 * ga0 + be0;
        tv[1] = (acc[2 * kt].y - m0) * rs0 * ga1 + be1;
        tv[2] = (acc[2 * kt].z - m1) * rs1 * ga0 + be0;
        tv[3] = (acc[2 * kt].w - m1) * rs1 * ga1 + be1;
        tv[4] = (acc[2 * kt + 1].x - m0) * rs0 * ga2 + be2;
        tv[5] = (acc[2 * kt + 1].y - m0) * rs0 * ga3 + be3;
        tv[6] = (acc[2 * kt + 1].z - m1) * rs1 * ga2 + be2;
        tv[7] = (acc[2 * kt + 1].w - m1) * rs1 * ga3 + be3;
#pragma unroll
        for (int j = 0; j < 8; j++) tv[j] = gelu_f(tv[j]);
        hf[kt].x = pkh(tv[0], tv[1]); hf[kt].y = pkh(tv[2], tv[3]);
        hf[kt].z = pkh(tv[4], tv[5]); hf[kt].w = pkh(tv[6], tv[7]);
    }

    // ---- phase 2: GEMM2 ----
    float4 acc2[NT2];
#pragma unroll
    for (int i = 0; i < NT2; i++) acc2[i] = make_float4(0.f, 0.f, 0.f, 0.f);

    for (int kt = 0; kt < KT2; kt++) {
        CPWAIT2();
        __syncthreads();
        uint32_t ah[4] = {hf[kt].x, hf[kt].y, hf[kt].z, hf[kt].w};
        const uint4* Bs = sB + (kt & 3) * SLAB2 + lane;
#pragma unroll
        for (int nt = 0; nt < NT2; nt++) {
            uint4 b = Bs[nt * 32];
            MMA4(acc2[nt], ah, b.x, b.y);
            MMA4(acc2[nt], ah, b.z, b.w);
        }
        pref_slab<SLAB2, 128>(sB, W2, kt + 3, KT2, tid);
    }

    // ---- LN2 + residual(x) ----
    s0 = 0.f; q0s = 0.f; s1 = 0.f; q1s = 0.f;
#pragma unroll
    for (int nt = 0; nt < NT2; nt++) {
        int c = nt * 8 + tg * 2;
        float bx = b2v[c], by = b2v[c + 1];
        acc2[nt].x += bx; acc2[nt].y += by;
        acc2[nt].z += bx; acc2[nt].w += by;
        s0 += acc2[nt].x + acc2[nt].y;
        q0s += acc2[nt].x * acc2[nt].x + acc2[nt].y * acc2[nt].y;
        s1 += acc2[nt].z + acc2[nt].w;
        q1s += acc2[nt].z * acc2[nt].z + acc2[nt].w * acc2[nt].w;
    }
#pragma unroll
    for (int off = 1; off <= 2; off <<= 1) {
        s0 += __shfl_xor_sync(0xffffffffu, s0, off);
        q0s += __shfl_xor_sync(0xffffffffu, q0s, off);
        s1 += __shfl_xor_sync(0xffffffffu, s1, off);
        q1s += __shfl_xor_sync(0xffffffffu, q1s, off);
    }
    m0 = s0 * (1.f / 128.f); v0 = q0s * (1.f / 128.f) - m0 * m0; rs0 = rsqrtf(v0 + 1e-5f);
    m1 = s1 * (1.f / 128.f); v1 = q1s * (1.f / 128.f) - m1 * m1; rs1 = rsqrtf(v1 + 1e-5f);

#pragma unroll
    for (int nt = 0; nt < NT2; nt++) {
        int c = nt * 8 + tg * 2;
        float ga0 = g2v[c], ga1 = g2v[c + 1], be0 = bt2v[c], be1 = bt2v[c + 1];
        if (ok0) {
            float t0 = (acc2[nt].x - m0) * rs0 * ga0 + be0;
            float t1 = (acc2[nt].y - m0) * rs0 * ga1 + be1;
            float2 e = *(float2*)&xbuf[(size_t)r0 * DD + c];
            e.x += t0; e.y += t1;
            *(float2*)&xbuf[(size_t)r0 * DD + c] = e;
        }
        if (ok1) {
            float t0 = (acc2[nt].z - m1) * rs1 * ga0 + be0;
            float t1 = (acc2[nt].w - m1) * rs1 * ga1 + be1;
            float2 e = *(float2*)&xbuf[(size_t)r1 * DD + c];
            e.x += t0; e.y += t1;
            *(float2*)&xbuf[(size_t)r1 * DD + c] = e;
        }
    }
}

// ---------------- host launcher ----------------
extern "C" void kernel_launch(void* const* d_in, const int* in_sizes, int n_in,
                              void* d_out, int out_size) {
    const float* x    = (const float*)d_in[0];
    const int*   ei   = (const int*)d_in[1];
    const float* ea   = (const float*)d_in[2];
    const float* ew1  = (const float*)d_in[3];
    const float* eb1  = (const float*)d_in[4];
    const float* eg1  = (const float*)d_in[5];
    const float* ebt1 = (const float*)d_in[6];
    const float* ew2  = (const float*)d_in[7];
    const float* eb2  = (const float*)d_in[8];
    const float* eg2  = (const float*)d_in[9];
    const float* ebt2 = (const float*)d_in[10];
    const float* nw1  = (const float*)d_in[11];
    const float* nb1  = (const float*)d_in[12];
    const float* ng1  = (const float*)d_in[13];
    const float* nbt1 = (const float*)d_in[14];
    const float* nw2  = (const float*)d_in[15];
    const float* nb2  = (const float*)d_in[16];
    const float* ng2  = (const float*)d_in[17];
    const float* nbt2 = (const float*)d_in[18];

    float* xo = (float*)d_out;
    float* eo = xo + (size_t)NN * DD;
    const int* rowi = ei;
    const int* coli = ei + NE;

    uint4 *ew1p, *ew2p, *nw1p, *nw2p;
    cudaGetSymbolAddress((void**)&ew1p, g_ew1p);
    cudaGetSymbolAddress((void**)&ew2p, g_ew2p);
    cudaGetSymbolAddress((void**)&nw1p, g_nw1p);
    cudaGetSymbolAddress((void**)&nw2p, g_nw2p);

    const int SMEM = 4 * 32 * 32 * 16;  // 65536 (max slab ring)
    cudaFuncSetAttribute(edge_fused, cudaFuncAttributeMaxDynamicSharedMemorySize, SMEM);
    cudaFuncSetAttribute(node_fused, cudaFuncAttributeMaxDynamicSharedMemorySize, SMEM);

    // pack weights into B-fragment layout
    {
        int t1 = NLAYERS * 24 * 32 * 32;
        int t2 = NLAYERS * 16 * 16 * 32;
        int t3 = NLAYERS * 16 * 32 * 32;
        pack_w<<<(t1 + 255) / 256, 256>>>(ew1, ew1p, 24, 32, 384, 256, t1);
        pack_w<<<(t2 + 255) / 256, 256>>>(ew2, ew2p, 16, 16, 256, 128, t2);
        pack_w<<<(t3 + 255) / 256, 256>>>(nw1, nw1p, 16, 32, 256, 256, t3);
        pack_w<<<(t2 + 255) / 256, 256>>>(nw2, nw2p, 16, 16, 256, 128, t2);
    }

    copy_kernel<<<(NN * DD + 255) / 256, 256>>>(x, xo, NN * DD);
    copy_kernel<<<(NE * DD + 255) / 256, 256>>>(ea, eo, NE * DD);
    zero_cnt_kernel<<<(NN + 255) / 256, 256>>>();
    count_kernel<<<(NE + 255) / 256, 256>>>(coli);
    invcnt_kernel<<<(NN + 255) / 256, 256>>>();
    zero_agg_kernel<<<(NN * DD + 255) / 256, 256>>>();  // once; node phase-1 re-zeroes per layer

    const int EG = (ERT + 7) / 8;  // 469
    const int NG = (NRT + 3) / 4;  // 157

    for (int l = 0; l < NLAYERS; l++) {
        edge_fused<<<EG, 256, SMEM>>>(
            ew1p + (size_t)l * 24 * 32 * 32, ew2p + (size_t)l * 16 * 16 * 32,
            eb1 + l * 256, eg1 + l * 256, ebt1 + l * 256,
            eb2 + l * 128, eg2 + l * 128, ebt2 + l * 128,
            xo, eo, rowi, coli);
        node_fused<<<NG, 128, SMEM>>>(
            nw1p + (size_t)l * 16 * 32 * 32, nw2p + (size_t)l * 16 * 16 * 32,
            nb1 + l * 256, ng1 + l * 256, nbt1 + l * 256,
            nb2 + l * 128, ng2 + l * 128, nbt2 + l * 128,
            xo);
    }
}

// round 12
// speedup vs baseline: 3.3737x; 1.0847x over previous
#include <cuda_runtime.h>
#include <cuda_fp16.h>
#include <math.h>
#include <stdint.h>

#define NN 10000
#define NE 60000
#define DD 128
#define NLAYERS 15

#define ERT 3750   // edge row tiles (60000/16)
#define NRT 625    // node row tiles (10000/16)

// ---------------- device scratch (allocation-free) ----------------
__device__ float g_agg[NN * DD];    // per-node aggregated edge features
__device__ float g_cnt[NN];         // 1/max(count,1)

// weights pre-packed as B-fragments {bh0,bh1,bl0,bl1} (fp16 hi/lo):
// layout [layer][ktile][ntile][lane]
__device__ uint4 g_ew1p[NLAYERS * 24 * 32 * 32];
__device__ uint4 g_ew2p[NLAYERS * 16 * 16 * 32];
__device__ uint4 g_nw1p[NLAYERS * 16 * 32 * 32];
__device__ uint4 g_nw2p[NLAYERS * 16 * 16 * 32];

// ---------------- helpers ----------------
__device__ __forceinline__ uint32_t pkh(float a, float b) {
    __half2 t = __floats2half2_rn(a, b);
    return *(uint32_t*)&t;
}
__device__ __forceinline__ uint32_t pkl(float a, float b) {
    __half ha = __float2half_rn(a), hb = __float2half_rn(b);
    return pkh(a - __half2float(ha), b - __half2float(hb));
}

// exact-GELU via Abramowitz-Stegun 7.1.26 erf (abs err <= 1.5e-7)
__device__ __forceinline__ float gelu_f(float t) {
    float x = fabsf(t) * 0.70710678118654752f;
    float k = __fdividef(1.f, fmaf(0.3275911f, x, 1.f));
    float p = fmaf(1.061405429f, k, -1.453152027f);
    p = fmaf(p, k, 1.421413741f);
    p = fmaf(p, k, -0.284496736f);
    p = fmaf(p, k, 0.254829592f);
    p = p * k;
    float e = __expf(-x * x);
    float er = copysignf(fmaf(-p, e, 1.f), t);
    return 0.5f * t * (1.f + er);
}

#define MMA4(d, a, b0, b1) \
    asm volatile("mma.sync.aligned.m16n8k16.row.col.f32.f16.f16.f32 " \
                 "{%0,%1,%2,%3},{%4,%5,%6,%7},{%8,%9},{%0,%1,%2,%3};" \
                 : "+f"((d).x), "+f"((d).y), "+f"((d).z), "+f"((d).w) \
                 : "r"((a)[0]), "r"((a)[1]), "r"((a)[2]), "r"((a)[3]), \
                   "r"(b0), "r"(b1))

// async B slab prefetch into 4-deep ring slot (kt & 3); always commits a group
template <int SLAB, int NTH>
__device__ __forceinline__ void pref_slab(uint4* sB, const uint4* Wp, int kt, int KT, int tid) {
    if (kt < KT) {
        const uint4* src = Wp + (size_t)kt * SLAB + tid;
        uint32_t dst = (uint32_t)__cvta_generic_to_shared(sB + (kt & 3) * SLAB + tid);
#pragma unroll
        for (int i = 0; i < SLAB / NTH; i++)
            asm volatile("cp.async.cg.shared.global [%0], [%1], 16;"
                         :: "r"(dst + i * NTH * 16), "l"(src + i * NTH));
    }
    asm volatile("cp.async.commit_group;" ::: "memory");
}
#define CPWAIT2() asm volatile("cp.async.wait_group 2;" ::: "memory")
#define CPWAIT0() asm volatile("cp.async.wait_group 0;" ::: "memory")

// ---------------- aux kernels ----------------
__global__ void copy_kernel(const float* __restrict__ src, float* __restrict__ dst, int n) {
    int i = blockIdx.x * blockDim.x + threadIdx.x;
    if (i < n) dst[i] = src[i];
}
__global__ void zero_cnt_kernel() {
    int i = blockIdx.x * blockDim.x + threadIdx.x;
    if (i < NN) g_cnt[i] = 0.f;
}
__global__ void count_kernel(const int* __restrict__ col) {
    int e = blockIdx.x * blockDim.x + threadIdx.x;
    if (e < NE) atomicAdd(&g_cnt[col[e]], 1.f);
}
__global__ void invcnt_kernel() {
    int i = blockIdx.x * blockDim.x + threadIdx.x;
    if (i < NN) g_cnt[i] = 1.f / fmaxf(g_cnt[i], 1.f);
}
__global__ void zero_agg_kernel() {
    int i = blockIdx.x * blockDim.x + threadIdx.x;
    if (i < NN * DD) g_agg[i] = 0.f;
}

// Pre-pack fp32 W[L][K][N] into per-lane B fragments {bh0,bh1,bl0,bl1} (fp16).
__global__ void pack_w(const float* __restrict__ W, uint4* __restrict__ out,
                       int KT, int NT, int K, int N, int total) {
    int idx = blockIdx.x * blockDim.x + threadIdx.x;
    if (idx >= total) return;
    int lane = idx & 31;
    int t = idx >> 5;
    int nt = t % NT; t /= NT;
    int kt = t % KT;
    int l = t / KT;
    int g = lane >> 2, tg = lane & 3;
    const float* Wl = W + (size_t)l * K * N;
    int n = nt * 8 + g;
    int ka = kt * 16 + tg * 2;
    float v00 = Wl[(size_t)ka * N + n];
    float v01 = Wl[(size_t)(ka + 1) * N + n];
    float v10 = Wl[(size_t)(ka + 8) * N + n];
    float v11 = Wl[(size_t)(ka + 9) * N + n];
    uint4 o;
    o.x = pkh(v00, v01);
    o.y = pkh(v10, v11);
    o.z = pkl(v00, v01);
    o.w = pkl(v10, v11);
    out[idx] = o;
}

// ---------------- fused edge MLP kernel (GEMM1 + LN + GELU + GEMM2 + LN + scatter) ----------------
// A1=[x[row]|x[col]|ea] K=384 N=256; hidden kept in registers as fp16 A-fragments;
// GEMM2 K=256 N=128; out: ea += LN2, atomicAdd into g_agg[col].
// 4 warps/CTA + min 2 CTAs/SM: co-resident CTA's mainloop fills this CTA's
// epilogue/phase-boundary bubbles.
__global__ void __launch_bounds__(128, 2)
edge_fused(const uint4* __restrict__ W1, const uint4* __restrict__ W2,
           const float* __restrict__ b1v, const float* __restrict__ g1v, const float* __restrict__ bt1v,
           const float* __restrict__ b2v, const float* __restrict__ g2v, const float* __restrict__ bt2v,
           float* __restrict__ xbuf, float* __restrict__ eabuf,
           const int* __restrict__ rowi, const int* __restrict__ coli) {
    constexpr int KT1 = 24, NT1 = 32, SLAB1 = NT1 * 32;
    constexpr int KT2 = 16, NT2 = 16, SLAB2 = NT2 * 32;
    extern __shared__ uint4 sB[];

    const int tid = threadIdx.x, lane = tid & 31, warp = tid >> 5;
    const int g = lane >> 2, tg = lane & 3;
    const int rt = blockIdx.x * 4 + warp;
    const int r0 = rt * 16 + g, r1 = r0 + 8;
    const int r0c = min(r0, NE - 1), r1c = min(r1, NE - 1);
    const bool ok0 = r0 < NE, ok1 = r1 < NE;

    const float* p00 = xbuf + (size_t)rowi[r0c] * DD;
    const float* p01 = xbuf + (size_t)coli[r0c] * DD;
    const float* p02 = eabuf + (size_t)r0c * DD;
    const float* p10 = xbuf + (size_t)rowi[r1c] * DD;
    const float* p11 = xbuf + (size_t)coli[r1c] * DD;
    const float* p12 = eabuf + (size_t)r1c * DD;

    auto loadA = [&](int kt, float2& a0, float2& a2, float2& b0, float2& b2) {
        int seg = kt >> 3, ko = (kt & 7) * 16 + tg * 2;
        const float* q0 = seg == 0 ? p00 : seg == 1 ? p01 : p02;
        const float* q1 = seg == 0 ? p10 : seg == 1 ? p11 : p12;
        a0 = *(const float2*)(q0 + ko); a2 = *(const float2*)(q0 + ko + 8);
        b0 = *(const float2*)(q1 + ko); b2 = *(const float2*)(q1 + ko + 8);
    };

    // ---- phase 1: GEMM1 ----
    float4 acc[NT1];
#pragma unroll
    for (int i = 0; i < NT1; i++) acc[i] = make_float4(0.f, 0.f, 0.f, 0.f);

    pref_slab<SLAB1, 128>(sB, W1, 0, KT1, tid);
    pref_slab<SLAB1, 128>(sB, W1, 1, KT1, tid);
    pref_slab<SLAB1, 128>(sB, W1, 2, KT1, tid);
    float2 ca0, ca2, cb0, cb2;
    loadA(0, ca0, ca2, cb0, cb2);

    for (int kt = 0; kt < KT1; kt++) {
        CPWAIT2();
        __syncthreads();
        float2 na0 = ca0, na2 = ca2, nb0 = cb0, nb2 = cb2;
        if (kt + 1 < KT1) loadA(kt + 1, na0, na2, nb0, nb2);
        uint32_t ah[4];
        ah[0] = pkh(ca0.x, ca0.y); ah[1] = pkh(cb0.x, cb0.y);
        ah[2] = pkh(ca2.x, ca2.y); ah[3] = pkh(cb2.x, cb2.y);
        const uint4* Bs = sB + (kt & 3) * SLAB1 + lane;
#pragma unroll
        for (int nt = 0; nt < NT1; nt++) {
            uint4 b = Bs[nt * 32];
            MMA4(acc[nt], ah, b.x, b.y);
            MMA4(acc[nt], ah, b.z, b.w);
        }
        pref_slab<SLAB1, 128>(sB, W1, kt + 3, KT1, tid);
        ca0 = na0; ca2 = na2; cb0 = nb0; cb2 = nb2;
    }

    // ---- LN1 stats ----
    float s0 = 0.f, q0s = 0.f, s1 = 0.f, q1s = 0.f;
#pragma unroll
    for (int nt = 0; nt < NT1; nt++) {
        int c = nt * 8 + tg * 2;
        float bx = b1v[c], by = b1v[c + 1];
        acc[nt].x += bx; acc[nt].y += by;
        acc[nt].z += bx; acc[nt].w += by;
        s0 += acc[nt].x + acc[nt].y;
        q0s += acc[nt].x * acc[nt].x + acc[nt].y * acc[nt].y;
        s1 += acc[nt].z + acc[nt].w;
        q1s += acc[nt].z * acc[nt].z + acc[nt].w * acc[nt].w;
    }
#pragma unroll
    for (int off = 1; off <= 2; off <<= 1) {
        s0 += __shfl_xor_sync(0xffffffffu, s0, off);
        q0s += __shfl_xor_sync(0xffffffffu, q0s, off);
        s1 += __shfl_xor_sync(0xffffffffu, s1, off);
        q1s += __shfl_xor_sync(0xffffffffu, q1s, off);
    }
    float m0 = s0 * (1.f / 256.f), v0 = q0s * (1.f / 256.f) - m0 * m0, rs0 = rsqrtf(v0 + 1e-5f);
    float m1 = s1 * (1.f / 256.f), v1 = q1s * (1.f / 256.f) - m1 * m1, rs1 = rsqrtf(v1 + 1e-5f);

    // ---- phase boundary: drain ring, start phase-2 prefetch, then GELU epilogue ----
    CPWAIT0();
    __syncthreads();
    pref_slab<SLAB2, 128>(sB, W2, 0, KT2, tid);
    pref_slab<SLAB2, 128>(sB, W2, 1, KT2, tid);
    pref_slab<SLAB2, 128>(sB, W2, 2, KT2, tid);

    uint4 hf[16];  // hidden rows as fp16 A-fragments for GEMM2
#pragma unroll
    for (int kt = 0; kt < 16; kt++) {
        int c = kt * 16 + tg * 2;
        float ga0 = g1v[c], ga1 = g1v[c + 1], be0 = bt1v[c], be1 = bt1v[c + 1];
        float ga2 = g1v[c + 8], ga3 = g1v[c + 9], be2 = bt1v[c + 8], be3 = bt1v[c + 9];
        float tv[8];
        tv[0] = (acc[2 * kt].x - m0) * rs0 * ga0 + be0;
        tv[1] = (acc[2 * kt].y - m0) * rs0 * ga1 + be1;
        tv[2] = (acc[2 * kt].z - m1) * rs1 * ga0 + be0;
        tv[3] = (acc[2 * kt].w - m1) * rs1 * ga1 + be1;
        tv[4] = (acc[2 * kt + 1].x - m0) * rs0 * ga2 + be2;
        tv[5] = (acc[2 * kt + 1].y - m0) * rs0 * ga3 + be3;
        tv[6] = (acc[2 * kt + 1].z - m1) * rs1 * ga2 + be2;
        tv[7] = (acc[2 * kt + 1].w - m1) * rs1 * ga3 + be3;
#pragma unroll
        for (int j = 0; j < 8; j++) tv[j] = gelu_f(tv[j]);
        hf[kt].x = pkh(tv[0], tv[1]); hf[kt].y = pkh(tv[2], tv[3]);
        hf[kt].z = pkh(tv[4], tv[5]); hf[kt].w = pkh(tv[6], tv[7]);
    }

    // ---- phase 2: GEMM2 (A from registers) ----
    float4 acc2[NT2];
#pragma unroll
    for (int i = 0; i < NT2; i++) acc2[i] = make_float4(0.f, 0.f, 0.f, 0.f);

    for (int kt = 0; kt < KT2; kt++) {
        CPWAIT2();
        __syncthreads();
        uint32_t ah[4] = {hf[kt].x, hf[kt].y, hf[kt].z, hf[kt].w};
        const uint4* Bs = sB + (kt & 3) * SLAB2 + lane;
#pragma unroll
        for (int nt = 0; nt < NT2; nt++) {
            uint4 b = Bs[nt * 32];
            MMA4(acc2[nt], ah, b.x, b.y);
            MMA4(acc2[nt], ah, b.z, b.w);
        }
        pref_slab<SLAB2, 128>(sB, W2, kt + 3, KT2, tid);
    }

    // ---- LN2 + residual(ea) + agg scatter ----
    s0 = 0.f; q0s = 0.f; s1 = 0.f; q1s = 0.f;
#pragma unroll
    for (int nt = 0; nt < NT2; nt++) {
        int c = nt * 8 + tg * 2;
        float bx = b2v[c], by = b2v[c + 1];
        acc2[nt].x += bx; acc2[nt].y += by;
        acc2[nt].z += bx; acc2[nt].w += by;
        s0 += acc2[nt].x + acc2[nt].y;
        q0s += acc2[nt].x * acc2[nt].x + acc2[nt].y * acc2[nt].y;
        s1 += acc2[nt].z + acc2[nt].w;
        q1s += acc2[nt].z * acc2[nt].z + acc2[nt].w * acc2[nt].w;
    }
#pragma unroll
    for (int off = 1; off <= 2; off <<= 1) {
        s0 += __shfl_xor_sync(0xffffffffu, s0, off);
        q0s += __shfl_xor_sync(0xffffffffu, q0s, off);
        s1 += __shfl_xor_sync(0xffffffffu, s1, off);
        q1s += __shfl_xor_sync(0xffffffffu, q1s, off);
    }
    m0 = s0 * (1.f / 128.f); v0 = q0s * (1.f / 128.f) - m0 * m0; rs0 = rsqrtf(v0 + 1e-5f);
    m1 = s1 * (1.f / 128.f); v1 = q1s * (1.f / 128.f) - m1 * m1; rs1 = rsqrtf(v1 + 1e-5f);

    int d0 = coli[r0c], d1 = coli[r1c];
#pragma unroll
    for (int nt = 0; nt < NT2; nt++) {
        int c = nt * 8 + tg * 2;
        float ga0 = g2v[c], ga1 = g2v[c + 1], be0 = bt2v[c], be1 = bt2v[c + 1];
        if (ok0) {
            float t0 = (acc2[nt].x - m0) * rs0 * ga0 + be0;
            float t1 = (acc2[nt].y - m0) * rs0 * ga1 + be1;
            float2 e = *(float2*)&eabuf[(size_t)r0 * DD + c];
            e.x += t0; e.y += t1;
            *(float2*)&eabuf[(size_t)r0 * DD + c] = e;
            atomicAdd(&g_agg[(size_t)d0 * DD + c], e.x);
            atomicAdd(&g_agg[(size_t)d0 * DD + c + 1], e.y);
        }
        if (ok1) {
            float t0 = (acc2[nt].z - m1) * rs1 * ga0 + be0;
            float t1 = (acc2[nt].w - m1) * rs1 * ga1 + be1;
            float2 e = *(float2*)&eabuf[(size_t)r1 * DD + c];
            e.x += t0; e.y += t1;
            *(float2*)&eabuf[(size_t)r1 * DD + c] = e;
            atomicAdd(&g_agg[(size_t)d1 * DD + c], e.x);
            atomicAdd(&g_agg[(size_t)d1 * DD + c + 1], e.y);
        }
    }
}

// ---------------- fused node MLP kernel ----------------
// A1=[x | agg*invcnt] K=256 N=256 (re-zeroes agg for next layer);
// GEMM2 K=256 N=128; out: x += LN2. 4 warps/CTA, min 2 CTAs/SM.
__global__ void __launch_bounds__(128, 2)
node_fused(const uint4* __restrict__ W1, const uint4* __restrict__ W2,
           const float* __restrict__ b1v, const float* __restrict__ g1v, const float* __restrict__ bt1v,
           const float* __restrict__ b2v, const float* __restrict__ g2v, const float* __restrict__ bt2v,
           float* __restrict__ xbuf) {
    constexpr int KT1 = 16, NT1 = 32, SLAB1 = NT1 * 32;
    constexpr int KT2 = 16, NT2 = 16, SLAB2 = NT2 * 32;
    extern __shared__ uint4 sB[];

    const int tid = threadIdx.x, lane = tid & 31, warp = tid >> 5;
    const int g = lane >> 2, tg = lane & 3;
    const int rt = blockIdx.x * 4 + warp;
    const int r0 = rt * 16 + g, r1 = r0 + 8;
    const int r0c = min(r0, NN - 1), r1c = min(r1, NN - 1);
    const bool ok0 = r0 < NN, ok1 = r1 < NN;

    const float* p00 = xbuf + (size_t)r0c * DD;
    float* p01 = g_agg + (size_t)r0c * DD;
    const float* p10 = xbuf + (size_t)r1c * DD;
    float* p11 = g_agg + (size_t)r1c * DD;
    const float ic0 = g_cnt[r0c], ic1 = g_cnt[r1c];

    auto loadA = [&](int kt, float2& a0, float2& a2, float2& b0, float2& b2) {
        int seg = kt >> 3, ko = (kt & 7) * 16 + tg * 2;
        const float* q0 = seg == 0 ? p00 : p01;
        const float* q1 = seg == 0 ? p10 : p11;
        a0 = *(const float2*)(q0 + ko); a2 = *(const float2*)(q0 + ko + 8);
        b0 = *(const float2*)(q1 + ko); b2 = *(const float2*)(q1 + ko + 8);
        if (seg == 1) {
            // each agg element read exactly once per layer: zero it for the next
            // layer's scatter. Guarded so clamped (out-of-range) warps never write.
            float2 z = make_float2(0.f, 0.f);
            if (ok0) { *(float2*)(p01 + ko) = z; *(float2*)(p01 + ko + 8) = z; }
            if (ok1) { *(float2*)(p11 + ko) = z; *(float2*)(p11 + ko + 8) = z; }
        }
    };

    // ---- phase 1: GEMM1 ----
    float4 acc[NT1];
#pragma unroll
    for (int i = 0; i < NT1; i++) acc[i] = make_float4(0.f, 0.f, 0.f, 0.f);

    pref_slab<SLAB1, 128>(sB, W1, 0, KT1, tid);
    pref_slab<SLAB1, 128>(sB, W1, 1, KT1, tid);
    pref_slab<SLAB1, 128>(sB, W1, 2, KT1, tid);
    float2 ca0, ca2, cb0, cb2;
    loadA(0, ca0, ca2, cb0, cb2);

    for (int kt = 0; kt < KT1; kt++) {
        CPWAIT2();
        __syncthreads();
        float2 na0 = ca0, na2 = ca2, nb0 = cb0, nb2 = cb2;
        if (kt + 1 < KT1) loadA(kt + 1, na0, na2, nb0, nb2);
        float s0f = 1.f, s1f = 1.f;
        if ((kt >> 3) == 1) { s0f = ic0; s1f = ic1; }
        uint32_t ah[4];
        ah[0] = pkh(ca0.x * s0f, ca0.y * s0f);
        ah[1] = pkh(cb0.x * s1f, cb0.y * s1f);
        ah[2] = pkh(ca2.x * s0f, ca2.y * s0f);
        ah[3] = pkh(cb2.x * s1f, cb2.y * s1f);
        const uint4* Bs = sB + (kt & 3) * SLAB1 + lane;
#pragma unroll
        for (int nt = 0; nt < NT1; nt++) {
            uint4 b = Bs[nt * 32];
            MMA4(acc[nt], ah, b.x, b.y);
            MMA4(acc[nt], ah, b.z, b.w);
        }
        pref_slab<SLAB1, 128>(sB, W1, kt + 3, KT1, tid);
        ca0 = na0; ca2 = na2; cb0 = nb0; cb2 = nb2;
    }

    // ---- LN1 stats ----
    float s0 = 0.f, q0s = 0.f, s1 = 0.f, q1s = 0.f;
#pragma unroll
    for (int nt = 0; nt < NT1; nt++) {
        int c = nt * 8 + tg * 2;
        float bx = b1v[c], by = b1v[c + 1];
        acc[nt].x += bx; acc[nt].y += by;
        acc[nt].z += bx; acc[nt].w += by;
        s0 += acc[nt].x + acc[nt].y;
        q0s += acc[nt].x * acc[nt].x + acc[nt].y * acc[nt].y;
        s1 += acc[nt].z + acc[nt].w;
        q1s += acc[nt].z * acc[nt].z + acc[nt].w * acc[nt].w;
    }
#pragma unroll
    for (int off = 1; off <= 2; off <<= 1) {
        s0 += __shfl_xor_sync(0xffffffffu, s0, off);
        q0s += __shfl_xor_sync(0xffffffffu, q0s, off);
        s1 += __shfl_xor_sync(0xffffffffu, s1, off);
        q1s += __shfl_xor_sync(0xffffffffu, q1s, off);
    }
    float m0 = s0 * (1.f / 256.f), v0 = q0s * (1.f / 256.f) - m0 * m0, rs0 = rsqrtf(v0 + 1e-5f);
    float m1 = s1 * (1.f / 256.f), v1 = q1s * (1.f / 256.f) - m1 * m1, rs1 = rsqrtf(v1 + 1e-5f);

    // ---- phase boundary ----
    CPWAIT0();
    __syncthreads();
    pref_slab<SLAB2, 128>(sB, W2, 0, KT2, tid);
    pref_slab<SLAB2, 128>(sB, W2, 1, KT2, tid);
    pref_slab<SLAB2, 128>(sB, W2, 2, KT2, tid);

    uint4 hf[16];
#pragma unroll
    for (int kt = 0; kt < 16; kt++) {
        int c = kt * 16 + tg * 2;
        float ga0 = g1v[c], ga1 = g1v[c + 1], be0 = bt1v[c], be1 = bt1v[c + 1];
        float ga2 = g1v[c + 8], ga3 = g1v[c + 9], be2 = bt1v[c + 8], be3 = bt1v[c + 9];
        float tv[8];
        tv[0] = (acc[2 * kt].x - m0) * rs0 * ga0 + be0;
        tv[1] = (acc[2 * kt].y - m0) * rs0 * ga1 + be1;
        tv[2] = (acc[2 * kt].z - m1) * rs1 * ga0 + be0;
        tv[3] = (acc[2 * kt].w - m1) * rs1 * ga1 + be1;
        tv[4] = (acc[2 * kt + 1].x - m0) * rs0 * ga2 + be2;
        tv[5] = (acc[2 * kt + 1].y - m0) * rs0 * ga3 + be3;
        tv[6] = (acc[2 * kt + 1].z - m1) * rs1 * ga2 + be2;
        tv[7] = (acc[2 * kt + 1].w - m1) * rs1 * ga3 + be3;
#pragma unroll
        for (int j = 0; j < 8; j++) tv[j] = gelu_f(tv[j]);
        hf[kt].x = pkh(tv[0], tv[1]); hf[kt].y = pkh(tv[2], tv[3]);
        hf[kt].z = pkh(tv[4], tv[5]); hf[kt].w = pkh(tv[6], tv[7]);
    }

    // ---- phase 2: GEMM2 ----
    float4 acc2[NT2];
#pragma unroll
    for (int i = 0; i < NT2; i++) acc2[i] = make_float4(0.f, 0.f, 0.f, 0.f);

    for (int kt = 0; kt < KT2; kt++) {
        CPWAIT2();
        __syncthreads();
        uint32_t ah[4] = {hf[kt].x, hf[kt].y, hf[kt].z, hf[kt].w};
        const uint4* Bs = sB + (kt & 3) * SLAB2 + lane;
#pragma unroll
        for (int nt = 0; nt < NT2; nt++) {
            uint4 b = Bs[nt * 32];
            MMA4(acc2[nt], ah, b.x, b.y);
            MMA4(acc2[nt], ah, b.z, b.w);
        }
        pref_slab<SLAB2, 128>(sB, W2, kt + 3, KT2, tid);
    }

    // ---- LN2 + residual(x) ----
    s0 = 0.f; q0s = 0.f; s1 = 0.f; q1s = 0.f;
#pragma unroll
    for (int nt = 0; nt < NT2; nt++) {
        int c = nt * 8 + tg * 2;
        float bx = b2v[c], by = b2v[c + 1];
        acc2[nt].x += bx; acc2[nt].y += by;
        acc2[nt].z += bx; acc2[nt].w += by;
        s0 += acc2[nt].x + acc2[nt].y;
        q0s += acc2[nt].x * acc2[nt].x + acc2[nt].y * acc2[nt].y;
        s1 += acc2[nt].z + acc2[nt].w;
        q1s += acc2[nt].z * acc2[nt].z + acc2[nt].w * acc2[nt].w;
    }
#pragma unroll
    for (int off = 1; off <= 2; off <<= 1) {
        s0 += __shfl_xor_sync(0xffffffffu, s0, off);
        q0s += __shfl_xor_sync(0xffffffffu, q0s, off);
        s1 += __shfl_xor_sync(0xffffffffu, s1, off);
        q1s += __shfl_xor_sync(0xffffffffu, q1s, off);
    }
    m0 = s0 * (1.f / 128.f); v0 = q0s * (1.f / 128.f) - m0 * m0; rs0 = rsqrtf(v0 + 1e-5f);
    m1 = s1 * (1.f / 128.f); v1 = q1s * (1.f / 128.f) - m1 * m1; rs1 = rsqrtf(v1 + 1e-5f);

#pragma unroll
    for (int nt = 0; nt < NT2; nt++) {
        int c = nt * 8 + tg * 2;
        float ga0 = g2v[c], ga1 = g2v[c + 1], be0 = bt2v[c], be1 = bt2v[c + 1];
        if (ok0) {
            float t0 = (acc2[nt].x - m0) * rs0 * ga0 + be0;
            float t1 = (acc2[nt].y - m0) * rs0 * ga1 + be1;
            float2 e = *(float2*)&xbuf[(size_t)r0 * DD + c];
            e.x += t0; e.y += t1;
            *(float2*)&xbuf[(size_t)r0 * DD + c] = e;
        }
        if (ok1) {
            float t0 = (acc2[nt].z - m1) * rs1 * ga0 + be0;
            float t1 = (acc2[nt].w - m1) * rs1 * ga1 + be1;
            float2 e = *(float2*)&xbuf[(size_t)r1 * DD + c];
            e.x += t0; e.y += t1;
            *(float2*)&xbuf[(size_t)r1 * DD + c] = e;
        }
    }
}

// ---------------- host launcher ----------------
extern "C" void kernel_launch(void* const* d_in, const int* in_sizes, int n_in,
                              void* d_out, int out_size) {
    const float* x    = (const float*)d_in[0];
    const int*   ei   = (const int*)d_in[1];
    const float* ea   = (const float*)d_in[2];
    const float* ew1  = (const float*)d_in[3];
    const float* eb1  = (const float*)d_in[4];
    const float* eg1  = (const float*)d_in[5];
    const float* ebt1 = (const float*)d_in[6];
    const float* ew2  = (const float*)d_in[7];
    const float* eb2  = (const float*)d_in[8];
    const float* eg2  = (const float*)d_in[9];
    const float* ebt2 = (const float*)d_in[10];
    const float* nw1  = (const float*)d_in[11];
    const float* nb1  = (const float*)d_in[12];
    const float* ng1  = (const float*)d_in[13];
    const float* nbt1 = (const float*)d_in[14];
    const float* nw2  = (const float*)d_in[15];
    const float* nb2  = (const float*)d_in[16];
    const float* ng2  = (const float*)d_in[17];
    const float* nbt2 = (const float*)d_in[18];

    float* xo = (float*)d_out;
    float* eo = xo + (size_t)NN * DD;
    const int* rowi = ei;
    const int* coli = ei + NE;

    uint4 *ew1p, *ew2p, *nw1p, *nw2p;
    cudaGetSymbolAddress((void**)&ew1p, g_ew1p);
    cudaGetSymbolAddress((void**)&ew2p, g_ew2p);
    cudaGetSymbolAddress((void**)&nw1p, g_nw1p);
    cudaGetSymbolAddress((void**)&nw2p, g_nw2p);

    const int SMEM = 4 * 32 * 32 * 16;  // 65536 (max slab ring)
    cudaFuncSetAttribute(edge_fused, cudaFuncAttributeMaxDynamicSharedMemorySize, SMEM);
    cudaFuncSetAttribute(node_fused, cudaFuncAttributeMaxDynamicSharedMemorySize, SMEM);

    // pack weights into B-fragment layout
    {
        int t1 = NLAYERS * 24 * 32 * 32;
        int t2 = NLAYERS * 16 * 16 * 32;
        int t3 = NLAYERS * 16 * 32 * 32;
        pack_w<<<(t1 + 255) / 256, 256>>>(ew1, ew1p, 24, 32, 384, 256, t1);
        pack_w<<<(t2 + 255) / 256, 256>>>(ew2, ew2p, 16, 16, 256, 128, t2);
        pack_w<<<(t3 + 255) / 256, 256>>>(nw1, nw1p, 16, 32, 256, 256, t3);
        pack_w<<<(t2 + 255) / 256, 256>>>(nw2, nw2p, 16, 16, 256, 128, t2);
    }

    copy_kernel<<<(NN * DD + 255) / 256, 256>>>(x, xo, NN * DD);
    copy_kernel<<<(NE * DD + 255) / 256, 256>>>(ea, eo, NE * DD);
    zero_cnt_kernel<<<(NN + 255) / 256, 256>>>();
    count_kernel<<<(NE + 255) / 256, 256>>>(coli);
    invcnt_kernel<<<(NN + 255) / 256, 256>>>();
    zero_agg_kernel<<<(NN * DD + 255) / 256, 256>>>();  // once; node phase-1 re-zeroes per layer

    const int EG = (ERT + 3) / 4;  // 938
    const int NG = (NRT + 3) / 4;  // 157

    for (int l = 0; l < NLAYERS; l++) {
        edge_fused<<<EG, 128, SMEM>>>(
            ew1p + (size_t)l * 24 * 32 * 32, ew2p + (size_t)l * 16 * 16 * 32,
            eb1 + l * 256, eg1 + l * 256, ebt1 + l * 256,
            eb2 + l * 128, eg2 + l * 128, ebt2 + l * 128,
            xo, eo, rowi, coli);
        node_fused<<<NG, 128, SMEM>>>(
            nw1p + (size_t)l * 16 * 32 * 32, nw2p + (size_t)l * 16 * 16 * 32,
            nb1 + l * 256, ng1 + l * 256, nbt1 + l * 256,
            nb2 + l * 128, ng2 + l * 128, nbt2 + l * 128,
            xo);
    }
}

// round 13
// speedup vs baseline: 3.6210x; 1.0733x over previous
#include <cuda_runtime.h>
#include <cuda_fp16.h>
#include <math.h>
#include <stdint.h>

#define NN 10000
#define NE 60000
#define DD 128
#define NLAYERS 15

#define ERT 3750   // edge row tiles (60000/16)
#define NRT 625    // node row tiles (10000/16)

// ---------------- device scratch (allocation-free) ----------------
__device__ float g_agg[NN * DD];    // per-node aggregated edge features
__device__ float g_cnt[NN];         // 1/max(count,1)
__device__ float g_X1[NN * 512];    // per-node [x@W1a + b1 | x@W1b] (fp32)

// weights pre-packed as B-fragments {bh0,bh1,bl0,bl1} (fp16 hi/lo):
// layout [layer][ktile][ntile][lane]
__device__ uint4 g_ew1a[NLAYERS * 8 * 32 * 32];   // W1 rows 0..127   (x[row] part)
__device__ uint4 g_ew1b[NLAYERS * 8 * 32 * 32];   // W1 rows 128..255 (x[col] part)
__device__ uint4 g_ew1c[NLAYERS * 8 * 32 * 32];   // W1 rows 256..383 (ea part)
__device__ uint4 g_ew2p[NLAYERS * 16 * 16 * 32];
__device__ uint4 g_nw1p[NLAYERS * 16 * 32 * 32];
__device__ uint4 g_nw2p[NLAYERS * 16 * 16 * 32];

// ---------------- helpers ----------------
__device__ __forceinline__ uint32_t pkh(float a, float b) {
    __half2 t = __floats2half2_rn(a, b);
    return *(uint32_t*)&t;
}
__device__ __forceinline__ uint32_t pkl(float a, float b) {
    __half ha = __float2half_rn(a), hb = __float2half_rn(b);
    return pkh(a - __half2float(ha), b - __half2float(hb));
}

// exact-GELU via Abramowitz-Stegun 7.1.26 erf (abs err <= 1.5e-7)
__device__ __forceinline__ float gelu_f(float t) {
    float x = fabsf(t) * 0.70710678118654752f;
    float k = __fdividef(1.f, fmaf(0.3275911f, x, 1.f));
    float p = fmaf(1.061405429f, k, -1.453152027f);
    p = fmaf(p, k, 1.421413741f);
    p = fmaf(p, k, -0.284496736f);
    p = fmaf(p, k, 0.254829592f);
    p = p * k;
    float e = __expf(-x * x);
    float er = copysignf(fmaf(-p, e, 1.f), t);
    return 0.5f * t * (1.f + er);
}

#define MMA4(d, a, b0, b1) \
    asm volatile("mma.sync.aligned.m16n8k16.row.col.f32.f16.f16.f32 " \
                 "{%0,%1,%2,%3},{%4,%5,%6,%7},{%8,%9},{%0,%1,%2,%3};" \
                 : "+f"((d).x), "+f"((d).y), "+f"((d).z), "+f"((d).w) \
                 : "r"((a)[0]), "r"((a)[1]), "r"((a)[2]), "r"((a)[3]), \
                   "r"(b0), "r"(b1))

// async B slab prefetch into 4-deep ring slot (kt & 3); always commits a group
template <int SLAB, int NTH>
__device__ __forceinline__ void pref_slab(uint4* sB, const uint4* Wp, int kt, int KT, int tid) {
    if (kt < KT) {
        const uint4* src = Wp + (size_t)kt * SLAB + tid;
        uint32_t dst = (uint32_t)__cvta_generic_to_shared(sB + (kt & 3) * SLAB + tid);
#pragma unroll
        for (int i = 0; i < SLAB / NTH; i++)
            asm volatile("cp.async.cg.shared.global [%0], [%1], 16;"
                         :: "r"(dst + i * NTH * 16), "l"(src + i * NTH));
    }
    asm volatile("cp.async.commit_group;" ::: "memory");
}
#define CPWAIT2() asm volatile("cp.async.wait_group 2;" ::: "memory")
#define CPWAIT0() asm volatile("cp.async.wait_group 0;" ::: "memory")

// ---------------- aux kernels ----------------
__global__ void copy_kernel(const float* __restrict__ src, float* __restrict__ dst, int n) {
    int i = blockIdx.x * blockDim.x + threadIdx.x;
    if (i < n) dst[i] = src[i];
}
__global__ void zero_cnt_kernel() {
    int i = blockIdx.x * blockDim.x + threadIdx.x;
    if (i < NN) g_cnt[i] = 0.f;
}
__global__ void count_kernel(const int* __restrict__ col) {
    int e = blockIdx.x * blockDim.x + threadIdx.x;
    if (e < NE) atomicAdd(&g_cnt[col[e]], 1.f);
}
__global__ void invcnt_kernel() {
    int i = blockIdx.x * blockDim.x + threadIdx.x;
    if (i < NN) g_cnt[i] = 1.f / fmaxf(g_cnt[i], 1.f);
}
__global__ void zero_agg_kernel() {
    int i = blockIdx.x * blockDim.x + threadIdx.x;
    if (i < NN * DD) g_agg[i] = 0.f;
}

// Pre-pack fp32 W[L][K][N] rows [k0, k0+16*KT) into per-lane B fragments.
__global__ void pack_w(const float* __restrict__ W, uint4* __restrict__ out,
                       int k0, int KT, int NT, int K, int N, int total) {
    int idx = blockIdx.x * blockDim.x + threadIdx.x;
    if (idx >= total) return;
    int lane = idx & 31;
    int t = idx >> 5;
    int nt = t % NT; t /= NT;
    int kt = t % KT;
    int l = t / KT;
    int g = lane >> 2, tg = lane & 3;
    const float* Wl = W + (size_t)l * K * N;
    int n = nt * 8 + g;
    int ka = k0 + kt * 16 + tg * 2;
    float v00 = Wl[(size_t)ka * N + n];
    float v01 = Wl[(size_t)(ka + 1) * N + n];
    float v10 = Wl[(size_t)(ka + 8) * N + n];
    float v11 = Wl[(size_t)(ka + 9) * N + n];
    uint4 o;
    o.x = pkh(v00, v01);
    o.y = pkh(v10, v11);
    o.z = pkl(v00, v01);
    o.w = pkl(v10, v11);
    out[idx] = o;
}

// ---------------- per-layer node precompute: X1 = [x@W1a + b1 | x@W1b] ----------------
// blockIdx.y = 0: W1a half (adds bias), 1: W1b half. K=128 (8 ktiles), N=256.
__global__ void __launch_bounds__(128, 2)
pre_x1(const uint4* __restrict__ Wa, const uint4* __restrict__ Wb,
       const float* __restrict__ b1v, const float* __restrict__ xbuf) {
    constexpr int KT = 8, NT = 32, SLAB = NT * 32;
    extern __shared__ uint4 sB[];

    const int tid = threadIdx.x, lane = tid & 31, warp = tid >> 5;
    const int g = lane >> 2, tg = lane & 3;
    const int half = blockIdx.y;
    const uint4* Wp = half ? Wb : Wa;
    const int rt = blockIdx.x * 4 + warp;
    const int r0 = rt * 16 + g, r1 = r0 + 8;
    const int r0c = min(r0, NN - 1), r1c = min(r1, NN - 1);
    const bool ok0 = r0 < NN, ok1 = r1 < NN;

    const float* p0 = xbuf + (size_t)r0c * DD;
    const float* p1 = xbuf + (size_t)r1c * DD;

    float4 acc[NT];
#pragma unroll
    for (int i = 0; i < NT; i++) acc[i] = make_float4(0.f, 0.f, 0.f, 0.f);

    pref_slab<SLAB, 128>(sB, Wp, 0, KT, tid);
    pref_slab<SLAB, 128>(sB, Wp, 1, KT, tid);
    pref_slab<SLAB, 128>(sB, Wp, 2, KT, tid);

    for (int kt = 0; kt < KT; kt++) {
        CPWAIT2();
        __syncthreads();
        int ko = kt * 16 + tg * 2;
        float2 a0 = *(const float2*)(p0 + ko);
        float2 a2 = *(const float2*)(p0 + ko + 8);
        float2 b0 = *(const float2*)(p1 + ko);
        float2 b2 = *(const float2*)(p1 + ko + 8);
        uint32_t ah[4];
        ah[0] = pkh(a0.x, a0.y); ah[1] = pkh(b0.x, b0.y);
        ah[2] = pkh(a2.x, a2.y); ah[3] = pkh(b2.x, b2.y);
        const uint4* Bs = sB + (kt & 3) * SLAB + lane;
#pragma unroll
        for (int nt = 0; nt < NT; nt++) {
            uint4 b = Bs[nt * 32];
            MMA4(acc[nt], ah, b.x, b.y);
            MMA4(acc[nt], ah, b.z, b.w);
        }
        pref_slab<SLAB, 128>(sB, Wp, kt + 3, KT, tid);
    }

    const int ofs = half * 256;
#pragma unroll
    for (int nt = 0; nt < NT; nt++) {
        int c = nt * 8 + tg * 2;
        float bx = half ? 0.f : b1v[c];
        float by = half ? 0.f : b1v[c + 1];
        if (ok0) *(float2*)&g_X1[(size_t)r0 * 512 + ofs + c] =
            make_float2(acc[nt].x + bx, acc[nt].y + by);
        if (ok1) *(float2*)&g_X1[(size_t)r1 * 512 + ofs + c] =
            make_float2(acc[nt].z + bx, acc[nt].w + by);
    }
}

// ---------------- fused edge MLP kernel ----------------
// GEMM1 = ea@W1c (K=128) + gathered X1[row], X1[col] adds (bias pre-folded);
// LN1 + GELU -> register fp16 fragments; GEMM2 K=256 N=128; LN2 + residual(ea)
// + atomicAdd scatter into g_agg[col]. 4 warps/CTA, min 2 CTAs/SM.
__global__ void __launch_bounds__(128, 2)
edge_fused(const uint4* __restrict__ W1, const uint4* __restrict__ W2,
           const float* __restrict__ g1v, const float* __restrict__ bt1v,
           const float* __restrict__ b2v, const float* __restrict__ g2v, const float* __restrict__ bt2v,
           float* __restrict__ eabuf,
           const int* __restrict__ rowi, const int* __restrict__ coli) {
    constexpr int KT1 = 8, NT1 = 32, SLAB1 = NT1 * 32;
    constexpr int KT2 = 16, NT2 = 16, SLAB2 = NT2 * 32;
    extern __shared__ uint4 sB[];

    const int tid = threadIdx.x, lane = tid & 31, warp = tid >> 5;
    const int g = lane >> 2, tg = lane & 3;
    const int rt = blockIdx.x * 4 + warp;
    const int r0 = rt * 16 + g, r1 = r0 + 8;
    const int r0c = min(r0, NE - 1), r1c = min(r1, NE - 1);
    const bool ok0 = r0 < NE, ok1 = r1 < NE;

    const int n0r = rowi[r0c], n0c = coli[r0c];
    const int n1r = rowi[r1c], n1c = coli[r1c];
    const float* p02 = eabuf + (size_t)r0c * DD;
    const float* p12 = eabuf + (size_t)r1c * DD;

    // ---- phase 1: GEMM1 (ea @ W1c) ----
    float4 acc[NT1];
#pragma unroll
    for (int i = 0; i < NT1; i++) acc[i] = make_float4(0.f, 0.f, 0.f, 0.f);

    pref_slab<SLAB1, 128>(sB, W1, 0, KT1, tid);
    pref_slab<SLAB1, 128>(sB, W1, 1, KT1, tid);
    pref_slab<SLAB1, 128>(sB, W1, 2, KT1, tid);

    for (int kt = 0; kt < KT1; kt++) {
        CPWAIT2();
        __syncthreads();
        int ko = kt * 16 + tg * 2;
        float2 a0 = *(const float2*)(p02 + ko);
        float2 a2 = *(const float2*)(p02 + ko + 8);
        float2 b0 = *(const float2*)(p12 + ko);
        float2 b2 = *(const float2*)(p12 + ko + 8);
        uint32_t ah[4];
        ah[0] = pkh(a0.x, a0.y); ah[1] = pkh(b0.x, b0.y);
        ah[2] = pkh(a2.x, a2.y); ah[3] = pkh(b2.x, b2.y);
        const uint4* Bs = sB + (kt & 3) * SLAB1 + lane;
#pragma unroll
        for (int nt = 0; nt < NT1; nt++) {
            uint4 b = Bs[nt * 32];
            MMA4(acc[nt], ah, b.x, b.y);
            MMA4(acc[nt], ah, b.z, b.w);
        }
        pref_slab<SLAB1, 128>(sB, W1, kt + 3, KT1, tid);
    }

    // ---- gather-add X1 rows + LN1 stats ----
    const float* xa0 = g_X1 + (size_t)n0r * 512;
    const float* xb0 = g_X1 + (size_t)n0c * 512 + 256;
    const float* xa1 = g_X1 + (size_t)n1r * 512;
    const float* xb1 = g_X1 + (size_t)n1c * 512 + 256;
    float s0 = 0.f, q0s = 0.f, s1 = 0.f, q1s = 0.f;
#pragma unroll
    for (int nt = 0; nt < NT1; nt++) {
        int c = nt * 8 + tg * 2;
        float2 va = *(const float2*)(xa0 + c);
        float2 vb = *(const float2*)(xb0 + c);
        float2 vc = *(const float2*)(xa1 + c);
        float2 vd = *(const float2*)(xb1 + c);
        acc[nt].x += va.x + vb.x; acc[nt].y += va.y + vb.y;
        acc[nt].z += vc.x + vd.x; acc[nt].w += vc.y + vd.y;
        s0 += acc[nt].x + acc[nt].y;
        q0s += acc[nt].x * acc[nt].x + acc[nt].y * acc[nt].y;
        s1 += acc[nt].z + acc[nt].w;
        q1s += acc[nt].z * acc[nt].z + acc[nt].w * acc[nt].w;
    }
#pragma unroll
    for (int off = 1; off <= 2; off <<= 1) {
        s0 += __shfl_xor_sync(0xffffffffu, s0, off);
        q0s += __shfl_xor_sync(0xffffffffu, q0s, off);
        s1 += __shfl_xor_sync(0xffffffffu, s1, off);
        q1s += __shfl_xor_sync(0xffffffffu, q1s, off);
    }
    float m0 = s0 * (1.f / 256.f), v0 = q0s * (1.f / 256.f) - m0 * m0, rs0 = rsqrtf(v0 + 1e-5f);
    float m1 = s1 * (1.f / 256.f), v1 = q1s * (1.f / 256.f) - m1 * m1, rs1 = rsqrtf(v1 + 1e-5f);

    // ---- phase boundary: drain ring, start phase-2 prefetch, then GELU epilogue ----
    CPWAIT0();
    __syncthreads();
    pref_slab<SLAB2, 128>(sB, W2, 0, KT2, tid);
    pref_slab<SLAB2, 128>(sB, W2, 1, KT2, tid);
    pref_slab<SLAB2, 128>(sB, W2, 2, KT2, tid);

    uint4 hf[16];  // hidden rows as fp16 A-fragments for GEMM2
#pragma unroll
    for (int kt = 0; kt < 16; kt++) {
        int c = kt * 16 + tg * 2;
        float ga0 = g1v[c], ga1 = g1v[c + 1], be0 = bt1v[c], be1 = bt1v[c + 1];
        float ga2 = g1v[c + 8], ga3 = g1v[c + 9], be2 = bt1v[c + 8], be3 = bt1v[c + 9];
        float tv[8];
        tv[0] = (acc[2 * kt].x - m0) * rs0 * ga0 + be0;
        tv[1] = (acc[2 * kt].y - m0) * rs0 * ga1 + be1;
        tv[2] = (acc[2 * kt].z - m1) * rs1 * ga0 + be0;
        tv[3] = (acc[2 * kt].w - m1) * rs1 * ga1 + be1;
        tv[4] = (acc[2 * kt + 1].x - m0) * rs0 * ga2 + be2;
        tv[5] = (acc[2 * kt + 1].y - m0) * rs0 * ga3 + be3;
        tv[6] = (acc[2 * kt + 1].z - m1) * rs1 * ga2 + be2;
        tv[7] = (acc[2 * kt + 1].w - m1) * rs1 * ga3 + be3;
#pragma unroll
        for (int j = 0; j < 8; j++) tv[j] = gelu_f(tv[j]);
        hf[kt].x = pkh(tv[0], tv[1]); hf[kt].y = pkh(tv[2], tv[3]);
        hf[kt].z = pkh(tv[4], tv[5]); hf[kt].w = pkh(tv[6], tv[7]);
    }

    // ---- phase 2: GEMM2 (A from registers) ----
    float4 acc2[NT2];
#pragma unroll
    for (int i = 0; i < NT2; i++) acc2[i] = make_float4(0.f, 0.f, 0.f, 0.f);

    for (int kt = 0; kt < KT2; kt++) {
        CPWAIT2();
        __syncthreads();
        uint32_t ah[4] = {hf[kt].x, hf[kt].y, hf[kt].z, hf[kt].w};
        const uint4* Bs = sB + (kt & 3) * SLAB2 + lane;
#pragma unroll
        for (int nt = 0; nt < NT2; nt++) {
            uint4 b = Bs[nt * 32];
            MMA4(acc2[nt], ah, b.x, b.y);
            MMA4(acc2[nt], ah, b.z, b.w);
        }
        pref_slab<SLAB2, 128>(sB, W2, kt + 3, KT2, tid);
    }

    // ---- LN2 + residual(ea) + agg scatter ----
    s0 = 0.f; q0s = 0.f; s1 = 0.f; q1s = 0.f;
#pragma unroll
    for (int nt = 0; nt < NT2; nt++) {
        int c = nt * 8 + tg * 2;
        float bx = b2v[c], by = b2v[c + 1];
        acc2[nt].x += bx; acc2[nt].y += by;
        acc2[nt].z += bx; acc2[nt].w += by;
        s0 += acc2[nt].x + acc2[nt].y;
        q0s += acc2[nt].x * acc2[nt].x + acc2[nt].y * acc2[nt].y;
        s1 += acc2[nt].z + acc2[nt].w;
        q1s += acc2[nt].z * acc2[nt].z + acc2[nt].w * acc2[nt].w;
    }
#pragma unroll
    for (int off = 1; off <= 2; off <<= 1) {
        s0 += __shfl_xor_sync(0xffffffffu, s0, off);
        q0s += __shfl_xor_sync(0xffffffffu, q0s, off);
        s1 += __shfl_xor_sync(0xffffffffu, s1, off);
        q1s += __shfl_xor_sync(0xffffffffu, q1s, off);
    }
    m0 = s0 * (1.f / 128.f); v0 = q0s * (1.f / 128.f) - m0 * m0; rs0 = rsqrtf(v0 + 1e-5f);
    m1 = s1 * (1.f / 128.f); v1 = q1s * (1.f / 128.f) - m1 * m1; rs1 = rsqrtf(v1 + 1e-5f);

#pragma unroll
    for (int nt = 0; nt < NT2; nt++) {
        int c = nt * 8 + tg * 2;
        float ga0 = g2v[c], ga1 = g2v[c + 1], be0 = bt2v[c], be1 = bt2v[c + 1];
        if (ok0) {
            float t0 = (acc2[nt].x - m0) * rs0 * ga0 + be0;
            float t1 = (acc2[nt].y - m0) * rs0 * ga1 + be1;
            float2 e = *(float2*)&eabuf[(size_t)r0 * DD + c];
            e.x += t0; e.y += t1;
            *(float2*)&eabuf[(size_t)r0 * DD + c] = e;
            atomicAdd(&g_agg[(size_t)n0c * DD + c], e.x);
            atomicAdd(&g_agg[(size_t)n0c * DD + c + 1], e.y);
        }
        if (ok1) {
            float t0 = (acc2[nt].z - m1) * rs1 * ga0 + be0;
            float t1 = (acc2[nt].w - m1) * rs1 * ga1 + be1;
            float2 e = *(float2*)&eabuf[(size_t)r1 * DD + c];
            e.x += t0; e.y += t1;
            *(float2*)&eabuf[(size_t)r1 * DD + c] = e;
            atomicAdd(&g_agg[(size_t)n1c * DD + c], e.x);
            atomicAdd(&g_agg[(size_t)n1c * DD + c + 1], e.y);
        }
    }
}

// ---------------- fused node MLP kernel ----------------
// A1=[x | agg*invcnt] K=256 N=256 (re-zeroes agg for next layer);
// GEMM2 K=256 N=128; out: x += LN2. 4 warps/CTA, min 2 CTAs/SM.
__global__ void __launch_bounds__(128, 2)
node_fused(const uint4* __restrict__ W1, const uint4* __restrict__ W2,
           const float* __restrict__ b1v, const float* __restrict__ g1v, const float* __restrict__ bt1v,
           const float* __restrict__ b2v, const float* __restrict__ g2v, const float* __restrict__ bt2v,
           float* __restrict__ xbuf) {
    constexpr int KT1 = 16, NT1 = 32, SLAB1 = NT1 * 32;
    constexpr int KT2 = 16, NT2 = 16, SLAB2 = NT2 * 32;
    extern __shared__ uint4 sB[];

    const int tid = threadIdx.x, lane = tid & 31, warp = tid >> 5;
    const int g = lane >> 2, tg = lane & 3;
    const int rt = blockIdx.x * 4 + warp;
    const int r0 = rt * 16 + g, r1 = r0 + 8;
    const int r0c = min(r0, NN - 1), r1c = min(r1, NN - 1);
    const bool ok0 = r0 < NN, ok1 = r1 < NN;

    const float* p00 = xbuf + (size_t)r0c * DD;
    float* p01 = g_agg + (size_t)r0c * DD;
    const float* p10 = xbuf + (size_t)r1c * DD;
    float* p11 = g_agg + (size_t)r1c * DD;
    const float ic0 = g_cnt[r0c], ic1 = g_cnt[r1c];

    auto loadA = [&](int kt, float2& a0, float2& a2, float2& b0, float2& b2) {
        int seg = kt >> 3, ko = (kt & 7) * 16 + tg * 2;
        const float* q0 = seg == 0 ? p00 : p01;
        const float* q1 = seg == 0 ? p10 : p11;
        a0 = *(const float2*)(q0 + ko); a2 = *(const float2*)(q0 + ko + 8);
        b0 = *(const float2*)(q1 + ko); b2 = *(const float2*)(q1 + ko + 8);
        if (seg == 1) {
            // each agg element read exactly once per layer: zero it for the next
            // layer's scatter. Guarded so clamped (out-of-range) warps never write.
            float2 z = make_float2(0.f, 0.f);
            if (ok0) { *(float2*)(p01 + ko) = z; *(float2*)(p01 + ko + 8) = z; }
            if (ok1) { *(float2*)(p11 + ko) = z; *(float2*)(p11 + ko + 8) = z; }
        }
    };

    // ---- phase 1: GEMM1 ----
    float4 acc[NT1];
#pragma unroll
    for (int i = 0; i < NT1; i++) acc[i] = make_float4(0.f, 0.f, 0.f, 0.f);

    pref_slab<SLAB1, 128>(sB, W1, 0, KT1, tid);
    pref_slab<SLAB1, 128>(sB, W1, 1, KT1, tid);
    pref_slab<SLAB1, 128>(sB, W1, 2, KT1, tid);
    float2 ca0, ca2, cb0, cb2;
    loadA(0, ca0, ca2, cb0, cb2);

    for (int kt = 0; kt < KT1; kt++) {
        CPWAIT2();
        __syncthreads();
        float2 na0 = ca0, na2 = ca2, nb0 = cb0, nb2 = cb2;
        if (kt + 1 < KT1) loadA(kt + 1, na0, na2, nb0, nb2);
        float s0f = 1.f, s1f = 1.f;
        if ((kt >> 3) == 1) { s0f = ic0; s1f = ic1; }
        uint32_t ah[4];
        ah[0] = pkh(ca0.x * s0f, ca0.y * s0f);
        ah[1] = pkh(cb0.x * s1f, cb0.y * s1f);
        ah[2] = pkh(ca2.x * s0f, ca2.y * s0f);
        ah[3] = pkh(cb2.x * s1f, cb2.y * s1f);
        const uint4* Bs = sB + (kt & 3) * SLAB1 + lane;
#pragma unroll
        for (int nt = 0; nt < NT1; nt++) {
            uint4 b = Bs[nt * 32];
            MMA4(acc[nt], ah, b.x, b.y);
            MMA4(acc[nt], ah, b.z, b.w);
        }
        pref_slab<SLAB1, 128>(sB, W1, kt + 3, KT1, tid);
        ca0 = na0; ca2 = na2; cb0 = nb0; cb2 = nb2;
    }

    // ---- LN1 stats ----
    float s0 = 0.f, q0s = 0.f, s1 = 0.f, q1s = 0.f;
#pragma unroll
    for (int nt = 0; nt < NT1; nt++) {
        int c = nt * 8 + tg * 2;
        float bx = b1v[c], by = b1v[c + 1];
        acc[nt].x += bx; acc[nt].y += by;
        acc[nt].z += bx; acc[nt].w += by;
        s0 += acc[nt].x + acc[nt].y;
        q0s += acc[nt].x * acc[nt].x + acc[nt].y * acc[nt].y;
        s1 += acc[nt].z + acc[nt].w;
        q1s += acc[nt].z * acc[nt].z + acc[nt].w * acc[nt].w;
    }
#pragma unroll
    for (int off = 1; off <= 2; off <<= 1) {
        s0 += __shfl_xor_sync(0xffffffffu, s0, off);
        q0s += __shfl_xor_sync(0xffffffffu, q0s, off);
        s1 += __shfl_xor_sync(0xffffffffu, s1, off);
        q1s += __shfl_xor_sync(0xffffffffu, q1s, off);
    }
    float m0 = s0 * (1.f / 256.f), v0 = q0s * (1.f / 256.f) - m0 * m0, rs0 = rsqrtf(v0 + 1e-5f);
    float m1 = s1 * (1.f / 256.f), v1 = q1s * (1.f / 256.f) - m1 * m1, rs1 = rsqrtf(v1 + 1e-5f);

    // ---- phase boundary ----
    CPWAIT0();
    __syncthreads();
    pref_slab<SLAB2, 128>(sB, W2, 0, KT2, tid);
    pref_slab<SLAB2, 128>(sB, W2, 1, KT2, tid);
    pref_slab<SLAB2, 128>(sB, W2, 2, KT2, tid);

    uint4 hf[16];
#pragma unroll
    for (int kt = 0; kt < 16; kt++) {
        int c = kt * 16 + tg * 2;
        float ga0 = g1v[c], ga1 = g1v[c + 1], be0 = bt1v[c], be1 = bt1v[c + 1];
        float ga2 = g1v[c + 8], ga3 = g1v[c + 9], be2 = bt1v[c + 8], be3 = bt1v[c + 9];
        float tv[8];
        tv[0] = (acc[2 * kt].x - m0) * rs0 * ga0 + be0;
        tv[1] = (acc[2 * kt].y - m0) * rs0 * ga1 + be1;
        tv[2] = (acc[2 * kt].z - m1) * rs1 * ga0 + be0;
        tv[3] = (acc[2 * kt].w - m1) * rs1 * ga1 + be1;
        tv[4] = (acc[2 * kt + 1].x - m0) * rs0 * ga2 + be2;
        tv[5] = (acc[2 * kt + 1].y - m0) * rs0 * ga3 + be3;
        tv[6] = (acc[2 * kt + 1].z - m1) * rs1 * ga2 + be2;
        tv[7] = (acc[2 * kt + 1].w - m1) * rs1 * ga3 + be3;
#pragma unroll
        for (int j = 0; j < 8; j++) tv[j] = gelu_f(tv[j]);
        hf[kt].x = pkh(tv[0], tv[1]); hf[kt].y = pkh(tv[2], tv[3]);
        hf[kt].z = pkh(tv[4], tv[5]); hf[kt].w = pkh(tv[6], tv[7]);
    }

    // ---- phase 2: GEMM2 ----
    float4 acc2[NT2];
#pragma unroll
    for (int i = 0; i < NT2; i++) acc2[i] = make_float4(0.f, 0.f, 0.f, 0.f);

    for (int kt = 0; kt < KT2; kt++) {
        CPWAIT2();
        __syncthreads();
        uint32_t ah[4] = {hf[kt].x, hf[kt].y, hf[kt].z, hf[kt].w};
        const uint4* Bs = sB + (kt & 3) * SLAB2 + lane;
#pragma unroll
        for (int nt = 0; nt < NT2; nt++) {
            uint4 b = Bs[nt * 32];
            MMA4(acc2[nt], ah, b.x, b.y);
            MMA4(acc2[nt], ah, b.z, b.w);
        }
        pref_slab<SLAB2, 128>(sB, W2, kt + 3, KT2, tid);
    }

    // ---- LN2 + residual(x) ----
    s0 = 0.f; q0s = 0.f; s1 = 0.f; q1s = 0.f;
#pragma unroll
    for (int nt = 0; nt < NT2; nt++) {
        int c = nt * 8 + tg * 2;
        float bx = b2v[c], by = b2v[c + 1];
        acc2[nt].x += bx; acc2[nt].y += by;
        acc2[nt].z += bx; acc2[nt].w += by;
        s0 += acc2[nt].x + acc2[nt].y;
        q0s += acc2[nt].x * acc2[nt].x + acc2[nt].y * acc2[nt].y;
        s1 += acc2[nt].z + acc2[nt].w;
        q1s += acc2[nt].z * acc2[nt].z + acc2[nt].w * acc2[nt].w;
    }
#pragma unroll
    for (int off = 1; off <= 2; off <<= 1) {
        s0 += __shfl_xor_sync(0xffffffffu, s0, off);
        q0s += __shfl_xor_sync(0xffffffffu, q0s, off);
        s1 += __shfl_xor_sync(0xffffffffu, s1, off);
        q1s += __shfl_xor_sync(0xffffffffu, q1s, off);
    }
    m0 = s0 * (1.f / 128.f); v0 = q0s * (1.f / 128.f) - m0 * m0; rs0 = rsqrtf(v0 + 1e-5f);
    m1 = s1 * (1.f / 128.f); v1 = q1s * (1.f / 128.f) - m1 * m1; rs1 = rsqrtf(v1 + 1e-5f);

#pragma unroll
    for (int nt = 0; nt < NT2; nt++) {
        int c = nt * 8 + tg * 2;
        float ga0 = g2v[c], ga1 = g2v[c + 1], be0 = bt2v[c], be1 = bt2v[c + 1];
        if (ok0) {
            float t0 = (acc2[nt].x - m0) * rs0 * ga0 + be0;
            float t1 = (acc2[nt].y - m0) * rs0 * ga1 + be1;
            float2 e = *(float2*)&xbuf[(size_t)r0 * DD + c];
            e.x += t0; e.y += t1;
            *(float2*)&xbuf[(size_t)r0 * DD + c] = e;
        }
        if (ok1) {
            float t0 = (acc2[nt].z - m1) * rs1 * ga0 + be0;
            float t1 = (acc2[nt].w - m1) * rs1 * ga1 + be1;
            float2 e = *(float2*)&xbuf[(size_t)r1 * DD + c];
            e.x += t0; e.y += t1;
            *(float2*)&xbuf[(size_t)r1 * DD + c] = e;
        }
    }
}

// ---------------- host launcher ----------------
extern "C" void kernel_launch(void* const* d_in, const int* in_sizes, int n_in,
                              void* d_out, int out_size) {
    const float* x    = (const float*)d_in[0];
    const int*   ei   = (const int*)d_in[1];
    const float* ea   = (const float*)d_in[2];
    const float* ew1  = (const float*)d_in[3];
    const float* eb1  = (const float*)d_in[4];
    const float* eg1  = (const float*)d_in[5];
    const float* ebt1 = (const float*)d_in[6];
    const float* ew2  = (const float*)d_in[7];
    const float* eb2  = (const float*)d_in[8];
    const float* eg2  = (const float*)d_in[9];
    const float* ebt2 = (const float*)d_in[10];
    const float* nw1  = (const float*)d_in[11];
    const float* nb1  = (const float*)d_in[12];
    const float* ng1  = (const float*)d_in[13];
    const float* nbt1 = (const float*)d_in[14];
    const float* nw2  = (const float*)d_in[15];
    const float* nb2  = (const float*)d_in[16];
    const float* ng2  = (const float*)d_in[17];
    const float* nbt2 = (const float*)d_in[18];

    float* xo = (float*)d_out;
    float* eo = xo + (size_t)NN * DD;
    const int* rowi = ei;
    const int* coli = ei + NE;

    uint4 *ew1a, *ew1b, *ew1c, *ew2p, *nw1p, *nw2p;
    cudaGetSymbolAddress((void**)&ew1a, g_ew1a);
    cudaGetSymbolAddress((void**)&ew1b, g_ew1b);
    cudaGetSymbolAddress((void**)&ew1c, g_ew1c);
    cudaGetSymbolAddress((void**)&ew2p, g_ew2p);
    cudaGetSymbolAddress((void**)&nw1p, g_nw1p);
    cudaGetSymbolAddress((void**)&nw2p, g_nw2p);

    const int SMEM = 4 * 32 * 32 * 16;  // 65536 (max slab ring)
    cudaFuncSetAttribute(pre_x1, cudaFuncAttributeMaxDynamicSharedMemorySize, SMEM);
    cudaFuncSetAttribute(edge_fused, cudaFuncAttributeMaxDynamicSharedMemorySize, SMEM);
    cudaFuncSetAttribute(node_fused, cudaFuncAttributeMaxDynamicSharedMemorySize, SMEM);

    // pack weights into B-fragment layout
    {
        int ta = NLAYERS * 8 * 32 * 32;
        int t2 = NLAYERS * 16 * 16 * 32;
        int t3 = NLAYERS * 16 * 32 * 32;
        pack_w<<<(ta + 255) / 256, 256>>>(ew1, ew1a, 0, 8, 32, 384, 256, ta);
        pack_w<<<(ta + 255) / 256, 256>>>(ew1, ew1b, 128, 8, 32, 384, 256, ta);
        pack_w<<<(ta + 255) / 256, 256>>>(ew1, ew1c, 256, 8, 32, 384, 256, ta);
        pack_w<<<(t2 + 255) / 256, 256>>>(ew2, ew2p, 0, 16, 16, 256, 128, t2);
        pack_w<<<(t3 + 255) / 256, 256>>>(nw1, nw1p, 0, 16, 32, 256, 256, t3);
        pack_w<<<(t2 + 255) / 256, 256>>>(nw2, nw2p, 0, 16, 16, 256, 128, t2);
    }

    copy_kernel<<<(NN * DD + 255) / 256, 256>>>(x, xo, NN * DD);
    copy_kernel<<<(NE * DD + 255) / 256, 256>>>(ea, eo, NE * DD);
    zero_cnt_kernel<<<(NN + 255) / 256, 256>>>();
    count_kernel<<<(NE + 255) / 256, 256>>>(coli);
    invcnt_kernel<<<(NN + 255) / 256, 256>>>();
    zero_agg_kernel<<<(NN * DD + 255) / 256, 256>>>();  // once; node phase-1 re-zeroes per layer

    const int EG = (ERT + 3) / 4;  // 938
    const int NG = (NRT + 3) / 4;  // 157

    for (int l = 0; l < NLAYERS; l++) {
        pre_x1<<<dim3(NG, 2), 128, SMEM>>>(
            ew1a + (size_t)l * 8 * 32 * 32, ew1b + (size_t)l * 8 * 32 * 32,
            eb1 + l * 256, xo);
        edge_fused<<<EG, 128, SMEM>>>(
            ew1c + (size_t)l * 8 * 32 * 32, ew2p + (size_t)l * 16 * 16 * 32,
            eg1 + l * 256, ebt1 + l * 256,
            eb2 + l * 128, eg2 + l * 128, ebt2 + l * 128,
            eo, rowi, coli);
        node_fused<<<NG, 128, SMEM>>>(
            nw1p + (size_t)l * 16 * 32 * 32, nw2p + (size_t)l * 16 * 16 * 32,
            nb1 + l * 256, ng1 + l * 256, nbt1 + l * 256,
            nb2 + l * 128, ng2 + l * 128, nbt2 + l * 128,
            xo);
    }
}